// round 1
// baseline (speedup 1.0000x reference)
#include <cuda_runtime.h>
#include <cuda_bf16.h>

// Problem constants
#define BB 16
#define CC 512
#define HH 32
#define WW 32
#define NN 1024          // H*W
#define K9 4608          // C*9
#define C3 1536          // 3*C

// ---------------- scratch (device globals; no allocation allowed) -----------
__device__ float g_xcol[(size_t)BB * K9 * NN];   // im2col(x): 302 MB
__device__ float g_A   [(size_t)BB * CC * NN];   // conv1 out
__device__ float g_Bm  [(size_t)BB * CC * NN];   // conv2 out
__device__ float g_D   [(size_t)BB * CC * NN];   // conv3 out
__device__ float g_M   [(size_t)BB * NN * NN];   // spatial attention matrix
__device__ float g_S   [(size_t)BB * CC * CC];   // channel attention matrix
__device__ float g_spat[(size_t)BB * CC * NN];
__device__ float g_chan[(size_t)BB * CC * NN];

// ---------------- im2col ----------------------------------------------------
// xcol[b][ci*9 + ky*3 + kx][n] = x[b][ci][h+ky-1][w+kx-1] (0 if OOB), n = h*32+w
__global__ void im2col_kernel(const float* __restrict__ x, float* __restrict__ xcol) {
    long gid = (long)blockIdx.x * 256 + threadIdx.x;
    int n   = (int)(gid & (NN - 1));
    long r  = gid >> 10;
    int row = (int)(r % K9);
    int b   = (int)(r / K9);
    int ci  = row / 9, tap = row % 9;
    int dy  = tap / 3 - 1, dx = tap % 3 - 1;
    int h   = n >> 5, w = n & 31;
    int ih  = h + dy, iw = w + dx;
    float v = 0.f;
    if ((unsigned)ih < HH && (unsigned)iw < WW)
        v = x[(((long)b * CC + ci) * HH + ih) * WW + iw];
    xcol[gid] = v;
}

// ---------------- generic batched SGEMM -------------------------------------
// C[b][m][n] (row-major, sCn=1) = acc? Cold + scale*(A@B) : scale*(A@B) + bias[m]
// A element: Ab[m*sAm + k*sAk]; B element: Bb[n*sBn + k*sBk].
// ATR/BTR select the tile-load index mapping for coalescing:
//   ATR=true  -> A is K-contiguous (sAk==1), load by (m,k) rows, transpose-store
//   ATR=false -> A is M-contiguous (sAm==1), load by (k,m) rows, direct store
#define TBM 64
#define TBN 64
#define TBK 16

template<bool ATR, bool BTR>
__global__ __launch_bounds__(256)
void sgemm_kernel(const float* __restrict__ A, const float* __restrict__ B,
                  float* __restrict__ C, int K,
                  long sAm, long sAk, long bsA,
                  long sBn, long sBk, long bsB,
                  long sCm, long bsC,
                  const float* __restrict__ bias,
                  const float* __restrict__ scale, int accum)
{
    __shared__ float As[TBK][TBM + 1];
    __shared__ float Bs[TBK][TBN + 1];

    const int tid = threadIdx.x;
    const int tx  = tid & 15;   // -> n
    const int ty  = tid >> 4;   // -> m
    const long m0 = (long)blockIdx.y * TBM;
    const long n0 = (long)blockIdx.x * TBN;

    const float* Ab = A + (long)blockIdx.z * bsA;
    const float* Bb = B + (long)blockIdx.z * bsB;
    float*       Cb = C + (long)blockIdx.z * bsC;

    float acc[4][4] = {};

    for (int k0 = 0; k0 < K; k0 += TBK) {
        // load A tile
        #pragma unroll
        for (int i = 0; i < 4; i++) {
            int idx = tid + i * 256;
            int m, kk;
            if (ATR) { m = idx >> 4; kk = idx & 15; }   // contiguous along k
            else     { m = idx & 63; kk = idx >> 6; }   // contiguous along m
            As[kk][m] = Ab[(m0 + m) * sAm + (long)(k0 + kk) * sAk];
        }
        // load B tile
        #pragma unroll
        for (int i = 0; i < 4; i++) {
            int idx = tid + i * 256;
            int n, kk;
            if (BTR) { n = idx >> 4; kk = idx & 15; }
            else     { n = idx & 63; kk = idx >> 6; }
            Bs[kk][n] = Bb[(n0 + n) * sBn + (long)(k0 + kk) * sBk];
        }
        __syncthreads();

        #pragma unroll
        for (int kk = 0; kk < TBK; kk++) {
            float a[4], b[4];
            #pragma unroll
            for (int i = 0; i < 4; i++) a[i] = As[kk][ty * 4 + i];
            #pragma unroll
            for (int j = 0; j < 4; j++) b[j] = Bs[kk][tx * 4 + j];
            #pragma unroll
            for (int i = 0; i < 4; i++)
                #pragma unroll
                for (int j = 0; j < 4; j++)
                    acc[i][j] += a[i] * b[j];
        }
        __syncthreads();
    }

    const float sc = scale ? *scale : 1.0f;
    #pragma unroll
    for (int i = 0; i < 4; i++) {
        long gm = m0 + ty * 4 + i;
        float bs = bias ? bias[gm] : 0.0f;
        #pragma unroll
        for (int j = 0; j < 4; j++) {
            long gn = n0 + tx * 4 + j;
            long off = gm * sCm + gn;
            float v = acc[i][j] * sc + bs;
            if (accum) v += Cb[off];
            Cb[off] = v;
        }
    }
}

// ---------------- row softmax (in place) ------------------------------------
__device__ __forceinline__ float warpMax(float v) {
    #pragma unroll
    for (int o = 16; o > 0; o >>= 1) v = fmaxf(v, __shfl_xor_sync(0xffffffffu, v, o));
    return v;
}
__device__ __forceinline__ float warpSum(float v) {
    #pragma unroll
    for (int o = 16; o > 0; o >>= 1) v += __shfl_xor_sync(0xffffffffu, v, o);
    return v;
}

template<int LEN>
__global__ __launch_bounds__(256)
void softmax_rows(float* __restrict__ buf) {
    constexpr int V = LEN / 256;
    float* row = buf + (long)blockIdx.x * LEN;
    const int tid  = threadIdx.x;
    const int lane = tid & 31;
    const int wid  = tid >> 5;
    __shared__ float sred[8];

    float v[V];
    float mx = -3.0e38f;
    #pragma unroll
    for (int j = 0; j < V; j++) {
        v[j] = row[tid + j * 256];
        mx = fmaxf(mx, v[j]);
    }
    mx = warpMax(mx);
    if (lane == 0) sred[wid] = mx;
    __syncthreads();
    if (tid == 0) {
        float m = sred[0];
        #pragma unroll
        for (int i = 1; i < 8; i++) m = fmaxf(m, sred[i]);
        sred[0] = m;
    }
    __syncthreads();
    mx = sred[0];
    __syncthreads();   // protect sred before reuse

    float s = 0.f;
    #pragma unroll
    for (int j = 0; j < V; j++) {
        v[j] = __expf(v[j] - mx);
        s += v[j];
    }
    s = warpSum(s);
    if (lane == 0) sred[wid] = s;
    __syncthreads();
    if (tid == 0) {
        float m = 0.f;
        #pragma unroll
        for (int i = 0; i < 8; i++) m += sred[i];
        sred[0] = m;
    }
    __syncthreads();
    const float inv = 1.0f / sred[0];
    #pragma unroll
    for (int j = 0; j < V; j++) row[tid + j * 256] = v[j] * inv;
}

// ---------------- launch -----------------------------------------------------
extern "C" void kernel_launch(void* const* d_in, const int* in_sizes, int n_in,
                              void* d_out, int out_size) {
    const float* x     = (const float*)d_in[0];
    const float* w1    = (const float*)d_in[1];
    const float* b1    = (const float*)d_in[2];
    const float* w2    = (const float*)d_in[3];
    const float* b2    = (const float*)d_in[4];
    const float* w3    = (const float*)d_in[5];
    const float* b3    = (const float*)d_in[6];
    const float* alpha = (const float*)d_in[7];
    const float* beta  = (const float*)d_in[8];
    const float* wf    = (const float*)d_in[9];
    const float* bf    = (const float*)d_in[10];
    float* out = (float*)d_out;

    float *xcol, *Ab, *Bb, *Db, *Mb, *Sb, *spat, *chan;
    cudaGetSymbolAddress((void**)&xcol, g_xcol);
    cudaGetSymbolAddress((void**)&Ab,   g_A);
    cudaGetSymbolAddress((void**)&Bb,   g_Bm);
    cudaGetSymbolAddress((void**)&Db,   g_D);
    cudaGetSymbolAddress((void**)&Mb,   g_M);
    cudaGetSymbolAddress((void**)&Sb,   g_S);
    cudaGetSymbolAddress((void**)&spat, g_spat);
    cudaGetSymbolAddress((void**)&chan, g_chan);

    const long sXb = (long)CC * NN;   // per-batch stride of [C,N] tensors
    const long sMb = (long)NN * NN;
    const long sSb = (long)CC * CC;
    const long sColb = (long)K9 * NN;

    // 1) im2col
    {
        long total = (long)BB * K9 * NN;
        im2col_kernel<<<(unsigned)(total / 256), 256>>>(x, xcol);
    }

    // 2) three 3x3 convs as GEMM: out[c][n] = W[c][k] * xcol[k][n] + b[c]
    {
        dim3 grid(NN / TBN, CC / TBM, BB);
        sgemm_kernel<true, false><<<grid, 256>>>(w1, xcol, Ab, K9,
            /*A*/ K9, 1, 0,  /*B*/ 1, NN, sColb,  /*C*/ NN, sXb, b1, nullptr, 0);
        sgemm_kernel<true, false><<<grid, 256>>>(w2, xcol, Bb, K9,
            K9, 1, 0,  1, NN, sColb,  NN, sXb, b2, nullptr, 0);
        sgemm_kernel<true, false><<<grid, 256>>>(w3, xcol, Db, K9,
            K9, 1, 0,  1, NN, sColb,  NN, sXb, b3, nullptr, 0);
    }

    // 3) M[n][m] = sum_c A[c][n] * Bm[c][m]
    {
        dim3 grid(NN / TBN, NN / TBM, BB);
        sgemm_kernel<false, false><<<grid, 256>>>(Ab, Bb, Mb, CC,
            /*A: sAm(n)=1, sAk(c)=N*/ 1, NN, sXb,
            /*B: sBn(m)=1, sBk(c)=N*/ 1, NN, sXb,
            NN, sMb, nullptr, nullptr, 0);
    }

    // 4) softmax over rows of M
    softmax_rows<NN><<<BB * NN, 256>>>(Mb);

    // 5) spat[c][n] = sum_m D[c][m] * Msm[n][m]
    {
        dim3 grid(NN / TBN, CC / TBM, BB);
        sgemm_kernel<true, true><<<grid, 256>>>(Db, Mb, spat, NN,
            /*A: sAm(c)=N, sAk(m)=1*/ NN, 1, sXb,
            /*B: sBn(n)=N, sBk(m)=1*/ NN, 1, sMb,
            NN, sXb, nullptr, nullptr, 0);
    }

    // 6) S[c][d] = sum_n x[c][n] * x[d][n]
    {
        dim3 grid(CC / TBN, CC / TBM, BB);
        sgemm_kernel<true, true><<<grid, 256>>>(x, x, Sb, NN,
            NN, 1, sXb,   NN, 1, sXb,   CC, sSb, nullptr, nullptr, 0);
    }

    // 7) softmax over rows of S
    softmax_rows<CC><<<BB * CC, 256>>>(Sb);

    // 8) chan[c][n] = sum_d Ssm[d][c] * x[d][n]
    {
        dim3 grid(NN / TBN, CC / TBM, BB);
        sgemm_kernel<false, false><<<grid, 256>>>(Sb, x, chan, CC,
            /*A: sAm(c)=1, sAk(d)=C*/ 1, CC, sSb,
            /*B: sBn(n)=1, sBk(d)=N*/ 1, NN, sXb,
            NN, sXb, nullptr, nullptr, 0);
    }

    // 9) fused 1x1 conv, split over the concat:
    //    out = bf + wf[:, :C]@x + alpha*(wf[:, C:2C]@spat) + beta*(wf[:, 2C:]@chan)
    {
        dim3 grid(NN / TBN, CC / TBM, BB);
        sgemm_kernel<true, false><<<grid, 256>>>(wf, x, out, CC,
            C3, 1, 0,   1, NN, sXb,   NN, sXb, bf, nullptr, 0);
        sgemm_kernel<true, false><<<grid, 256>>>(wf + CC, spat, out, CC,
            C3, 1, 0,   1, NN, sXb,   NN, sXb, nullptr, alpha, 1);
        sgemm_kernel<true, false><<<grid, 256>>>(wf + 2 * CC, chan, out, CC,
            C3, 1, 0,   1, NN, sXb,   NN, sXb, nullptr, beta, 1);
    }
}

// round 2
// speedup vs baseline: 1.4353x; 1.4353x over previous
#include <cuda_runtime.h>
#include <cuda_bf16.h>

// Problem constants
#define BB 16
#define CC 512
#define HH 32
#define WW 32
#define NN 1024          // H*W
#define K9 4608          // C*9
#define C3 1536          // 3*C

// ---------------- scratch (device globals; no allocation allowed) -----------
__device__ float g_xcol[(size_t)BB * K9 * NN];   // im2col(x): 302 MB
__device__ float g_A   [(size_t)BB * CC * NN];   // conv1 out
__device__ float g_Bm  [(size_t)BB * CC * NN];   // conv2 out
__device__ float g_D   [(size_t)BB * CC * NN];   // conv3 out
__device__ float g_M   [(size_t)BB * NN * NN];   // spatial attention matrix
__device__ float g_S   [(size_t)BB * CC * CC];   // channel attention matrix
__device__ float g_spat[(size_t)BB * CC * NN];
__device__ float g_chan[(size_t)BB * CC * NN];

// ---------------- f32x2 packed-FMA helpers ----------------------------------
typedef unsigned long long ull;

__device__ __forceinline__ ull pack2(float lo, float hi) {
    ull r;
    asm("mov.b64 %0, {%1, %2};" : "=l"(r) : "f"(lo), "f"(hi));
    return r;
}
__device__ __forceinline__ void unpack2(ull v, float& lo, float& hi) {
    asm("mov.b64 {%0, %1}, %2;" : "=f"(lo), "=f"(hi) : "l"(v));
}
__device__ __forceinline__ void fma2(ull& d, ull a, ull b) {
    asm("fma.rn.f32x2 %0, %1, %2, %3;" : "=l"(d) : "l"(a), "l"(b), "l"(d));
}

// ---------------- im2col ----------------------------------------------------
__global__ void im2col_kernel(const float* __restrict__ x, float* __restrict__ xcol) {
    long gid = (long)blockIdx.x * 256 + threadIdx.x;
    int n   = (int)(gid & (NN - 1));
    long r  = gid >> 10;
    int row = (int)(r % K9);
    int b   = (int)(r / K9);
    int ci  = row / 9, tap = row % 9;
    int dy  = tap / 3 - 1, dx = tap % 3 - 1;
    int h   = n >> 5, w = n & 31;
    int ih  = h + dy, iw = w + dx;
    float v = 0.f;
    if ((unsigned)ih < HH && (unsigned)iw < WW)
        v = x[(((long)b * CC + ci) * HH + ih) * WW + iw];
    xcol[gid] = v;
}

// ---------------- 128x128x8 SGEMM with packed f32x2 FMA ----------------------
// C[b][m][n] (row-major) = [accum +] scale*(A@B) [+ bias[m]]
// A element: Ab[m*sAm + k*sAk]; B element: Bb[n*sBn + k*sBk].
//   ATR=true  -> A is K-contiguous (sAk==1)
//   ATR=false -> A is M-contiguous (sAm==1)
//   BTR analogous for B/N.
#define BM 128
#define BN 128
#define BK 8
#define SROW 132   // padded smem row stride (floats); 132*4B keeps 16B alignment

template<bool ATR, bool BTR>
__global__ __launch_bounds__(256, 2)
void sgemm2_kernel(const float* __restrict__ A, const float* __restrict__ B,
                   float* __restrict__ C, int K,
                   long sAm, long sAk, long bsA,
                   long sBn, long sBk, long bsB,
                   long sCm, long bsC,
                   const float* __restrict__ bias,
                   const float* __restrict__ scale, int accum)
{
    __shared__ float As[BK][SROW];
    __shared__ float Bs[BK][SROW];

    const int tid = threadIdx.x;
    const int tx  = tid & 15;   // -> n fragment (8 cols)
    const int ty  = tid >> 4;   // -> m fragment (8 rows)
    const long m0 = (long)blockIdx.y * BM;
    const long n0 = (long)blockIdx.x * BN;

    const float* Ab = A + (long)blockIdx.z * bsA;
    const float* Bb = B + (long)blockIdx.z * bsB;
    float*       Cb = C + (long)blockIdx.z * bsC;

    // global-load index decomposition (per-thread, fixed)
    int a_m, a_k;   // ATR: a_m=row, a_k=k-offset*4 ; !ATR: a_k=row(k), a_m=m-offset*4
    if (ATR) { a_m = tid >> 1;  a_k = (tid & 1) * 4; }
    else     { a_k = tid >> 5;  a_m = (tid & 31) * 4; }
    int b_n, b_k;
    if (BTR) { b_n = tid >> 1;  b_k = (tid & 1) * 4; }
    else     { b_k = tid >> 5;  b_n = (tid & 31) * 4; }

    ull acc[8][4];
    #pragma unroll
    for (int i = 0; i < 8; i++)
        #pragma unroll
        for (int j = 0; j < 4; j++) acc[i][j] = 0ull;

    // prefetch first tiles
    float4 pa, pb;
    {
        if (ATR) pa = *(const float4*)&Ab[(m0 + a_m) * sAm + a_k];
        else     pa = *(const float4*)&Ab[(long)a_k * sAk + m0 + a_m];
        if (BTR) pb = *(const float4*)&Bb[(n0 + b_n) * sBn + b_k];
        else     pb = *(const float4*)&Bb[(long)b_k * sBk + n0 + b_n];
    }

    for (int k0 = 0; k0 < K; k0 += BK) {
        // store prefetched tiles to smem
        if (ATR) {
            As[a_k + 0][a_m] = pa.x;  As[a_k + 1][a_m] = pa.y;
            As[a_k + 2][a_m] = pa.z;  As[a_k + 3][a_m] = pa.w;
        } else {
            *(float4*)&As[a_k][a_m] = pa;
        }
        if (BTR) {
            Bs[b_k + 0][b_n] = pb.x;  Bs[b_k + 1][b_n] = pb.y;
            Bs[b_k + 2][b_n] = pb.z;  Bs[b_k + 3][b_n] = pb.w;
        } else {
            *(float4*)&Bs[b_k][b_n] = pb;
        }
        __syncthreads();

        // prefetch next
        int kn = k0 + BK;
        if (kn < K) {
            if (ATR) pa = *(const float4*)&Ab[(m0 + a_m) * sAm + kn + a_k];
            else     pa = *(const float4*)&Ab[(long)(kn + a_k) * sAk + m0 + a_m];
            if (BTR) pb = *(const float4*)&Bb[(n0 + b_n) * sBn + kn + b_k];
            else     pb = *(const float4*)&Bb[(long)(kn + b_k) * sBk + n0 + b_n];
        }

        // compute
        #pragma unroll
        for (int kk = 0; kk < BK; kk++) {
            float4 a0 = *(const float4*)&As[kk][ty * 8];
            float4 a1 = *(const float4*)&As[kk][ty * 8 + 4];
            float4 b0 = *(const float4*)&Bs[kk][tx * 8];
            float4 b1 = *(const float4*)&Bs[kk][tx * 8 + 4];
            ull bp[4];
            bp[0] = pack2(b0.x, b0.y);  bp[1] = pack2(b0.z, b0.w);
            bp[2] = pack2(b1.x, b1.y);  bp[3] = pack2(b1.z, b1.w);
            float av[8] = {a0.x, a0.y, a0.z, a0.w, a1.x, a1.y, a1.z, a1.w};
            #pragma unroll
            for (int i = 0; i < 8; i++) {
                ull ad = pack2(av[i], av[i]);
                #pragma unroll
                for (int j = 0; j < 4; j++) fma2(acc[i][j], ad, bp[j]);
            }
        }
        __syncthreads();
    }

    const float sc = scale ? *scale : 1.0f;
    #pragma unroll
    for (int i = 0; i < 8; i++) {
        long gm = m0 + ty * 8 + i;
        float bs = bias ? bias[gm] : 0.0f;
        float* crow = Cb + gm * sCm + n0 + tx * 8;
        #pragma unroll
        for (int j = 0; j < 4; j++) {
            float lo, hi;
            unpack2(acc[i][j], lo, hi);
            float2 v;
            v.x = lo * sc + bs;
            v.y = hi * sc + bs;
            if (accum) {
                float2 o = *(const float2*)&crow[j * 2];
                v.x += o.x;  v.y += o.y;
            }
            *(float2*)&crow[j * 2] = v;
        }
    }
}

// ---------------- row softmax (in place) ------------------------------------
__device__ __forceinline__ float warpMax(float v) {
    #pragma unroll
    for (int o = 16; o > 0; o >>= 1) v = fmaxf(v, __shfl_xor_sync(0xffffffffu, v, o));
    return v;
}
__device__ __forceinline__ float warpSum(float v) {
    #pragma unroll
    for (int o = 16; o > 0; o >>= 1) v += __shfl_xor_sync(0xffffffffu, v, o);
    return v;
}

template<int LEN>
__global__ __launch_bounds__(256)
void softmax_rows(float* __restrict__ buf) {
    constexpr int V = LEN / 256;
    float* row = buf + (long)blockIdx.x * LEN;
    const int tid  = threadIdx.x;
    const int lane = tid & 31;
    const int wid  = tid >> 5;
    __shared__ float sred[8];

    float v[V];
    float mx = -3.0e38f;
    #pragma unroll
    for (int j = 0; j < V; j++) {
        v[j] = row[tid + j * 256];
        mx = fmaxf(mx, v[j]);
    }
    mx = warpMax(mx);
    if (lane == 0) sred[wid] = mx;
    __syncthreads();
    if (tid == 0) {
        float m = sred[0];
        #pragma unroll
        for (int i = 1; i < 8; i++) m = fmaxf(m, sred[i]);
        sred[0] = m;
    }
    __syncthreads();
    mx = sred[0];
    __syncthreads();

    float s = 0.f;
    #pragma unroll
    for (int j = 0; j < V; j++) {
        v[j] = __expf(v[j] - mx);
        s += v[j];
    }
    s = warpSum(s);
    if (lane == 0) sred[wid] = s;
    __syncthreads();
    if (tid == 0) {
        float m = 0.f;
        #pragma unroll
        for (int i = 0; i < 8; i++) m += sred[i];
        sred[0] = m;
    }
    __syncthreads();
    const float inv = 1.0f / sred[0];
    #pragma unroll
    for (int j = 0; j < V; j++) row[tid + j * 256] = v[j] * inv;
}

// ---------------- launch -----------------------------------------------------
extern "C" void kernel_launch(void* const* d_in, const int* in_sizes, int n_in,
                              void* d_out, int out_size) {
    const float* x     = (const float*)d_in[0];
    const float* w1    = (const float*)d_in[1];
    const float* b1    = (const float*)d_in[2];
    const float* w2    = (const float*)d_in[3];
    const float* b2    = (const float*)d_in[4];
    const float* w3    = (const float*)d_in[5];
    const float* b3    = (const float*)d_in[6];
    const float* alpha = (const float*)d_in[7];
    const float* beta  = (const float*)d_in[8];
    const float* wf    = (const float*)d_in[9];
    const float* bf    = (const float*)d_in[10];
    float* out = (float*)d_out;

    float *xcol, *Ab, *Bb, *Db, *Mb, *Sb, *spat, *chan;
    cudaGetSymbolAddress((void**)&xcol, g_xcol);
    cudaGetSymbolAddress((void**)&Ab,   g_A);
    cudaGetSymbolAddress((void**)&Bb,   g_Bm);
    cudaGetSymbolAddress((void**)&Db,   g_D);
    cudaGetSymbolAddress((void**)&Mb,   g_M);
    cudaGetSymbolAddress((void**)&Sb,   g_S);
    cudaGetSymbolAddress((void**)&spat, g_spat);
    cudaGetSymbolAddress((void**)&chan, g_chan);

    const long sXb = (long)CC * NN;
    const long sMb = (long)NN * NN;
    const long sSb = (long)CC * CC;
    const long sColb = (long)K9 * NN;

    // 1) im2col
    {
        long total = (long)BB * K9 * NN;
        im2col_kernel<<<(unsigned)(total / 256), 256>>>(x, xcol);
    }

    // 2) three 3x3 convs as GEMM: out[c][n] = W[c][k] * xcol[k][n] + b[c]
    {
        dim3 grid(NN / BN, CC / BM, BB);
        sgemm2_kernel<true, false><<<grid, 256>>>(w1, xcol, Ab, K9,
            K9, 1, 0,  1, NN, sColb,  NN, sXb, b1, nullptr, 0);
        sgemm2_kernel<true, false><<<grid, 256>>>(w2, xcol, Bb, K9,
            K9, 1, 0,  1, NN, sColb,  NN, sXb, b2, nullptr, 0);
        sgemm2_kernel<true, false><<<grid, 256>>>(w3, xcol, Db, K9,
            K9, 1, 0,  1, NN, sColb,  NN, sXb, b3, nullptr, 0);
    }

    // 3) M[n][m] = sum_c A[c][n] * Bm[c][m]
    {
        dim3 grid(NN / BN, NN / BM, BB);
        sgemm2_kernel<false, false><<<grid, 256>>>(Ab, Bb, Mb, CC,
            1, NN, sXb,   1, NN, sXb,   NN, sMb, nullptr, nullptr, 0);
    }

    // 4) softmax over rows of M
    softmax_rows<NN><<<BB * NN, 256>>>(Mb);

    // 5) spat[c][n] = sum_m D[c][m] * Msm[n][m]
    {
        dim3 grid(NN / BN, CC / BM, BB);
        sgemm2_kernel<true, true><<<grid, 256>>>(Db, Mb, spat, NN,
            NN, 1, sXb,   NN, 1, sMb,   NN, sXb, nullptr, nullptr, 0);
    }

    // 6) S[c][d] = sum_n x[c][n] * x[d][n]
    {
        dim3 grid(CC / BN, CC / BM, BB);
        sgemm2_kernel<true, true><<<grid, 256>>>(x, x, Sb, NN,
            NN, 1, sXb,   NN, 1, sXb,   CC, sSb, nullptr, nullptr, 0);
    }

    // 7) softmax over rows of S
    softmax_rows<CC><<<BB * CC, 256>>>(Sb);

    // 8) chan[c][n] = sum_d Ssm[d][c] * x[d][n]
    {
        dim3 grid(NN / BN, CC / BM, BB);
        sgemm2_kernel<false, false><<<grid, 256>>>(Sb, x, chan, CC,
            1, CC, sSb,   1, NN, sXb,   NN, sXb, nullptr, nullptr, 0);
    }

    // 9) fused 1x1 conv over the implicit concat
    {
        dim3 grid(NN / BN, CC / BM, BB);
        sgemm2_kernel<true, false><<<grid, 256>>>(wf, x, out, CC,
            C3, 1, 0,   1, NN, sXb,   NN, sXb, bf, nullptr, 0);
        sgemm2_kernel<true, false><<<grid, 256>>>(wf + CC, spat, out, CC,
            C3, 1, 0,   1, NN, sXb,   NN, sXb, nullptr, alpha, 1);
        sgemm2_kernel<true, false><<<grid, 256>>>(wf + 2 * CC, chan, out, CC,
            C3, 1, 0,   1, NN, sXb,   NN, sXb, nullptr, beta, 1);
    }
}

// round 4
// speedup vs baseline: 3.2898x; 2.2921x over previous
#include <cuda_runtime.h>
#include <cuda_bf16.h>
#include <cstdint>

#define BB 16
#define CC 512
#define HH 32
#define WW 32
#define NN 1024
#define K9 4608
#define C3 1536

typedef __nv_bfloat16 bf16;

// ---------------- scratch (device globals) -----------------------------------
__device__ bf16 g_xcolT_h[(size_t)BB * NN * K9];
__device__ bf16 g_xcolT_l[(size_t)BB * NN * K9];
__device__ bf16 g_w1h[CC * K9], g_w1l[CC * K9];
__device__ bf16 g_w2h[CC * K9], g_w2l[CC * K9];
__device__ bf16 g_w3h[CC * K9], g_w3l[CC * K9];
__device__ bf16 g_wfh[CC * C3], g_wfl[CC * C3];
__device__ float g_A [(size_t)BB * CC * NN];
__device__ float g_Bm[(size_t)BB * CC * NN];
__device__ float g_D [(size_t)BB * CC * NN];
__device__ bf16 g_ATh [(size_t)BB * NN * CC], g_ATl [(size_t)BB * NN * CC];
__device__ bf16 g_BmTh[(size_t)BB * NN * CC], g_BmTl[(size_t)BB * NN * CC];
__device__ bf16 g_Dh[(size_t)BB * CC * NN], g_Dl[(size_t)BB * CC * NN];
__device__ bf16 g_xh[(size_t)BB * CC * NN], g_xl[(size_t)BB * CC * NN];
__device__ float g_M[(size_t)BB * NN * NN];
__device__ bf16 g_Mh[(size_t)BB * NN * NN], g_Ml[(size_t)BB * NN * NN];
__device__ float g_S[(size_t)BB * CC * CC];
__device__ bf16 g_STh[(size_t)BB * CC * CC], g_STl[(size_t)BB * CC * CC];
__device__ float g_spat[(size_t)BB * CC * NN];
__device__ float g_chan[(size_t)BB * CC * NN];
__device__ bf16 g_catTh[(size_t)BB * NN * C3], g_catTl[(size_t)BB * NN * C3];

// ---------------- helpers ------------------------------------------------------
__device__ __forceinline__ uint32_t smem_u32(const void* p) {
    uint32_t a;
    asm("{ .reg .u64 t; cvta.to.shared.u64 t, %1; cvt.u32.u64 %0, t; }"
        : "=r"(a) : "l"(p));
    return a;
}
__device__ __forceinline__ void ldsm_x4(uint32_t* r, uint32_t addr) {
    asm volatile("ldmatrix.sync.aligned.m8n8.x4.shared.b16 {%0,%1,%2,%3}, [%4];"
                 : "=r"(r[0]), "=r"(r[1]), "=r"(r[2]), "=r"(r[3]) : "r"(addr));
}
__device__ __forceinline__ void ldsm_x2(uint32_t* r, uint32_t addr) {
    asm volatile("ldmatrix.sync.aligned.m8n8.x2.shared.b16 {%0,%1}, [%2];"
                 : "=r"(r[0]), "=r"(r[1]) : "r"(addr));
}
__device__ __forceinline__ void mma16816(float* d, const uint32_t* a, const uint32_t* b) {
    asm volatile("mma.sync.aligned.m16n8k16.row.col.f32.bf16.bf16.f32 "
                 "{%0,%1,%2,%3}, {%4,%5,%6,%7}, {%8,%9}, {%0,%1,%2,%3};"
                 : "+f"(d[0]), "+f"(d[1]), "+f"(d[2]), "+f"(d[3])
                 : "r"(a[0]), "r"(a[1]), "r"(a[2]), "r"(a[3]), "r"(b[0]), "r"(b[1]));
}

// ---------------- mma.sync bf16-split GEMM ------------------------------------
// C[m][n] = sum_k (Ahi+Alo)[m][k]*(Bhi+Blo)[n][k] (3-term) + bias[m]
// Tiles: block 128x128, BK=32; 8 warps in 2(M)x4(N); warp tile 64x32.
// Smem tile: 128 rows x 64B (32 bf16), chunk swizzle: ch ^= (row>>1)&3.
#define TILEB 8192
#define GEMM_SMEM (2 * 4 * TILEB)   // 64 KB

__device__ __forceinline__ void stage_load(
    uint32_t sbase, int s,
    const bf16* __restrict__ Ahi, const bf16* __restrict__ Alo,
    const bf16* __restrict__ Bhi, const bf16* __restrict__ Blo,
    long m0, long n0, long lda, long ldb, long k0, int tid)
{
    #pragma unroll
    for (int t = 0; t < 4; t++) {
        const bf16* S = (t == 0) ? Ahi : (t == 1) ? Alo : (t == 2) ? Bhi : Blo;
        const long rb = (t < 2) ? m0 : n0;
        const long ld = (t < 2) ? lda : ldb;
        uint32_t tb = sbase + (uint32_t)(s * 4 + t) * TILEB;
        #pragma unroll
        for (int p = 0; p < 2; p++) {
            int row = (tid >> 2) + p * 64;
            int ch  = tid & 3;
            const void* g = (const void*)(S + (rb + row) * ld + k0 + ch * 8);
            uint32_t dst = tb + (uint32_t)(row * 64 + ((ch ^ ((row >> 1) & 3)) << 4));
            asm volatile("cp.async.cg.shared.global [%0], [%1], 16;"
                         :: "r"(dst), "l"(g) : "memory");
        }
    }
    asm volatile("cp.async.commit_group;" ::: "memory");
}

__global__ __launch_bounds__(256, 1)
void mma_gemm(const bf16* __restrict__ Ahi, const bf16* __restrict__ Alo, long lda, long bsA,
              const bf16* __restrict__ Bhi, const bf16* __restrict__ Blo, long ldb, long bsB,
              float* __restrict__ C, long ldc, long bsC,
              const float* __restrict__ bias, int K)
{
    extern __shared__ char smem[];
    const uint32_t sb = smem_u32(smem);
    const int tid = threadIdx.x;
    const int wid = tid >> 5, lane = tid & 31;
    const int warp_m = wid & 1, warp_n = wid >> 1;
    const long m0 = (long)blockIdx.y * 128, n0 = (long)blockIdx.x * 128;
    Ahi += (long)blockIdx.z * bsA;  Alo += (long)blockIdx.z * bsA;
    Bhi += (long)blockIdx.z * bsB;  Blo += (long)blockIdx.z * bsB;
    C   += (long)blockIdx.z * bsC;

    float d[4][4][4];
    #pragma unroll
    for (int i = 0; i < 4; i++)
        #pragma unroll
        for (int j = 0; j < 4; j++)
            #pragma unroll
            for (int q = 0; q < 4; q++) d[i][j][q] = 0.f;

    const int NC = K >> 5;
    stage_load(sb, 0, Ahi, Alo, Bhi, Blo, m0, n0, lda, ldb, 0, tid);

    for (int i = 0; i < NC; i++) {
        const int s = i & 1;
        if (i + 1 < NC) {
            stage_load(sb, s ^ 1, Ahi, Alo, Bhi, Blo, m0, n0, lda, ldb, (long)(i + 1) * 32, tid);
            asm volatile("cp.async.wait_group 1;" ::: "memory");
        } else {
            asm volatile("cp.async.wait_group 0;" ::: "memory");
        }
        __syncthreads();

        const uint32_t bAh = sb + (uint32_t)(s * 4 + 0) * TILEB;
        const uint32_t bAl = sb + (uint32_t)(s * 4 + 1) * TILEB;
        const uint32_t bBh = sb + (uint32_t)(s * 4 + 2) * TILEB;
        const uint32_t bBl = sb + (uint32_t)(s * 4 + 3) * TILEB;

        #pragma unroll
        for (int ks = 0; ks < 2; ks++) {
            uint32_t ah[4][4], al[4][4];
            #pragma unroll
            for (int tm = 0; tm < 4; tm++) {
                int row = warp_m * 64 + tm * 16 + (lane & 15);
                int ch  = ks * 2 + ((lane >> 4) & 1);
                uint32_t off = (uint32_t)(row * 64 + ((ch ^ ((row >> 1) & 3)) << 4));
                ldsm_x4(ah[tm], bAh + off);
                ldsm_x4(al[tm], bAl + off);
            }
            uint32_t bh[4][2], bl[4][2];
            #pragma unroll
            for (int tn = 0; tn < 4; tn++) {
                int row = warp_n * 32 + tn * 8 + (lane & 7);
                int ch  = ks * 2 + ((lane >> 3) & 1);
                uint32_t off = (uint32_t)(row * 64 + ((ch ^ ((row >> 1) & 3)) << 4));
                ldsm_x2(bh[tn], bBh + off);
                ldsm_x2(bl[tn], bBl + off);
            }
            #pragma unroll
            for (int tm = 0; tm < 4; tm++)
                #pragma unroll
                for (int tn = 0; tn < 4; tn++) {
                    mma16816(d[tm][tn], ah[tm], bh[tn]);
                    mma16816(d[tm][tn], ah[tm], bl[tn]);
                    mma16816(d[tm][tn], al[tm], bh[tn]);
                }
        }
        __syncthreads();
    }

    // epilogue
    #pragma unroll
    for (int tm = 0; tm < 4; tm++) {
        const long m = m0 + warp_m * 64 + tm * 16 + (lane >> 2);
        const float bs0 = bias ? bias[m]     : 0.f;
        const float bs1 = bias ? bias[m + 8] : 0.f;
        #pragma unroll
        for (int tn = 0; tn < 4; tn++) {
            const long n = n0 + warp_n * 32 + tn * 8 + (lane & 3) * 2;
            float2 v0 = make_float2(d[tm][tn][0] + bs0, d[tm][tn][1] + bs0);
            float2 v1 = make_float2(d[tm][tn][2] + bs1, d[tm][tn][3] + bs1);
            *(float2*)&C[m * ldc + n]       = v0;
            *(float2*)&C[(m + 8) * ldc + n] = v1;
        }
    }
}

// ---------------- im2col + split: xcolT[b][n][k] -----------------------------
__global__ void im2col_split(const float* __restrict__ x,
                             bf16* __restrict__ oh, bf16* __restrict__ ol) {
    long gid = (long)blockIdx.x * 256 + threadIdx.x;
    int k = (int)(gid % K9);
    long r = gid / K9;
    int n = (int)(r & (NN - 1));
    int b = (int)(r >> 10);
    int ci = k / 9, tap = k % 9;
    int dy = tap / 3 - 1, dx = tap % 3 - 1;
    int h = n >> 5, w = n & 31;
    int ih = h + dy, iw = w + dx;
    float v = 0.f;
    if ((unsigned)ih < HH && (unsigned)iw < WW)
        v = x[(((long)b * CC + ci) * HH + ih) * WW + iw];
    bf16 hi = __float2bfloat16(v);
    oh[gid] = hi;
    ol[gid] = __float2bfloat16(v - __bfloat162float(hi));
}

// ---------------- plain split -------------------------------------------------
__global__ void split_kernel(const float* __restrict__ in,
                             bf16* __restrict__ oh, bf16* __restrict__ ol) {
    long g = (long)blockIdx.x * 256 + threadIdx.x;
    float v = in[g];
    bf16 hi = __float2bfloat16(v);
    oh[g] = hi;
    ol[g] = __float2bfloat16(v - __bfloat162float(hi));
}

// ---------------- transpose + split (optional scale) --------------------------
__global__ void splitT_kernel(const float* __restrict__ in, long ldi, long bsi,
                              bf16* __restrict__ oh, bf16* __restrict__ ol,
                              long ldo, long bso, long coloff,
                              const float* __restrict__ scale) {
    __shared__ float t[32][33];
    const int tx = threadIdx.x, ty = threadIdx.y;
    const long i0 = (long)blockIdx.x * 32, j0 = (long)blockIdx.y * 32;
    const float* I = in + (long)blockIdx.z * bsi;
    bf16* H = oh + (long)blockIdx.z * bso + coloff;
    bf16* L = ol + (long)blockIdx.z * bso + coloff;
    const float sc = scale ? *scale : 1.0f;
    #pragma unroll
    for (int k = 0; k < 4; k++)
        t[ty + k * 8][tx] = I[(i0 + ty + k * 8) * ldi + j0 + tx];
    __syncthreads();
    #pragma unroll
    for (int k = 0; k < 4; k++) {
        float v = t[tx][ty + k * 8] * sc;
        bf16 hi = __float2bfloat16(v);
        long off = (j0 + ty + k * 8) * ldo + i0 + tx;
        H[off] = hi;
        L[off] = __float2bfloat16(v - __bfloat162float(hi));
    }
}

// ---------------- softmax ----------------------------------------------------
__device__ __forceinline__ float warpMax(float v) {
    #pragma unroll
    for (int o = 16; o > 0; o >>= 1) v = fmaxf(v, __shfl_xor_sync(0xffffffffu, v, o));
    return v;
}
__device__ __forceinline__ float warpSum(float v) {
    #pragma unroll
    for (int o = 16; o > 0; o >>= 1) v += __shfl_xor_sync(0xffffffffu, v, o);
    return v;
}

__global__ __launch_bounds__(256)
void softmax1024_split(const float* __restrict__ buf,
                       bf16* __restrict__ oh, bf16* __restrict__ ol) {
    const long base = (long)blockIdx.x * NN;
    const float* row = buf + base;
    const int tid = threadIdx.x, lane = tid & 31, wid = tid >> 5;
    __shared__ float sred[8];
    float v[4];
    float mx = -3.0e38f;
    #pragma unroll
    for (int j = 0; j < 4; j++) { v[j] = row[tid + j * 256]; mx = fmaxf(mx, v[j]); }
    mx = warpMax(mx);
    if (lane == 0) sred[wid] = mx;
    __syncthreads();
    if (tid == 0) {
        float m = sred[0];
        #pragma unroll
        for (int i = 1; i < 8; i++) m = fmaxf(m, sred[i]);
        sred[0] = m;
    }
    __syncthreads();
    mx = sred[0];
    __syncthreads();
    float s = 0.f;
    #pragma unroll
    for (int j = 0; j < 4; j++) { v[j] = __expf(v[j] - mx); s += v[j]; }
    s = warpSum(s);
    if (lane == 0) sred[wid] = s;
    __syncthreads();
    if (tid == 0) {
        float m = 0.f;
        #pragma unroll
        for (int i = 0; i < 8; i++) m += sred[i];
        sred[0] = m;
    }
    __syncthreads();
    const float inv = 1.0f / sred[0];
    #pragma unroll
    for (int j = 0; j < 4; j++) {
        float w = v[j] * inv;
        bf16 hi = __float2bfloat16(w);
        oh[base + tid + j * 256] = hi;
        ol[base + tid + j * 256] = __float2bfloat16(w - __bfloat162float(hi));
    }
}

__global__ __launch_bounds__(256)
void softmax512(float* __restrict__ buf) {
    float* row = buf + (long)blockIdx.x * CC;
    const int tid = threadIdx.x, lane = tid & 31, wid = tid >> 5;
    __shared__ float sred[8];
    float v[2];
    float mx = -3.0e38f;
    #pragma unroll
    for (int j = 0; j < 2; j++) { v[j] = row[tid + j * 256]; mx = fmaxf(mx, v[j]); }
    mx = warpMax(mx);
    if (lane == 0) sred[wid] = mx;
    __syncthreads();
    if (tid == 0) {
        float m = sred[0];
        #pragma unroll
        for (int i = 1; i < 8; i++) m = fmaxf(m, sred[i]);
        sred[0] = m;
    }
    __syncthreads();
    mx = sred[0];
    __syncthreads();
    float s = 0.f;
    #pragma unroll
    for (int j = 0; j < 2; j++) { v[j] = __expf(v[j] - mx); s += v[j]; }
    s = warpSum(s);
    if (lane == 0) sred[wid] = s;
    __syncthreads();
    if (tid == 0) {
        float m = 0.f;
        #pragma unroll
        for (int i = 0; i < 8; i++) m += sred[i];
        sred[0] = m;
    }
    __syncthreads();
    const float inv = 1.0f / sred[0];
    #pragma unroll
    for (int j = 0; j < 2; j++) row[tid + j * 256] = v[j] * inv;
}

// ---------------- launch -----------------------------------------------------
extern "C" void kernel_launch(void* const* d_in, const int* in_sizes, int n_in,
                              void* d_out, int out_size) {
    const float* x     = (const float*)d_in[0];
    const float* w1    = (const float*)d_in[1];
    const float* b1    = (const float*)d_in[2];
    const float* w2    = (const float*)d_in[3];
    const float* b2    = (const float*)d_in[4];
    const float* w3    = (const float*)d_in[5];
    const float* b3    = (const float*)d_in[6];
    const float* alpha = (const float*)d_in[7];
    const float* beta  = (const float*)d_in[8];
    const float* wf    = (const float*)d_in[9];
    const float* bf    = (const float*)d_in[10];
    float* out = (float*)d_out;

    cudaFuncSetAttribute(mma_gemm, cudaFuncAttributeMaxDynamicSharedMemorySize, GEMM_SMEM);

    bf16 *xcolTh, *xcolTl, *w1h, *w1l, *w2h, *w2l, *w3h, *w3l, *wfh, *wfl;
    bf16 *ATh, *ATl, *BmTh, *BmTl, *Dh, *Dl, *xh, *xl, *Mh, *Ml, *STh, *STl, *catTh, *catTl;
    float *Ab, *Bmb, *Db, *Mb, *Sb, *spat, *chan;
    cudaGetSymbolAddress((void**)&xcolTh, g_xcolT_h);
    cudaGetSymbolAddress((void**)&xcolTl, g_xcolT_l);
    cudaGetSymbolAddress((void**)&w1h, g_w1h);  cudaGetSymbolAddress((void**)&w1l, g_w1l);
    cudaGetSymbolAddress((void**)&w2h, g_w2h);  cudaGetSymbolAddress((void**)&w2l, g_w2l);
    cudaGetSymbolAddress((void**)&w3h, g_w3h);  cudaGetSymbolAddress((void**)&w3l, g_w3l);
    cudaGetSymbolAddress((void**)&wfh, g_wfh);  cudaGetSymbolAddress((void**)&wfl, g_wfl);
    cudaGetSymbolAddress((void**)&Ab,  g_A);
    cudaGetSymbolAddress((void**)&Bmb, g_Bm);
    cudaGetSymbolAddress((void**)&Db,  g_D);
    cudaGetSymbolAddress((void**)&ATh, g_ATh);  cudaGetSymbolAddress((void**)&ATl, g_ATl);
    cudaGetSymbolAddress((void**)&BmTh, g_BmTh); cudaGetSymbolAddress((void**)&BmTl, g_BmTl);
    cudaGetSymbolAddress((void**)&Dh, g_Dh);    cudaGetSymbolAddress((void**)&Dl, g_Dl);
    cudaGetSymbolAddress((void**)&xh, g_xh);    cudaGetSymbolAddress((void**)&xl, g_xl);
    cudaGetSymbolAddress((void**)&Mb, g_M);
    cudaGetSymbolAddress((void**)&Mh, g_Mh);    cudaGetSymbolAddress((void**)&Ml, g_Ml);
    cudaGetSymbolAddress((void**)&Sb, g_S);
    cudaGetSymbolAddress((void**)&STh, g_STh);  cudaGetSymbolAddress((void**)&STl, g_STl);
    cudaGetSymbolAddress((void**)&spat, g_spat);
    cudaGetSymbolAddress((void**)&chan, g_chan);
    cudaGetSymbolAddress((void**)&catTh, g_catTh);
    cudaGetSymbolAddress((void**)&catTl, g_catTl);

    const long sX  = (long)CC * NN;
    const long sM  = (long)NN * NN;
    const long sS  = (long)CC * CC;
    const long sCol = (long)NN * K9;
    const long sCat = (long)NN * C3;
    dim3 blkT(32, 8);

    // 1) im2col + split -> xcolT[b][n][k]
    im2col_split<<<(unsigned)((long)BB * NN * K9 / 256), 256>>>(x, xcolTh, xcolTl);

    // 2) weight splits
    split_kernel<<<CC * K9 / 256, 256>>>(w1, w1h, w1l);
    split_kernel<<<CC * K9 / 256, 256>>>(w2, w2h, w2l);
    split_kernel<<<CC * K9 / 256, 256>>>(w3, w3h, w3l);
    split_kernel<<<CC * C3 / 256, 256>>>(wf, wfh, wfl);

    // 3) three 3x3 convs: out[c][n] = W[c][:] . xcolT[n][:]
    {
        dim3 g(NN / 128, CC / 128, BB);
        mma_gemm<<<g, 256, GEMM_SMEM>>>(w1h, w1l, K9, 0, xcolTh, xcolTl, K9, sCol,
                                        Ab, NN, sX, b1, K9);
        mma_gemm<<<g, 256, GEMM_SMEM>>>(w2h, w2l, K9, 0, xcolTh, xcolTl, K9, sCol,
                                        Bmb, NN, sX, b2, K9);
        mma_gemm<<<g, 256, GEMM_SMEM>>>(w3h, w3l, K9, 0, xcolTh, xcolTl, K9, sCol,
                                        Db, NN, sX, b3, K9);
    }

    // 4) splits for attention GEMMs
    splitT_kernel<<<dim3(CC / 32, NN / 32, BB), blkT>>>(Ab, NN, sX, ATh, ATl, CC, sM / 2, 0, nullptr);
    splitT_kernel<<<dim3(CC / 32, NN / 32, BB), blkT>>>(Bmb, NN, sX, BmTh, BmTl, CC, sM / 2, 0, nullptr);
    split_kernel<<<(unsigned)((long)BB * sX / 256), 256>>>(Db, Dh, Dl);
    split_kernel<<<(unsigned)((long)BB * sX / 256), 256>>>(x, xh, xl);

    // 5) M[n][m] = AT[n][:] . BmT[m][:]
    {
        dim3 g(NN / 128, NN / 128, BB);
        mma_gemm<<<g, 256, GEMM_SMEM>>>(ATh, ATl, CC, sM / 2, BmTh, BmTl, CC, sM / 2,
                                        Mb, NN, sM, nullptr, CC);
    }

    // 6) softmax rows of M -> Mh/Ml
    softmax1024_split<<<BB * NN, 256>>>(Mb, Mh, Ml);

    // 7) spat[c][n] = D[c][:] . Msm[n][:]
    {
        dim3 g(NN / 128, CC / 128, BB);
        mma_gemm<<<g, 256, GEMM_SMEM>>>(Dh, Dl, NN, sX, Mh, Ml, NN, sM,
                                        spat, NN, sX, nullptr, NN);
    }

    // 8) S[c][d] = x[c][:] . x[d][:]
    {
        dim3 g(CC / 128, CC / 128, BB);
        mma_gemm<<<g, 256, GEMM_SMEM>>>(xh, xl, NN, sX, xh, xl, NN, sX,
                                        Sb, CC, sS, nullptr, NN);
    }

    // 9) softmax rows of S (fp32 in place)
    softmax512<<<BB * CC, 256>>>(Sb);

    // 10) ST split (Ssm^T), xT -> catT[:,0:512]
    splitT_kernel<<<dim3(CC / 32, CC / 32, BB), blkT>>>(Sb, CC, sS, STh, STl, CC, sS, 0, nullptr);
    splitT_kernel<<<dim3(CC / 32, NN / 32, BB), blkT>>>(x, NN, sX, catTh, catTl, C3, sCat, 0, nullptr);

    // 11) chan[c][n] = ST[c][:] . xT[n][:]
    {
        dim3 g(NN / 128, CC / 128, BB);
        mma_gemm<<<g, 256, GEMM_SMEM>>>(STh, STl, CC, sS, catTh, catTl, C3, sCat,
                                        chan, NN, sX, nullptr, CC);
    }

    // 12) alpha*spat^T, beta*chan^T -> catT columns
    splitT_kernel<<<dim3(CC / 32, NN / 32, BB), blkT>>>(spat, NN, sX, catTh, catTl, C3, sCat, CC, alpha);
    splitT_kernel<<<dim3(CC / 32, NN / 32, BB), blkT>>>(chan, NN, sX, catTh, catTl, C3, sCat, 2 * CC, beta);

    // 13) fuse: out[c][n] = wf[c][:] . catT[n][:] + bf[c]
    {
        dim3 g(NN / 128, CC / 128, BB);
        mma_gemm<<<g, 256, GEMM_SMEM>>>(wfh, wfl, C3, 0, catTh, catTl, C3, sCat,
                                        out, NN, sX, bf, C3);
    }
}

// round 5
// speedup vs baseline: 3.4641x; 1.0530x over previous
#include <cuda_runtime.h>
#include <cuda_bf16.h>
#include <cstdint>

#define BB 16
#define CC 512
#define HH 32
#define WW 32
#define NN 1024
#define K9 4608
#define C3 1536

typedef __nv_bfloat16 bf16;

// ---------------- scratch (device globals) -----------------------------------
__device__ bf16 g_xcolT_h[(size_t)BB * NN * K9];
__device__ bf16 g_xcolT_l[(size_t)BB * NN * K9];
__device__ bf16 g_w1h[CC * K9], g_w1l[CC * K9];
__device__ bf16 g_w2h[CC * K9], g_w2l[CC * K9];
__device__ bf16 g_w3h[CC * K9], g_w3l[CC * K9];
__device__ bf16 g_wfh[CC * C3], g_wfl[CC * C3];
// conv outputs, bf16 split, [b][c][n]
__device__ bf16 g_Ah[(size_t)BB * CC * NN], g_Al[(size_t)BB * CC * NN];
__device__ bf16 g_Bmh[(size_t)BB * CC * NN], g_Bml[(size_t)BB * CC * NN];
__device__ bf16 g_Dh[(size_t)BB * CC * NN], g_Dl[(size_t)BB * CC * NN];
__device__ bf16 g_xh[(size_t)BB * CC * NN], g_xl[(size_t)BB * CC * NN];
__device__ float g_M[(size_t)BB * NN * NN];
__device__ bf16 g_Mh[(size_t)BB * NN * NN], g_Ml[(size_t)BB * NN * NN];
__device__ float g_S[(size_t)BB * CC * CC];
__device__ bf16 g_Sh[(size_t)BB * CC * CC], g_Sl[(size_t)BB * CC * CC];
__device__ bf16 g_spath[(size_t)BB * CC * NN], g_spatl[(size_t)BB * CC * NN];
__device__ bf16 g_chanh[(size_t)BB * CC * NN], g_chanl[(size_t)BB * CC * NN];

// ---------------- helpers ------------------------------------------------------
__device__ __forceinline__ uint32_t smem_u32(const void* p) {
    uint32_t a;
    asm("{ .reg .u64 t; cvta.to.shared.u64 t, %1; cvt.u32.u64 %0, t; }"
        : "=r"(a) : "l"(p));
    return a;
}
__device__ __forceinline__ void ldsm_x4(uint32_t* r, uint32_t addr) {
    asm volatile("ldmatrix.sync.aligned.m8n8.x4.shared.b16 {%0,%1,%2,%3}, [%4];"
                 : "=r"(r[0]), "=r"(r[1]), "=r"(r[2]), "=r"(r[3]) : "r"(addr));
}
__device__ __forceinline__ void ldsm_x4_t(uint32_t* r, uint32_t addr) {
    asm volatile("ldmatrix.sync.aligned.m8n8.x4.trans.shared.b16 {%0,%1,%2,%3}, [%4];"
                 : "=r"(r[0]), "=r"(r[1]), "=r"(r[2]), "=r"(r[3]) : "r"(addr));
}
__device__ __forceinline__ void ldsm_x2(uint32_t* r, uint32_t addr) {
    asm volatile("ldmatrix.sync.aligned.m8n8.x2.shared.b16 {%0,%1}, [%2];"
                 : "=r"(r[0]), "=r"(r[1]) : "r"(addr));
}
__device__ __forceinline__ void ldsm_x2_t(uint32_t* r, uint32_t addr) {
    asm volatile("ldmatrix.sync.aligned.m8n8.x2.trans.shared.b16 {%0,%1}, [%2];"
                 : "=r"(r[0]), "=r"(r[1]) : "r"(addr));
}
__device__ __forceinline__ void mma16816(float* d, const uint32_t* a, const uint32_t* b) {
    asm volatile("mma.sync.aligned.m16n8k16.row.col.f32.bf16.bf16.f32 "
                 "{%0,%1,%2,%3}, {%4,%5,%6,%7}, {%8,%9}, {%0,%1,%2,%3};"
                 : "+f"(d[0]), "+f"(d[1]), "+f"(d[2]), "+f"(d[3])
                 : "r"(a[0]), "r"(a[1]), "r"(a[2]), "r"(a[3]), "r"(b[0]), "r"(b[1]));
}

// ---------------- GEMM config --------------------------------------------------
// Block 128x128, BK=32, 8 warps (2 M x 4 N), warp tile 64x32.
// K-major tile: 128 rows x 64B (4 chunks), swizzle: ch ^= (row>>1)&3.
// MN-major (trans) tile: 32 k-rows x 256B (16 chunks), swizzle: ch ^= row&7.
#define TILEB 8192
#define STAGES 4
#define GEMM_SMEM (STAGES * 4 * TILEB)   // 128 KB

// one 8KB tile fill via cp.async (256 threads, 2x16B each)
template<bool TR>
__device__ __forceinline__ void load_tile(uint32_t tb, const bf16* __restrict__ S,
                                          long rowbase, long ld, long k0, int tid) {
    if (!TR) {
        #pragma unroll
        for (int p = 0; p < 2; p++) {
            int row = (tid >> 2) + p * 64;
            int ch  = tid & 3;
            const void* g = (const void*)(S + (rowbase + row) * ld + k0 + ch * 8);
            uint32_t dst = tb + (uint32_t)(row * 64 + ((ch ^ ((row >> 1) & 3)) << 4));
            asm volatile("cp.async.cg.shared.global [%0], [%1], 16;"
                         :: "r"(dst), "l"(g) : "memory");
        }
    } else {
        #pragma unroll
        for (int p = 0; p < 2; p++) {
            int row = (tid >> 4) + p * 16;     // k-row 0..31
            int ch  = tid & 15;                // 16 chunks of 16B = 128 cols
            const void* g = (const void*)(S + (k0 + row) * ld + rowbase + ch * 8);
            uint32_t dst = tb + (uint32_t)(row * 256 + ((ch ^ (row & 7)) << 4));
            asm volatile("cp.async.cg.shared.global [%0], [%1], 16;"
                         :: "r"(dst), "l"(g) : "memory");
        }
    }
}

// EPI: 0 = fp32 (+bias), 1 = bf16 hi/lo split (*scale, +bias)
template<bool ATR, bool BTR, int EPI, bool SEG>
__global__ __launch_bounds__(256, 1)
void mma_gemm(const bf16* __restrict__ Ah_, const bf16* __restrict__ Al_, long lda, long bsA,
              const bf16* __restrict__ B0h, const bf16* __restrict__ B0l,
              const bf16* __restrict__ B1h, const bf16* __restrict__ B1l,
              const bf16* __restrict__ B2h, const bf16* __restrict__ B2l,
              long ldb, long bsB,
              float* __restrict__ Cf, bf16* __restrict__ Ch, bf16* __restrict__ Cl,
              long ldc, long bsC,
              const float* __restrict__ bias, const float* __restrict__ scale, int K)
{
    extern __shared__ char smem[];
    const uint32_t sb = smem_u32(smem);
    const int tid = threadIdx.x;
    const int wid = tid >> 5, lane = tid & 31;
    const int warp_m = wid & 1, warp_n = wid >> 1;
    const long m0 = (long)blockIdx.y * 128, n0 = (long)blockIdx.x * 128;
    const long zA = (long)blockIdx.z * bsA, zB = (long)blockIdx.z * bsB;
    Ah_ += zA;  Al_ += zA;
    B0h += zB;  B0l += zB;  B1h += zB;  B1l += zB;  B2h += zB;  B2l += zB;

    float d[4][4][4];
    #pragma unroll
    for (int i = 0; i < 4; i++)
        #pragma unroll
        for (int j = 0; j < 4; j++)
            #pragma unroll
            for (int q = 0; q < 4; q++) d[i][j][q] = 0.f;

    const int NC = K >> 5;

    auto loadstage = [&](int i) {
        const int s = i & (STAGES - 1);
        const long k0 = (long)i * 32;
        const bf16 *Bh = B0h, *Bl = B0l;
        long kb = k0;
        if (SEG) {
            int seg = (int)(k0 >> 9);
            kb = k0 & 511;
            Bh = (seg == 0) ? B0h : (seg == 1) ? B1h : B2h;
            Bl = (seg == 0) ? B0l : (seg == 1) ? B1l : B2l;
        }
        uint32_t tb = sb + (uint32_t)s * 4 * TILEB;
        load_tile<ATR>(tb,             Ah_, m0, lda, k0, tid);
        load_tile<ATR>(tb + TILEB,     Al_, m0, lda, k0, tid);
        load_tile<BTR>(tb + 2 * TILEB, Bh,  n0, ldb, kb, tid);
        load_tile<BTR>(tb + 3 * TILEB, Bl,  n0, ldb, kb, tid);
        asm volatile("cp.async.commit_group;" ::: "memory");
    };

    const int npro = (NC < STAGES - 1) ? NC : (STAGES - 1);
    for (int i = 0; i < npro; i++) loadstage(i);

    for (int i = 0; i < NC; i++) {
        if (i + STAGES - 1 < NC) {
            loadstage(i + STAGES - 1);
            asm volatile("cp.async.wait_group %0;" :: "n"(STAGES - 1) : "memory");
        } else {
            asm volatile("cp.async.wait_group 0;" ::: "memory");
        }
        __syncthreads();

        const int s = i & (STAGES - 1);
        const uint32_t bAh = sb + (uint32_t)(s * 4 + 0) * TILEB;
        const uint32_t bAl = sb + (uint32_t)(s * 4 + 1) * TILEB;
        const uint32_t bBh = sb + (uint32_t)(s * 4 + 2) * TILEB;
        const uint32_t bBl = sb + (uint32_t)(s * 4 + 3) * TILEB;

        #pragma unroll
        for (int ks = 0; ks < 2; ks++) {
            uint32_t ah[4][4], al[4][4];
            #pragma unroll
            for (int tm = 0; tm < 4; tm++) {
                if (!ATR) {
                    int row = warp_m * 64 + tm * 16 + (lane & 15);
                    int ch  = ks * 2 + (lane >> 4);
                    uint32_t off = (uint32_t)(row * 64 + ((ch ^ ((row >> 1) & 3)) << 4));
                    ldsm_x4(ah[tm], bAh + off);
                    ldsm_x4(al[tm], bAl + off);
                } else {
                    int krow = ks * 16 + (lane & 7) + ((lane >> 4) << 3);
                    int mch  = ((warp_m * 64 + tm * 16) >> 3) + ((lane >> 3) & 1);
                    uint32_t off = (uint32_t)(krow * 256 + ((mch ^ (krow & 7)) << 4));
                    ldsm_x4_t(ah[tm], bAh + off);
                    ldsm_x4_t(al[tm], bAl + off);
                }
            }
            uint32_t bh[4][2], bl[4][2];
            #pragma unroll
            for (int tn = 0; tn < 4; tn++) {
                if (!BTR) {
                    int row = warp_n * 32 + tn * 8 + (lane & 7);
                    int ch  = ks * 2 + ((lane >> 3) & 1);
                    uint32_t off = (uint32_t)(row * 64 + ((ch ^ ((row >> 1) & 3)) << 4));
                    ldsm_x2(bh[tn], bBh + off);
                    ldsm_x2(bl[tn], bBl + off);
                } else {
                    int krow = ks * 16 + (lane & 7) + ((lane >> 3) & 1) * 8;
                    int nch  = (warp_n * 32 + tn * 8) >> 3;
                    uint32_t off = (uint32_t)(krow * 256 + ((nch ^ (krow & 7)) << 4));
                    ldsm_x2_t(bh[tn], bBh + off);
                    ldsm_x2_t(bl[tn], bBl + off);
                }
            }
            #pragma unroll
            for (int tm = 0; tm < 4; tm++)
                #pragma unroll
                for (int tn = 0; tn < 4; tn++) {
                    mma16816(d[tm][tn], ah[tm], bh[tn]);
                    mma16816(d[tm][tn], ah[tm], bl[tn]);
                    mma16816(d[tm][tn], al[tm], bh[tn]);
                }
        }
        __syncthreads();
    }

    // ---------------- epilogue ----------------
    if (EPI == 0) {
        float* Cb = Cf + (long)blockIdx.z * bsC;
        #pragma unroll
        for (int tm = 0; tm < 4; tm++) {
            const long m = m0 + warp_m * 64 + tm * 16 + (lane >> 2);
            const float bs0 = bias ? bias[m]     : 0.f;
            const float bs1 = bias ? bias[m + 8] : 0.f;
            #pragma unroll
            for (int tn = 0; tn < 4; tn++) {
                const long n = n0 + warp_n * 32 + tn * 8 + (lane & 3) * 2;
                *(float2*)&Cb[m * ldc + n] =
                    make_float2(d[tm][tn][0] + bs0, d[tm][tn][1] + bs0);
                *(float2*)&Cb[(m + 8) * ldc + n] =
                    make_float2(d[tm][tn][2] + bs1, d[tm][tn][3] + bs1);
            }
        }
    } else {
        bf16* Hb = Ch + (long)blockIdx.z * bsC;
        bf16* Lb = Cl + (long)blockIdx.z * bsC;
        const float sc = scale ? *scale : 1.0f;
        #pragma unroll
        for (int tm = 0; tm < 4; tm++) {
            const long m = m0 + warp_m * 64 + tm * 16 + (lane >> 2);
            const float bs0 = bias ? bias[m]     : 0.f;
            const float bs1 = bias ? bias[m + 8] : 0.f;
            #pragma unroll
            for (int tn = 0; tn < 4; tn++) {
                const long n = n0 + warp_n * 32 + tn * 8 + (lane & 3) * 2;
                float v0 = d[tm][tn][0] * sc + bs0;
                float v1 = d[tm][tn][1] * sc + bs0;
                float v2 = d[tm][tn][2] * sc + bs1;
                float v3 = d[tm][tn][3] * sc + bs1;
                __nv_bfloat162 hv0, lv0, hv1, lv1;
                hv0.x = __float2bfloat16(v0);
                hv0.y = __float2bfloat16(v1);
                lv0.x = __float2bfloat16(v0 - __bfloat162float(hv0.x));
                lv0.y = __float2bfloat16(v1 - __bfloat162float(hv0.y));
                hv1.x = __float2bfloat16(v2);
                hv1.y = __float2bfloat16(v3);
                lv1.x = __float2bfloat16(v2 - __bfloat162float(hv1.x));
                lv1.y = __float2bfloat16(v3 - __bfloat162float(hv1.y));
                *(__nv_bfloat162*)&Hb[m * ldc + n]       = hv0;
                *(__nv_bfloat162*)&Lb[m * ldc + n]       = lv0;
                *(__nv_bfloat162*)&Hb[(m + 8) * ldc + n] = hv1;
                *(__nv_bfloat162*)&Lb[(m + 8) * ldc + n] = lv1;
            }
        }
    }
}

// ---------------- im2col + split ------------------------------------------------
__global__ void im2col_split(const float* __restrict__ x,
                             bf16* __restrict__ oh, bf16* __restrict__ ol) {
    long gid = (long)blockIdx.x * 256 + threadIdx.x;
    int k = (int)(gid % K9);
    long r = gid / K9;
    int n = (int)(r & (NN - 1));
    int b = (int)(r >> 10);
    int ci = k / 9, tap = k % 9;
    int dy = tap / 3 - 1, dx = tap % 3 - 1;
    int h = n >> 5, w = n & 31;
    int ih = h + dy, iw = w + dx;
    float v = 0.f;
    if ((unsigned)ih < HH && (unsigned)iw < WW)
        v = x[(((long)b * CC + ci) * HH + ih) * WW + iw];
    bf16 hi = __float2bfloat16(v);
    oh[gid] = hi;
    ol[gid] = __float2bfloat16(v - __bfloat162float(hi));
}

__global__ void split_kernel(const float* __restrict__ in,
                             bf16* __restrict__ oh, bf16* __restrict__ ol) {
    long g = (long)blockIdx.x * 256 + threadIdx.x;
    float v = in[g];
    bf16 hi = __float2bfloat16(v);
    oh[g] = hi;
    ol[g] = __float2bfloat16(v - __bfloat162float(hi));
}

// ---------------- softmax -------------------------------------------------------
__device__ __forceinline__ float warpMax(float v) {
    #pragma unroll
    for (int o = 16; o > 0; o >>= 1) v = fmaxf(v, __shfl_xor_sync(0xffffffffu, v, o));
    return v;
}
__device__ __forceinline__ float warpSum(float v) {
    #pragma unroll
    for (int o = 16; o > 0; o >>= 1) v += __shfl_xor_sync(0xffffffffu, v, o);
    return v;
}

template<int LEN>
__global__ __launch_bounds__(256)
void softmax_split(const float* __restrict__ buf,
                   bf16* __restrict__ oh, bf16* __restrict__ ol) {
    constexpr int V = LEN / 256;
    const long base = (long)blockIdx.x * LEN;
    const float* row = buf + base;
    const int tid = threadIdx.x, lane = tid & 31, wid = tid >> 5;
    __shared__ float sred[8];
    float v[V];
    float mx = -3.0e38f;
    #pragma unroll
    for (int j = 0; j < V; j++) { v[j] = row[tid + j * 256]; mx = fmaxf(mx, v[j]); }
    mx = warpMax(mx);
    if (lane == 0) sred[wid] = mx;
    __syncthreads();
    if (tid == 0) {
        float m = sred[0];
        #pragma unroll
        for (int i = 1; i < 8; i++) m = fmaxf(m, sred[i]);
        sred[0] = m;
    }
    __syncthreads();
    mx = sred[0];
    __syncthreads();
    float s = 0.f;
    #pragma unroll
    for (int j = 0; j < V; j++) { v[j] = __expf(v[j] - mx); s += v[j]; }
    s = warpSum(s);
    if (lane == 0) sred[wid] = s;
    __syncthreads();
    if (tid == 0) {
        float m = 0.f;
        #pragma unroll
        for (int i = 0; i < 8; i++) m += sred[i];
        sred[0] = m;
    }
    __syncthreads();
    const float inv = 1.0f / sred[0];
    #pragma unroll
    for (int j = 0; j < V; j++) {
        float w = v[j] * inv;
        bf16 hi = __float2bfloat16(w);
        oh[base + tid + j * 256] = hi;
        ol[base + tid + j * 256] = __float2bfloat16(w - __bfloat162float(hi));
    }
}

// ---------------- launch --------------------------------------------------------
extern "C" void kernel_launch(void* const* d_in, const int* in_sizes, int n_in,
                              void* d_out, int out_size) {
    const float* x     = (const float*)d_in[0];
    const float* w1    = (const float*)d_in[1];
    const float* b1    = (const float*)d_in[2];
    const float* w2    = (const float*)d_in[3];
    const float* b2    = (const float*)d_in[4];
    const float* w3    = (const float*)d_in[5];
    const float* b3    = (const float*)d_in[6];
    const float* alpha = (const float*)d_in[7];
    const float* beta  = (const float*)d_in[8];
    const float* wf    = (const float*)d_in[9];
    const float* bf    = (const float*)d_in[10];
    float* out = (float*)d_out;

    cudaFuncSetAttribute(mma_gemm<false,false,1,false>, cudaFuncAttributeMaxDynamicSharedMemorySize, GEMM_SMEM);
    cudaFuncSetAttribute(mma_gemm<true, true, 0,false>, cudaFuncAttributeMaxDynamicSharedMemorySize, GEMM_SMEM);
    cudaFuncSetAttribute(mma_gemm<false,false,0,false>, cudaFuncAttributeMaxDynamicSharedMemorySize, GEMM_SMEM);
    cudaFuncSetAttribute(mma_gemm<true, true, 1,false>, cudaFuncAttributeMaxDynamicSharedMemorySize, GEMM_SMEM);
    cudaFuncSetAttribute(mma_gemm<false,true, 0,true >, cudaFuncAttributeMaxDynamicSharedMemorySize, GEMM_SMEM);

    bf16 *xcolTh, *xcolTl, *w1h, *w1l, *w2h, *w2l, *w3h, *w3l, *wfh, *wfl;
    bf16 *Ah, *Al, *Bmh, *Bml, *Dh, *Dl, *xh, *xl, *Mh, *Ml, *Sh, *Sl;
    bf16 *spath, *spatl, *chanh, *chanl;
    float *Mb, *Sb;
    cudaGetSymbolAddress((void**)&xcolTh, g_xcolT_h);
    cudaGetSymbolAddress((void**)&xcolTl, g_xcolT_l);
    cudaGetSymbolAddress((void**)&w1h, g_w1h);  cudaGetSymbolAddress((void**)&w1l, g_w1l);
    cudaGetSymbolAddress((void**)&w2h, g_w2h);  cudaGetSymbolAddress((void**)&w2l, g_w2l);
    cudaGetSymbolAddress((void**)&w3h, g_w3h);  cudaGetSymbolAddress((void**)&w3l, g_w3l);
    cudaGetSymbolAddress((void**)&wfh, g_wfh);  cudaGetSymbolAddress((void**)&wfl, g_wfl);
    cudaGetSymbolAddress((void**)&Ah,  g_Ah);   cudaGetSymbolAddress((void**)&Al,  g_Al);
    cudaGetSymbolAddress((void**)&Bmh, g_Bmh);  cudaGetSymbolAddress((void**)&Bml, g_Bml);
    cudaGetSymbolAddress((void**)&Dh,  g_Dh);   cudaGetSymbolAddress((void**)&Dl,  g_Dl);
    cudaGetSymbolAddress((void**)&xh,  g_xh);   cudaGetSymbolAddress((void**)&xl,  g_xl);
    cudaGetSymbolAddress((void**)&Mb,  g_M);
    cudaGetSymbolAddress((void**)&Mh,  g_Mh);   cudaGetSymbolAddress((void**)&Ml,  g_Ml);
    cudaGetSymbolAddress((void**)&Sb,  g_S);
    cudaGetSymbolAddress((void**)&Sh,  g_Sh);   cudaGetSymbolAddress((void**)&Sl,  g_Sl);
    cudaGetSymbolAddress((void**)&spath, g_spath); cudaGetSymbolAddress((void**)&spatl, g_spatl);
    cudaGetSymbolAddress((void**)&chanh, g_chanh); cudaGetSymbolAddress((void**)&chanl, g_chanl);

    const long sX  = (long)CC * NN;
    const long sM  = (long)NN * NN;
    const long sS  = (long)CC * CC;
    const long sCol = (long)NN * K9;

    // 1) im2col + split, input/weight splits
    im2col_split<<<(unsigned)((long)BB * NN * K9 / 256), 256>>>(x, xcolTh, xcolTl);
    split_kernel<<<CC * K9 / 256, 256>>>(w1, w1h, w1l);
    split_kernel<<<CC * K9 / 256, 256>>>(w2, w2h, w2l);
    split_kernel<<<CC * K9 / 256, 256>>>(w3, w3h, w3l);
    split_kernel<<<CC * C3 / 256, 256>>>(wf, wfh, wfl);
    split_kernel<<<(unsigned)((long)BB * sX / 256), 256>>>(x, xh, xl);

    // 2) convs: C[c][n] = W[c][:] . xcolT[n][:] + b   (epi: bf16 split)
    {
        dim3 g(NN / 128, CC / 128, BB);
        mma_gemm<false,false,1,false><<<g, 256, GEMM_SMEM>>>(
            w1h, w1l, K9, 0, xcolTh, xcolTl, xcolTh, xcolTl, xcolTh, xcolTl, K9, sCol,
            nullptr, Ah, Al, NN, sX, b1, nullptr, K9);
        mma_gemm<false,false,1,false><<<g, 256, GEMM_SMEM>>>(
            w2h, w2l, K9, 0, xcolTh, xcolTl, xcolTh, xcolTl, xcolTh, xcolTl, K9, sCol,
            nullptr, Bmh, Bml, NN, sX, b2, nullptr, K9);
        mma_gemm<false,false,1,false><<<g, 256, GEMM_SMEM>>>(
            w3h, w3l, K9, 0, xcolTh, xcolTl, xcolTh, xcolTl, xcolTh, xcolTl, K9, sCol,
            nullptr, Dh, Dl, NN, sX, b3, nullptr, K9);
    }

    // 3) M[n][m] = sum_c A[c][n]*Bm[c][m]   (both operands MN-major -> trans)
    {
        dim3 g(NN / 128, NN / 128, BB);
        mma_gemm<true,true,0,false><<<g, 256, GEMM_SMEM>>>(
            Ah, Al, NN, sX, Bmh, Bml, Bmh, Bml, Bmh, Bml, NN, sX,
            Mb, nullptr, nullptr, NN, sM, nullptr, nullptr, CC);
    }

    // 4) softmax rows of M -> Mh/Ml
    softmax_split<NN><<<BB * NN, 256>>>(Mb, Mh, Ml);

    // 5) spat[c][n] = sum_m D[c][m]*Msm[n][m]   (epi: alpha * -> bf16 split)
    {
        dim3 g(NN / 128, CC / 128, BB);
        mma_gemm<false,false,1,false><<<g, 256, GEMM_SMEM>>>(
            Dh, Dl, NN, sX, Mh, Ml, Mh, Ml, Mh, Ml, NN, sM,
            nullptr, spath, spatl, NN, sX, nullptr, alpha, NN);
    }

    // 6) S[c][d] = sum_n x[c][n]*x[d][n]
    {
        dim3 g(CC / 128, CC / 128, BB);
        mma_gemm<false,false,0,false><<<g, 256, GEMM_SMEM>>>(
            xh, xl, NN, sX, xh, xl, xh, xl, xh, xl, NN, sX,
            Sb, nullptr, nullptr, CC, sS, nullptr, nullptr, NN);
    }

    // 7) softmax rows of S -> Sh/Sl
    softmax_split<CC><<<BB * CC, 256>>>(Sb, Sh, Sl);

    // 8) chan[c][n] = sum_d Ssm[d][c]*x[d][n]  (both trans; epi: beta * -> bf16 split)
    {
        dim3 g(NN / 128, CC / 128, BB);
        mma_gemm<true,true,1,false><<<g, 256, GEMM_SMEM>>>(
            Sh, Sl, CC, sS, xh, xl, xh, xl, xh, xl, NN, sX,
            nullptr, chanh, chanl, NN, sX, nullptr, beta, CC);
    }

    // 9) fuse: out[c][n] = bf[c] + sum over [x; a*spat; b*chan] (segmented B, trans)
    {
        dim3 g(NN / 128, CC / 128, BB);
        mma_gemm<false,true,0,true><<<g, 256, GEMM_SMEM>>>(
            wfh, wfl, C3, 0, xh, xl, spath, spatl, chanh, chanl, NN, sX,
            out, nullptr, nullptr, NN, sX, bf, nullptr, C3);
    }
}

// round 6
// speedup vs baseline: 3.4726x; 1.0025x over previous
#include <cuda_runtime.h>
#include <cuda_bf16.h>
#include <cstdint>

#define BB 16
#define CC 512
#define HH 32
#define WW 32
#define NN 1024
#define K9 4608
#define C3 1536

typedef __nv_bfloat16 bf16;

// ---------------- scratch (device globals) -----------------------------------
__device__ bf16 g_xcolT_h[(size_t)BB * NN * K9];
__device__ bf16 g_xcolT_l[(size_t)BB * NN * K9];
__device__ bf16 g_w1h[CC * K9], g_w1l[CC * K9];
__device__ bf16 g_w2h[CC * K9], g_w2l[CC * K9];
__device__ bf16 g_w3h[CC * K9], g_w3l[CC * K9];
__device__ bf16 g_wfh[CC * C3], g_wfl[CC * C3];
__device__ bf16 g_Ah[(size_t)BB * CC * NN], g_Al[(size_t)BB * CC * NN];
__device__ bf16 g_Bmh[(size_t)BB * CC * NN], g_Bml[(size_t)BB * CC * NN];
__device__ bf16 g_Dh[(size_t)BB * CC * NN], g_Dl[(size_t)BB * CC * NN];
__device__ bf16 g_xh[(size_t)BB * CC * NN], g_xl[(size_t)BB * CC * NN];
__device__ float g_M[(size_t)BB * NN * NN];
__device__ bf16 g_Mh[(size_t)BB * NN * NN], g_Ml[(size_t)BB * NN * NN];
__device__ float g_S[(size_t)BB * CC * CC];
__device__ bf16 g_Sh[(size_t)BB * CC * CC], g_Sl[(size_t)BB * CC * CC];
__device__ bf16 g_spath[(size_t)BB * CC * NN], g_spatl[(size_t)BB * CC * NN];
__device__ bf16 g_chanh[(size_t)BB * CC * NN], g_chanl[(size_t)BB * CC * NN];

// ---------------- helpers ------------------------------------------------------
__device__ __forceinline__ uint32_t smem_u32(const void* p) {
    uint32_t a;
    asm("{ .reg .u64 t; cvta.to.shared.u64 t, %1; cvt.u32.u64 %0, t; }"
        : "=r"(a) : "l"(p));
    return a;
}
__device__ __forceinline__ void ldsm_x4(uint32_t* r, uint32_t addr) {
    asm volatile("ldmatrix.sync.aligned.m8n8.x4.shared.b16 {%0,%1,%2,%3}, [%4];"
                 : "=r"(r[0]), "=r"(r[1]), "=r"(r[2]), "=r"(r[3]) : "r"(addr));
}
__device__ __forceinline__ void ldsm_x4_t(uint32_t* r, uint32_t addr) {
    asm volatile("ldmatrix.sync.aligned.m8n8.x4.trans.shared.b16 {%0,%1,%2,%3}, [%4];"
                 : "=r"(r[0]), "=r"(r[1]), "=r"(r[2]), "=r"(r[3]) : "r"(addr));
}
__device__ __forceinline__ void ldsm_x2(uint32_t* r, uint32_t addr) {
    asm volatile("ldmatrix.sync.aligned.m8n8.x2.shared.b16 {%0,%1}, [%2];"
                 : "=r"(r[0]), "=r"(r[1]) : "r"(addr));
}
__device__ __forceinline__ void ldsm_x2_t(uint32_t* r, uint32_t addr) {
    asm volatile("ldmatrix.sync.aligned.m8n8.x2.trans.shared.b16 {%0,%1}, [%2];"
                 : "=r"(r[0]), "=r"(r[1]) : "r"(addr));
}
__device__ __forceinline__ void mma16816(float* d, const uint32_t* a, const uint32_t* b) {
    asm volatile("mma.sync.aligned.m16n8k16.row.col.f32.bf16.bf16.f32 "
                 "{%0,%1,%2,%3}, {%4,%5,%6,%7}, {%8,%9}, {%0,%1,%2,%3};"
                 : "+f"(d[0]), "+f"(d[1]), "+f"(d[2]), "+f"(d[3])
                 : "r"(a[0]), "r"(a[1]), "r"(a[2]), "r"(a[3]), "r"(b[0]), "r"(b[1]));
}

// ---------------- GEMM config --------------------------------------------------
// Block 128x128, BK=32, 8 warps (2 M x 4 N), warp tile 64x32.
// K-major tile: 128 rows x 64B (4 chunks), swizzle: ch ^= (row>>1)&3.
// MN-major (trans) tile: 32 k-rows x 256B (16 chunks), swizzle: ch ^= row&7.
#define TILEB 8192
#define STAGES 4
#define GEMM_SMEM (STAGES * 4 * TILEB)   // 128 KB

template<bool TR>
__device__ __forceinline__ void load_tile(uint32_t tb, const bf16* __restrict__ S,
                                          long rowbase, long ld, long k0, int tid) {
    if (!TR) {
        #pragma unroll
        for (int p = 0; p < 2; p++) {
            int row = (tid >> 2) + p * 64;
            int ch  = tid & 3;
            const void* g = (const void*)(S + (rowbase + row) * ld + k0 + ch * 8);
            uint32_t dst = tb + (uint32_t)(row * 64 + ((ch ^ ((row >> 1) & 3)) << 4));
            asm volatile("cp.async.cg.shared.global [%0], [%1], 16;"
                         :: "r"(dst), "l"(g) : "memory");
        }
    } else {
        #pragma unroll
        for (int p = 0; p < 2; p++) {
            int row = (tid >> 4) + p * 16;
            int ch  = tid & 15;
            const void* g = (const void*)(S + (k0 + row) * ld + rowbase + ch * 8);
            uint32_t dst = tb + (uint32_t)(row * 256 + ((ch ^ (row & 7)) << 4));
            asm volatile("cp.async.cg.shared.global [%0], [%1], 16;"
                         :: "r"(dst), "l"(g) : "memory");
        }
    }
}

// EPI: 0 = fp32 (+bias), 1 = bf16 hi/lo split (*scale, +bias)
template<bool ATR, bool BTR, int EPI, bool SEG>
__global__ __launch_bounds__(256, 1)
void mma_gemm(const bf16* __restrict__ Ah_, const bf16* __restrict__ Al_, long lda, long bsA,
              const bf16* __restrict__ B0h, const bf16* __restrict__ B0l,
              const bf16* __restrict__ B1h, const bf16* __restrict__ B1l,
              const bf16* __restrict__ B2h, const bf16* __restrict__ B2l,
              long ldb, long bsB,
              float* __restrict__ Cf, bf16* __restrict__ Ch, bf16* __restrict__ Cl,
              long ldc, long bsC,
              const float* __restrict__ bias, const float* __restrict__ scale, int K)
{
    extern __shared__ char smem[];
    const uint32_t sb = smem_u32(smem);
    const int tid = threadIdx.x;
    const int wid = tid >> 5, lane = tid & 31;
    const int warp_m = wid & 1, warp_n = wid >> 1;
    const long m0 = (long)blockIdx.y * 128, n0 = (long)blockIdx.x * 128;
    const long zA = (long)blockIdx.z * bsA, zB = (long)blockIdx.z * bsB;
    Ah_ += zA;  Al_ += zA;
    B0h += zB;  B0l += zB;  B1h += zB;  B1l += zB;  B2h += zB;  B2l += zB;

    float d[4][4][4];
    #pragma unroll
    for (int i = 0; i < 4; i++)
        #pragma unroll
        for (int j = 0; j < 4; j++)
            #pragma unroll
            for (int q = 0; q < 4; q++) d[i][j][q] = 0.f;

    const int NC = K >> 5;

    auto loadstage = [&](int i) {
        const int s = i & (STAGES - 1);
        const long k0 = (long)i * 32;
        const bf16 *Bh = B0h, *Bl = B0l;
        long kb = k0;
        if (SEG) {
            int seg = (int)(k0 >> 9);
            kb = k0 & 511;
            Bh = (seg == 0) ? B0h : (seg == 1) ? B1h : B2h;
            Bl = (seg == 0) ? B0l : (seg == 1) ? B1l : B2l;
        }
        uint32_t tb = sb + (uint32_t)s * 4 * TILEB;
        load_tile<ATR>(tb,             Ah_, m0, lda, k0, tid);
        load_tile<ATR>(tb + TILEB,     Al_, m0, lda, k0, tid);
        load_tile<BTR>(tb + 2 * TILEB, Bh,  n0, ldb, kb, tid);
        load_tile<BTR>(tb + 3 * TILEB, Bl,  n0, ldb, kb, tid);
        asm volatile("cp.async.commit_group;" ::: "memory");
    };

    // prologue: stages 0 .. STAGES-2
    for (int i = 0; i < STAGES - 1; i++) {
        if (i < NC) loadstage(i);
        else        asm volatile("cp.async.commit_group;" ::: "memory");
    }

    for (int i = 0; i < NC; i++) {
        asm volatile("cp.async.wait_group %0;" :: "n"(STAGES - 2) : "memory");
        __syncthreads();
        // issue next stage AFTER sync: slot (i+STAGES-1)&3 == (i-1)&3, whose
        // consumers all passed the sync above.
        if (i + STAGES - 1 < NC) loadstage(i + STAGES - 1);
        else                     asm volatile("cp.async.commit_group;" ::: "memory");

        const int s = i & (STAGES - 1);
        const uint32_t bAh = sb + (uint32_t)(s * 4 + 0) * TILEB;
        const uint32_t bAl = sb + (uint32_t)(s * 4 + 1) * TILEB;
        const uint32_t bBh = sb + (uint32_t)(s * 4 + 2) * TILEB;
        const uint32_t bBl = sb + (uint32_t)(s * 4 + 3) * TILEB;

        #pragma unroll
        for (int ks = 0; ks < 2; ks++) {
            uint32_t ah[4][4], al[4][4];
            #pragma unroll
            for (int tm = 0; tm < 4; tm++) {
                if (!ATR) {
                    int row = warp_m * 64 + tm * 16 + (lane & 15);
                    int ch  = ks * 2 + (lane >> 4);
                    uint32_t off = (uint32_t)(row * 64 + ((ch ^ ((row >> 1) & 3)) << 4));
                    ldsm_x4(ah[tm], bAh + off);
                    ldsm_x4(al[tm], bAl + off);
                } else {
                    int krow = ks * 16 + (lane & 7) + ((lane >> 4) << 3);
                    int mch  = ((warp_m * 64 + tm * 16) >> 3) + ((lane >> 3) & 1);
                    uint32_t off = (uint32_t)(krow * 256 + ((mch ^ (krow & 7)) << 4));
                    ldsm_x4_t(ah[tm], bAh + off);
                    ldsm_x4_t(al[tm], bAl + off);
                }
            }
            uint32_t bh[4][2], bl[4][2];
            #pragma unroll
            for (int tn = 0; tn < 4; tn++) {
                if (!BTR) {
                    int row = warp_n * 32 + tn * 8 + (lane & 7);
                    int ch  = ks * 2 + ((lane >> 3) & 1);
                    uint32_t off = (uint32_t)(row * 64 + ((ch ^ ((row >> 1) & 3)) << 4));
                    ldsm_x2(bh[tn], bBh + off);
                    ldsm_x2(bl[tn], bBl + off);
                } else {
                    int krow = ks * 16 + (lane & 7) + ((lane >> 3) & 1) * 8;
                    int nch  = (warp_n * 32 + tn * 8) >> 3;
                    uint32_t off = (uint32_t)(krow * 256 + ((nch ^ (krow & 7)) << 4));
                    ldsm_x2_t(bh[tn], bBh + off);
                    ldsm_x2_t(bl[tn], bBl + off);
                }
            }
            // term-outer order: consecutive volatile MMAs target distinct
            // accumulators (dependency distance 16 instead of 1).
            // Per-accumulator order stays hh, hl, lh -> bit-identical results.
            #pragma unroll
            for (int q = 0; q < 3; q++)
                #pragma unroll
                for (int tm = 0; tm < 4; tm++)
                    #pragma unroll
                    for (int tn = 0; tn < 4; tn++) {
                        const uint32_t* aa = (q == 2) ? al[tm] : ah[tm];
                        const uint32_t* bb = (q == 1) ? bl[tn] : bh[tn];
                        mma16816(d[tm][tn], aa, bb);
                    }
        }
        __syncthreads();
    }

    // ---------------- epilogue ----------------
    if (EPI == 0) {
        float* Cb = Cf + (long)blockIdx.z * bsC;
        #pragma unroll
        for (int tm = 0; tm < 4; tm++) {
            const long m = m0 + warp_m * 64 + tm * 16 + (lane >> 2);
            const float bs0 = bias ? bias[m]     : 0.f;
            const float bs1 = bias ? bias[m + 8] : 0.f;
            #pragma unroll
            for (int tn = 0; tn < 4; tn++) {
                const long n = n0 + warp_n * 32 + tn * 8 + (lane & 3) * 2;
                *(float2*)&Cb[m * ldc + n] =
                    make_float2(d[tm][tn][0] + bs0, d[tm][tn][1] + bs0);
                *(float2*)&Cb[(m + 8) * ldc + n] =
                    make_float2(d[tm][tn][2] + bs1, d[tm][tn][3] + bs1);
            }
        }
    } else {
        bf16* Hb = Ch + (long)blockIdx.z * bsC;
        bf16* Lb = Cl + (long)blockIdx.z * bsC;
        const float sc = scale ? *scale : 1.0f;
        #pragma unroll
        for (int tm = 0; tm < 4; tm++) {
            const long m = m0 + warp_m * 64 + tm * 16 + (lane >> 2);
            const float bs0 = bias ? bias[m]     : 0.f;
            const float bs1 = bias ? bias[m + 8] : 0.f;
            #pragma unroll
            for (int tn = 0; tn < 4; tn++) {
                const long n = n0 + warp_n * 32 + tn * 8 + (lane & 3) * 2;
                float v0 = d[tm][tn][0] * sc + bs0;
                float v1 = d[tm][tn][1] * sc + bs0;
                float v2 = d[tm][tn][2] * sc + bs1;
                float v3 = d[tm][tn][3] * sc + bs1;
                __nv_bfloat162 hv0, lv0, hv1, lv1;
                hv0.x = __float2bfloat16(v0);
                hv0.y = __float2bfloat16(v1);
                lv0.x = __float2bfloat16(v0 - __bfloat162float(hv0.x));
                lv0.y = __float2bfloat16(v1 - __bfloat162float(hv0.y));
                hv1.x = __float2bfloat16(v2);
                hv1.y = __float2bfloat16(v3);
                lv1.x = __float2bfloat16(v2 - __bfloat162float(hv1.x));
                lv1.y = __float2bfloat16(v3 - __bfloat162float(hv1.y));
                *(__nv_bfloat162*)&Hb[m * ldc + n]       = hv0;
                *(__nv_bfloat162*)&Lb[m * ldc + n]       = lv0;
                *(__nv_bfloat162*)&Hb[(m + 8) * ldc + n] = hv1;
                *(__nv_bfloat162*)&Lb[(m + 8) * ldc + n] = lv1;
            }
        }
    }
}

// ---------------- im2col + split ------------------------------------------------
__global__ void im2col_split(const float* __restrict__ x,
                             bf16* __restrict__ oh, bf16* __restrict__ ol) {
    long gid = (long)blockIdx.x * 256 + threadIdx.x;
    int k = (int)(gid % K9);
    long r = gid / K9;
    int n = (int)(r & (NN - 1));
    int b = (int)(r >> 10);
    int ci = k / 9, tap = k % 9;
    int dy = tap / 3 - 1, dx = tap % 3 - 1;
    int h = n >> 5, w = n & 31;
    int ih = h + dy, iw = w + dx;
    float v = 0.f;
    if ((unsigned)ih < HH && (unsigned)iw < WW)
        v = x[(((long)b * CC + ci) * HH + ih) * WW + iw];
    bf16 hi = __float2bfloat16(v);
    oh[gid] = hi;
    ol[gid] = __float2bfloat16(v - __bfloat162float(hi));
}

__global__ void split_kernel(const float* __restrict__ in,
                             bf16* __restrict__ oh, bf16* __restrict__ ol) {
    long g = (long)blockIdx.x * 256 + threadIdx.x;
    float v = in[g];
    bf16 hi = __float2bfloat16(v);
    oh[g] = hi;
    ol[g] = __float2bfloat16(v - __bfloat162float(hi));
}

// ---------------- softmax -------------------------------------------------------
__device__ __forceinline__ float warpMax(float v) {
    #pragma unroll
    for (int o = 16; o > 0; o >>= 1) v = fmaxf(v, __shfl_xor_sync(0xffffffffu, v, o));
    return v;
}
__device__ __forceinline__ float warpSum(float v) {
    #pragma unroll
    for (int o = 16; o > 0; o >>= 1) v += __shfl_xor_sync(0xffffffffu, v, o);
    return v;
}

template<int LEN>
__global__ __launch_bounds__(256)
void softmax_split(const float* __restrict__ buf,
                   bf16* __restrict__ oh, bf16* __restrict__ ol) {
    constexpr int V = LEN / 256;
    const long base = (long)blockIdx.x * LEN;
    const float* row = buf + base;
    const int tid = threadIdx.x, lane = tid & 31, wid = tid >> 5;
    __shared__ float sred[8];
    float v[V];
    float mx = -3.0e38f;
    #pragma unroll
    for (int j = 0; j < V; j++) { v[j] = row[tid + j * 256]; mx = fmaxf(mx, v[j]); }
    mx = warpMax(mx);
    if (lane == 0) sred[wid] = mx;
    __syncthreads();
    if (tid == 0) {
        float m = sred[0];
        #pragma unroll
        for (int i = 1; i < 8; i++) m = fmaxf(m, sred[i]);
        sred[0] = m;
    }
    __syncthreads();
    mx = sred[0];
    __syncthreads();
    float s = 0.f;
    #pragma unroll
    for (int j = 0; j < V; j++) { v[j] = __expf(v[j] - mx); s += v[j]; }
    s = warpSum(s);
    if (lane == 0) sred[wid] = s;
    __syncthreads();
    if (tid == 0) {
        float m = 0.f;
        #pragma unroll
        for (int i = 0; i < 8; i++) m += sred[i];
        sred[0] = m;
    }
    __syncthreads();
    const float inv = 1.0f / sred[0];
    #pragma unroll
    for (int j = 0; j < V; j++) {
        float w = v[j] * inv;
        bf16 hi = __float2bfloat16(w);
        oh[base + tid + j * 256] = hi;
        ol[base + tid + j * 256] = __float2bfloat16(w - __bfloat162float(hi));
    }
}

// ---------------- launch --------------------------------------------------------
extern "C" void kernel_launch(void* const* d_in, const int* in_sizes, int n_in,
                              void* d_out, int out_size) {
    const float* x     = (const float*)d_in[0];
    const float* w1    = (const float*)d_in[1];
    const float* b1    = (const float*)d_in[2];
    const float* w2    = (const float*)d_in[3];
    const float* b2    = (const float*)d_in[4];
    const float* w3    = (const float*)d_in[5];
    const float* b3    = (const float*)d_in[6];
    const float* alpha = (const float*)d_in[7];
    const float* beta  = (const float*)d_in[8];
    const float* wf    = (const float*)d_in[9];
    const float* bf    = (const float*)d_in[10];
    float* out = (float*)d_out;

    cudaFuncSetAttribute(mma_gemm<false,false,1,false>, cudaFuncAttributeMaxDynamicSharedMemorySize, GEMM_SMEM);
    cudaFuncSetAttribute(mma_gemm<true, true, 0,false>, cudaFuncAttributeMaxDynamicSharedMemorySize, GEMM_SMEM);
    cudaFuncSetAttribute(mma_gemm<false,false,0,false>, cudaFuncAttributeMaxDynamicSharedMemorySize, GEMM_SMEM);
    cudaFuncSetAttribute(mma_gemm<true, true, 1,false>, cudaFuncAttributeMaxDynamicSharedMemorySize, GEMM_SMEM);
    cudaFuncSetAttribute(mma_gemm<false,true, 0,true >, cudaFuncAttributeMaxDynamicSharedMemorySize, GEMM_SMEM);

    bf16 *xcolTh, *xcolTl, *w1h, *w1l, *w2h, *w2l, *w3h, *w3l, *wfh, *wfl;
    bf16 *Ah, *Al, *Bmh, *Bml, *Dh, *Dl, *xh, *xl, *Mh, *Ml, *Sh, *Sl;
    bf16 *spath, *spatl, *chanh, *chanl;
    float *Mb, *Sb;
    cudaGetSymbolAddress((void**)&xcolTh, g_xcolT_h);
    cudaGetSymbolAddress((void**)&xcolTl, g_xcolT_l);
    cudaGetSymbolAddress((void**)&w1h, g_w1h);  cudaGetSymbolAddress((void**)&w1l, g_w1l);
    cudaGetSymbolAddress((void**)&w2h, g_w2h);  cudaGetSymbolAddress((void**)&w2l, g_w2l);
    cudaGetSymbolAddress((void**)&w3h, g_w3h);  cudaGetSymbolAddress((void**)&w3l, g_w3l);
    cudaGetSymbolAddress((void**)&wfh, g_wfh);  cudaGetSymbolAddress((void**)&wfl, g_wfl);
    cudaGetSymbolAddress((void**)&Ah,  g_Ah);   cudaGetSymbolAddress((void**)&Al,  g_Al);
    cudaGetSymbolAddress((void**)&Bmh, g_Bmh);  cudaGetSymbolAddress((void**)&Bml, g_Bml);
    cudaGetSymbolAddress((void**)&Dh,  g_Dh);   cudaGetSymbolAddress((void**)&Dl,  g_Dl);
    cudaGetSymbolAddress((void**)&xh,  g_xh);   cudaGetSymbolAddress((void**)&xl,  g_xl);
    cudaGetSymbolAddress((void**)&Mb,  g_M);
    cudaGetSymbolAddress((void**)&Mh,  g_Mh);   cudaGetSymbolAddress((void**)&Ml,  g_Ml);
    cudaGetSymbolAddress((void**)&Sb,  g_S);
    cudaGetSymbolAddress((void**)&Sh,  g_Sh);   cudaGetSymbolAddress((void**)&Sl,  g_Sl);
    cudaGetSymbolAddress((void**)&spath, g_spath); cudaGetSymbolAddress((void**)&spatl, g_spatl);
    cudaGetSymbolAddress((void**)&chanh, g_chanh); cudaGetSymbolAddress((void**)&chanl, g_chanl);

    const long sX  = (long)CC * NN;
    const long sM  = (long)NN * NN;
    const long sS  = (long)CC * CC;
    const long sCol = (long)NN * K9;

    // 1) im2col + split, input/weight splits
    im2col_split<<<(unsigned)((long)BB * NN * K9 / 256), 256>>>(x, xcolTh, xcolTl);
    split_kernel<<<CC * K9 / 256, 256>>>(w1, w1h, w1l);
    split_kernel<<<CC * K9 / 256, 256>>>(w2, w2h, w2l);
    split_kernel<<<CC * K9 / 256, 256>>>(w3, w3h, w3l);
    split_kernel<<<CC * C3 / 256, 256>>>(wf, wfh, wfl);
    split_kernel<<<(unsigned)((long)BB * sX / 256), 256>>>(x, xh, xl);

    // 2) convs: C[c][n] = W[c][:] . xcolT[n][:] + b   (epi: bf16 split)
    {
        dim3 g(NN / 128, CC / 128, BB);
        mma_gemm<false,false,1,false><<<g, 256, GEMM_SMEM>>>(
            w1h, w1l, K9, 0, xcolTh, xcolTl, xcolTh, xcolTl, xcolTh, xcolTl, K9, sCol,
            nullptr, Ah, Al, NN, sX, b1, nullptr, K9);
        mma_gemm<false,false,1,false><<<g, 256, GEMM_SMEM>>>(
            w2h, w2l, K9, 0, xcolTh, xcolTl, xcolTh, xcolTl, xcolTh, xcolTl, K9, sCol,
            nullptr, Bmh, Bml, NN, sX, b2, nullptr, K9);
        mma_gemm<false,false,1,false><<<g, 256, GEMM_SMEM>>>(
            w3h, w3l, K9, 0, xcolTh, xcolTl, xcolTh, xcolTl, xcolTh, xcolTl, K9, sCol,
            nullptr, Dh, Dl, NN, sX, b3, nullptr, K9);
    }

    // 3) M[n][m] = sum_c A[c][n]*Bm[c][m]
    {
        dim3 g(NN / 128, NN / 128, BB);
        mma_gemm<true,true,0,false><<<g, 256, GEMM_SMEM>>>(
            Ah, Al, NN, sX, Bmh, Bml, Bmh, Bml, Bmh, Bml, NN, sX,
            Mb, nullptr, nullptr, NN, sM, nullptr, nullptr, CC);
    }

    // 4) softmax rows of M -> Mh/Ml
    softmax_split<NN><<<BB * NN, 256>>>(Mb, Mh, Ml);

    // 5) spat[c][n] = sum_m D[c][m]*Msm[n][m]   (epi: alpha -> bf16 split)
    {
        dim3 g(NN / 128, CC / 128, BB);
        mma_gemm<false,false,1,false><<<g, 256, GEMM_SMEM>>>(
            Dh, Dl, NN, sX, Mh, Ml, Mh, Ml, Mh, Ml, NN, sM,
            nullptr, spath, spatl, NN, sX, nullptr, alpha, NN);
    }

    // 6) S[c][d] = sum_n x[c][n]*x[d][n]
    {
        dim3 g(CC / 128, CC / 128, BB);
        mma_gemm<false,false,0,false><<<g, 256, GEMM_SMEM>>>(
            xh, xl, NN, sX, xh, xl, xh, xl, xh, xl, NN, sX,
            Sb, nullptr, nullptr, CC, sS, nullptr, nullptr, NN);
    }

    // 7) softmax rows of S -> Sh/Sl
    softmax_split<CC><<<BB * CC, 256>>>(Sb, Sh, Sl);

    // 8) chan[c][n] = sum_d Ssm[d][c]*x[d][n]  (epi: beta -> bf16 split)
    {
        dim3 g(NN / 128, CC / 128, BB);
        mma_gemm<true,true,1,false><<<g, 256, GEMM_SMEM>>>(
            Sh, Sl, CC, sS, xh, xl, xh, xl, xh, xl, NN, sX,
            nullptr, chanh, chanl, NN, sX, nullptr, beta, CC);
    }

    // 9) fuse: out[c][n] = bf[c] + sum over [x; a*spat; b*chan]
    {
        dim3 g(NN / 128, CC / 128, BB);
        mma_gemm<false,true,0,true><<<g, 256, GEMM_SMEM>>>(
            wfh, wfl, C3, 0, xh, xl, spath, spatl, chanh, chanl, NN, sX,
            out, nullptr, nullptr, NN, sX, bf, nullptr, C3);
    }
}

// round 7
// speedup vs baseline: 6.3194x; 1.8198x over previous
#include <cuda_runtime.h>
#include <cuda_bf16.h>
#include <cstdint>

#define BB 16
#define CC 512
#define HH 32
#define WW 32
#define NN 1024
#define C3 1536
#define NT 256          // winograd tiles per image (16x16)

typedef __nv_bfloat16 bf16;

// ---------------- scratch (device globals) -----------------------------------
// Winograd V: [z=b*16+t][ci][tile], bf16 split
__device__ bf16 g_Vh[(size_t)BB * 16 * CC * NT];
__device__ bf16 g_Vl[(size_t)BB * 16 * CC * NT];
// Winograd U per conv: [t][co][ci]
__device__ bf16 g_U1h[16 * CC * CC], g_U1l[16 * CC * CC];
__device__ bf16 g_U2h[16 * CC * CC], g_U2l[16 * CC * CC];
__device__ bf16 g_U3h[16 * CC * CC], g_U3l[16 * CC * CC];
// Winograd M (fp32), reused across the 3 convs: [z][co][tile]
__device__ float g_Mw[(size_t)BB * 16 * CC * NT];
__device__ bf16 g_wfh[CC * C3], g_wfl[CC * C3];
__device__ bf16 g_Ah[(size_t)BB * CC * NN], g_Al[(size_t)BB * CC * NN];
__device__ bf16 g_Bmh[(size_t)BB * CC * NN], g_Bml[(size_t)BB * CC * NN];
__device__ bf16 g_Dh[(size_t)BB * CC * NN], g_Dl[(size_t)BB * CC * NN];
__device__ bf16 g_xh[(size_t)BB * CC * NN], g_xl[(size_t)BB * CC * NN];
__device__ float g_M[(size_t)BB * NN * NN];
__device__ bf16 g_Mh[(size_t)BB * NN * NN], g_Ml[(size_t)BB * NN * NN];
__device__ float g_S[(size_t)BB * CC * CC];
__device__ bf16 g_Sh[(size_t)BB * CC * CC], g_Sl[(size_t)BB * CC * CC];
__device__ bf16 g_spath[(size_t)BB * CC * NN], g_spatl[(size_t)BB * CC * NN];
__device__ bf16 g_chanh[(size_t)BB * CC * NN], g_chanl[(size_t)BB * CC * NN];

// ---------------- helpers ------------------------------------------------------
__device__ __forceinline__ uint32_t smem_u32(const void* p) {
    uint32_t a;
    asm("{ .reg .u64 t; cvta.to.shared.u64 t, %1; cvt.u32.u64 %0, t; }"
        : "=r"(a) : "l"(p));
    return a;
}
__device__ __forceinline__ void ldsm_x4(uint32_t* r, uint32_t addr) {
    asm volatile("ldmatrix.sync.aligned.m8n8.x4.shared.b16 {%0,%1,%2,%3}, [%4];"
                 : "=r"(r[0]), "=r"(r[1]), "=r"(r[2]), "=r"(r[3]) : "r"(addr));
}
__device__ __forceinline__ void ldsm_x4_t(uint32_t* r, uint32_t addr) {
    asm volatile("ldmatrix.sync.aligned.m8n8.x4.trans.shared.b16 {%0,%1,%2,%3}, [%4];"
                 : "=r"(r[0]), "=r"(r[1]), "=r"(r[2]), "=r"(r[3]) : "r"(addr));
}
__device__ __forceinline__ void ldsm_x2(uint32_t* r, uint32_t addr) {
    asm volatile("ldmatrix.sync.aligned.m8n8.x2.shared.b16 {%0,%1}, [%2];"
                 : "=r"(r[0]), "=r"(r[1]) : "r"(addr));
}
__device__ __forceinline__ void ldsm_x2_t(uint32_t* r, uint32_t addr) {
    asm volatile("ldmatrix.sync.aligned.m8n8.x2.trans.shared.b16 {%0,%1}, [%2];"
                 : "=r"(r[0]), "=r"(r[1]) : "r"(addr));
}
__device__ __forceinline__ void mma16816(float* d, const uint32_t* a, const uint32_t* b) {
    asm volatile("mma.sync.aligned.m16n8k16.row.col.f32.bf16.bf16.f32 "
                 "{%0,%1,%2,%3}, {%4,%5,%6,%7}, {%8,%9}, {%0,%1,%2,%3};"
                 : "+f"(d[0]), "+f"(d[1]), "+f"(d[2]), "+f"(d[3])
                 : "r"(a[0]), "r"(a[1]), "r"(a[2]), "r"(a[3]), "r"(b[0]), "r"(b[1]));
}
__device__ __forceinline__ void split_store(bf16* H, bf16* L, long off, float v) {
    bf16 hi = __float2bfloat16(v);
    H[off] = hi;
    L[off] = __float2bfloat16(v - __bfloat162float(hi));
}

// ---------------- GEMM (unchanged core from R5/R6) ------------------------------
#define TILEB 8192
#define STAGES 4
#define GEMM_SMEM (STAGES * 4 * TILEB)   // 128 KB

template<bool TR>
__device__ __forceinline__ void load_tile(uint32_t tb, const bf16* __restrict__ S,
                                          long rowbase, long ld, long k0, int tid) {
    if (!TR) {
        #pragma unroll
        for (int p = 0; p < 2; p++) {
            int row = (tid >> 2) + p * 64;
            int ch  = tid & 3;
            const void* g = (const void*)(S + (rowbase + row) * ld + k0 + ch * 8);
            uint32_t dst = tb + (uint32_t)(row * 64 + ((ch ^ ((row >> 1) & 3)) << 4));
            asm volatile("cp.async.cg.shared.global [%0], [%1], 16;"
                         :: "r"(dst), "l"(g) : "memory");
        }
    } else {
        #pragma unroll
        for (int p = 0; p < 2; p++) {
            int row = (tid >> 4) + p * 16;
            int ch  = tid & 15;
            const void* g = (const void*)(S + (k0 + row) * ld + rowbase + ch * 8);
            uint32_t dst = tb + (uint32_t)(row * 256 + ((ch ^ (row & 7)) << 4));
            asm volatile("cp.async.cg.shared.global [%0], [%1], 16;"
                         :: "r"(dst), "l"(g) : "memory");
        }
    }
}

// EPI: 0 = fp32 (+bias), 1 = bf16 hi/lo split (*scale, +bias)
template<bool ATR, bool BTR, int EPI, bool SEG>
__global__ __launch_bounds__(256, 1)
void mma_gemm(const bf16* __restrict__ Ah_, const bf16* __restrict__ Al_,
              long lda, long bsA, unsigned zmA,
              const bf16* __restrict__ B0h, const bf16* __restrict__ B0l,
              const bf16* __restrict__ B1h, const bf16* __restrict__ B1l,
              const bf16* __restrict__ B2h, const bf16* __restrict__ B2l,
              long ldb, long bsB,
              float* __restrict__ Cf, bf16* __restrict__ Ch, bf16* __restrict__ Cl,
              long ldc, long bsC,
              const float* __restrict__ bias, const float* __restrict__ scale, int K)
{
    extern __shared__ char smem[];
    const uint32_t sb = smem_u32(smem);
    const int tid = threadIdx.x;
    const int wid = tid >> 5, lane = tid & 31;
    const int warp_m = wid & 1, warp_n = wid >> 1;
    const long m0 = (long)blockIdx.y * 128, n0 = (long)blockIdx.x * 128;
    const long zA = (long)(blockIdx.z & zmA) * bsA, zB = (long)blockIdx.z * bsB;
    Ah_ += zA;  Al_ += zA;
    B0h += zB;  B0l += zB;  B1h += zB;  B1l += zB;  B2h += zB;  B2l += zB;

    float d[4][4][4];
    #pragma unroll
    for (int i = 0; i < 4; i++)
        #pragma unroll
        for (int j = 0; j < 4; j++)
            #pragma unroll
            for (int q = 0; q < 4; q++) d[i][j][q] = 0.f;

    const int NC = K >> 5;

    auto loadstage = [&](int i) {
        const int s = i & (STAGES - 1);
        const long k0 = (long)i * 32;
        const bf16 *Bh = B0h, *Bl = B0l;
        long kb = k0;
        if (SEG) {
            int seg = (int)(k0 >> 9);
            kb = k0 & 511;
            Bh = (seg == 0) ? B0h : (seg == 1) ? B1h : B2h;
            Bl = (seg == 0) ? B0l : (seg == 1) ? B1l : B2l;
        }
        uint32_t tb = sb + (uint32_t)s * 4 * TILEB;
        load_tile<ATR>(tb,             Ah_, m0, lda, k0, tid);
        load_tile<ATR>(tb + TILEB,     Al_, m0, lda, k0, tid);
        load_tile<BTR>(tb + 2 * TILEB, Bh,  n0, ldb, kb, tid);
        load_tile<BTR>(tb + 3 * TILEB, Bl,  n0, ldb, kb, tid);
        asm volatile("cp.async.commit_group;" ::: "memory");
    };

    for (int i = 0; i < STAGES - 1; i++) {
        if (i < NC) loadstage(i);
        else        asm volatile("cp.async.commit_group;" ::: "memory");
    }

    for (int i = 0; i < NC; i++) {
        asm volatile("cp.async.wait_group %0;" :: "n"(STAGES - 2) : "memory");
        __syncthreads();
        if (i + STAGES - 1 < NC) loadstage(i + STAGES - 1);
        else                     asm volatile("cp.async.commit_group;" ::: "memory");

        const int s = i & (STAGES - 1);
        const uint32_t bAh = sb + (uint32_t)(s * 4 + 0) * TILEB;
        const uint32_t bAl = sb + (uint32_t)(s * 4 + 1) * TILEB;
        const uint32_t bBh = sb + (uint32_t)(s * 4 + 2) * TILEB;
        const uint32_t bBl = sb + (uint32_t)(s * 4 + 3) * TILEB;

        #pragma unroll
        for (int ks = 0; ks < 2; ks++) {
            uint32_t ah[4][4], al[4][4];
            #pragma unroll
            for (int tm = 0; tm < 4; tm++) {
                if (!ATR) {
                    int row = warp_m * 64 + tm * 16 + (lane & 15);
                    int ch  = ks * 2 + (lane >> 4);
                    uint32_t off = (uint32_t)(row * 64 + ((ch ^ ((row >> 1) & 3)) << 4));
                    ldsm_x4(ah[tm], bAh + off);
                    ldsm_x4(al[tm], bAl + off);
                } else {
                    int krow = ks * 16 + (lane & 7) + ((lane >> 4) << 3);
                    int mch  = ((warp_m * 64 + tm * 16) >> 3) + ((lane >> 3) & 1);
                    uint32_t off = (uint32_t)(krow * 256 + ((mch ^ (krow & 7)) << 4));
                    ldsm_x4_t(ah[tm], bAh + off);
                    ldsm_x4_t(al[tm], bAl + off);
                }
            }
            uint32_t bh[4][2], bl[4][2];
            #pragma unroll
            for (int tn = 0; tn < 4; tn++) {
                if (!BTR) {
                    int row = warp_n * 32 + tn * 8 + (lane & 7);
                    int ch  = ks * 2 + ((lane >> 3) & 1);
                    uint32_t off = (uint32_t)(row * 64 + ((ch ^ ((row >> 1) & 3)) << 4));
                    ldsm_x2(bh[tn], bBh + off);
                    ldsm_x2(bl[tn], bBl + off);
                } else {
                    int krow = ks * 16 + (lane & 7) + ((lane >> 3) & 1) * 8;
                    int nch  = (warp_n * 32 + tn * 8) >> 3;
                    uint32_t off = (uint32_t)(krow * 256 + ((nch ^ (krow & 7)) << 4));
                    ldsm_x2_t(bh[tn], bBh + off);
                    ldsm_x2_t(bl[tn], bBl + off);
                }
            }
            #pragma unroll
            for (int q = 0; q < 3; q++)
                #pragma unroll
                for (int tm = 0; tm < 4; tm++)
                    #pragma unroll
                    for (int tn = 0; tn < 4; tn++) {
                        const uint32_t* aa = (q == 2) ? al[tm] : ah[tm];
                        const uint32_t* bb = (q == 1) ? bl[tn] : bh[tn];
                        mma16816(d[tm][tn], aa, bb);
                    }
        }
        __syncthreads();
    }

    if (EPI == 0) {
        float* Cb = Cf + (long)blockIdx.z * bsC;
        #pragma unroll
        for (int tm = 0; tm < 4; tm++) {
            const long m = m0 + warp_m * 64 + tm * 16 + (lane >> 2);
            const float bs0 = bias ? bias[m]     : 0.f;
            const float bs1 = bias ? bias[m + 8] : 0.f;
            #pragma unroll
            for (int tn = 0; tn < 4; tn++) {
                const long n = n0 + warp_n * 32 + tn * 8 + (lane & 3) * 2;
                *(float2*)&Cb[m * ldc + n] =
                    make_float2(d[tm][tn][0] + bs0, d[tm][tn][1] + bs0);
                *(float2*)&Cb[(m + 8) * ldc + n] =
                    make_float2(d[tm][tn][2] + bs1, d[tm][tn][3] + bs1);
            }
        }
    } else {
        bf16* Hb = Ch + (long)blockIdx.z * bsC;
        bf16* Lb = Cl + (long)blockIdx.z * bsC;
        const float sc = scale ? *scale : 1.0f;
        #pragma unroll
        for (int tm = 0; tm < 4; tm++) {
            const long m = m0 + warp_m * 64 + tm * 16 + (lane >> 2);
            const float bs0 = bias ? bias[m]     : 0.f;
            const float bs1 = bias ? bias[m + 8] : 0.f;
            #pragma unroll
            for (int tn = 0; tn < 4; tn++) {
                const long n = n0 + warp_n * 32 + tn * 8 + (lane & 3) * 2;
                float v0 = d[tm][tn][0] * sc + bs0;
                float v1 = d[tm][tn][1] * sc + bs0;
                float v2 = d[tm][tn][2] * sc + bs1;
                float v3 = d[tm][tn][3] * sc + bs1;
                __nv_bfloat162 hv0, lv0, hv1, lv1;
                hv0.x = __float2bfloat16(v0);
                hv0.y = __float2bfloat16(v1);
                lv0.x = __float2bfloat16(v0 - __bfloat162float(hv0.x));
                lv0.y = __float2bfloat16(v1 - __bfloat162float(hv0.y));
                hv1.x = __float2bfloat16(v2);
                hv1.y = __float2bfloat16(v3);
                lv1.x = __float2bfloat16(v2 - __bfloat162float(hv1.x));
                lv1.y = __float2bfloat16(v3 - __bfloat162float(hv1.y));
                *(__nv_bfloat162*)&Hb[m * ldc + n]       = hv0;
                *(__nv_bfloat162*)&Lb[m * ldc + n]       = lv0;
                *(__nv_bfloat162*)&Hb[(m + 8) * ldc + n] = hv1;
                *(__nv_bfloat162*)&Lb[(m + 8) * ldc + n] = lv1;
            }
        }
    }
}

// ---------------- Winograd F(2x2,3x3) transforms -------------------------------
// Input: V = B^T d B per (b, ci, tile); V layout [z=b*16+t][ci][tile]
__global__ __launch_bounds__(256)
void wino_input(const float* __restrict__ x, bf16* __restrict__ Vh, bf16* __restrict__ Vl) {
    long gid = (long)blockIdx.x * 256 + threadIdx.x;
    int tile = (int)(gid & (NT - 1));
    long r = gid >> 8;
    int ci = (int)(r & (CC - 1));
    int b  = (int)(r >> 9);
    int ty = tile >> 4, tx = tile & 15;
    const float* xb = x + ((long)b * CC + ci) * NN;
    const int h0 = 2 * ty - 1, w0 = 2 * tx - 1;

    float dd[4][4];
    #pragma unroll
    for (int i = 0; i < 4; i++) {
        int ih = h0 + i;
        #pragma unroll
        for (int j = 0; j < 4; j++) {
            int iw = w0 + j;
            dd[i][j] = ((unsigned)ih < HH && (unsigned)iw < WW) ? xb[ih * WW + iw] : 0.f;
        }
    }
    float t[4][4];
    #pragma unroll
    for (int j = 0; j < 4; j++) {
        t[0][j] = dd[0][j] - dd[2][j];
        t[1][j] = dd[1][j] + dd[2][j];
        t[2][j] = dd[2][j] - dd[1][j];
        t[3][j] = dd[1][j] - dd[3][j];
    }
    float V[4][4];
    #pragma unroll
    for (int i = 0; i < 4; i++) {
        V[i][0] = t[i][0] - t[i][2];
        V[i][1] = t[i][1] + t[i][2];
        V[i][2] = t[i][2] - t[i][1];
        V[i][3] = t[i][1] - t[i][3];
    }
    #pragma unroll
    for (int c = 0; c < 16; c++) {
        long off = (((long)(b * 16 + c) * CC) + ci) * NT + tile;
        split_store(Vh, Vl, off, V[c >> 2][c & 3]);
    }
}

// Weight: U = G g G^T per (co, ci); U layout [t][co][ci]
__global__ __launch_bounds__(256)
void wino_weight(const float* __restrict__ w, bf16* __restrict__ Uh, bf16* __restrict__ Ul) {
    int gid = blockIdx.x * 256 + threadIdx.x;   // co*512 + ci
    int ci = gid & (CC - 1), co = gid >> 9;
    const float* g = w + (long)gid * 9;
    float rr[4][3];
    #pragma unroll
    for (int j = 0; j < 3; j++) {
        float g0 = g[0 * 3 + j], g1 = g[1 * 3 + j], g2 = g[2 * 3 + j];
        rr[0][j] = g0;
        rr[1][j] = 0.5f * (g0 + g1 + g2);
        rr[2][j] = 0.5f * (g0 - g1 + g2);
        rr[3][j] = g2;
    }
    #pragma unroll
    for (int i = 0; i < 4; i++) {
        float U0 = rr[i][0];
        float U1 = 0.5f * (rr[i][0] + rr[i][1] + rr[i][2]);
        float U2 = 0.5f * (rr[i][0] - rr[i][1] + rr[i][2]);
        float U3 = rr[i][2];
        float Uv[4] = {U0, U1, U2, U3};
        #pragma unroll
        for (int j = 0; j < 4; j++) {
            long off = ((long)(i * 4 + j) * CC + co) * CC + ci;
            split_store(Uh, Ul, off, Uv[j]);
        }
    }
}

// Output: Y = A^T M A + bias per (b, co, tile) -> conv out [b][co][n] split bf16
__global__ __launch_bounds__(256)
void wino_output(const float* __restrict__ M, const float* __restrict__ bias,
                 bf16* __restrict__ oh, bf16* __restrict__ ol) {
    long gid = (long)blockIdx.x * 256 + threadIdx.x;
    int tile = (int)(gid & (NT - 1));
    long r = gid >> 8;
    int co = (int)(r & (CC - 1));
    int b  = (int)(r >> 9);

    float m[4][4];
    #pragma unroll
    for (int c = 0; c < 16; c++)
        m[c >> 2][c & 3] = M[(((long)(b * 16 + c) * CC) + co) * NT + tile];

    float s[2][4];
    #pragma unroll
    for (int j = 0; j < 4; j++) {
        s[0][j] = m[0][j] + m[1][j] + m[2][j];
        s[1][j] = m[1][j] - m[2][j] - m[3][j];
    }
    const float bs = bias[co];
    float Y[2][2];
    #pragma unroll
    for (int i = 0; i < 2; i++) {
        Y[i][0] = s[i][0] + s[i][1] + s[i][2] + bs;
        Y[i][1] = s[i][1] - s[i][2] - s[i][3] + bs;
    }
    int ty = tile >> 4, tx = tile & 15;
    long base = ((long)b * CC + co) * NN + (2 * ty) * WW + 2 * tx;
    split_store(oh, ol, base,          Y[0][0]);
    split_store(oh, ol, base + 1,      Y[0][1]);
    split_store(oh, ol, base + WW,     Y[1][0]);
    split_store(oh, ol, base + WW + 1, Y[1][1]);
}

// ---------------- plain split ---------------------------------------------------
__global__ void split_kernel(const float* __restrict__ in,
                             bf16* __restrict__ oh, bf16* __restrict__ ol) {
    long g = (long)blockIdx.x * 256 + threadIdx.x;
    split_store(oh, ol, g, in[g]);
}

// ---------------- softmax -------------------------------------------------------
__device__ __forceinline__ float warpMax(float v) {
    #pragma unroll
    for (int o = 16; o > 0; o >>= 1) v = fmaxf(v, __shfl_xor_sync(0xffffffffu, v, o));
    return v;
}
__device__ __forceinline__ float warpSum(float v) {
    #pragma unroll
    for (int o = 16; o > 0; o >>= 1) v += __shfl_xor_sync(0xffffffffu, v, o);
    return v;
}

template<int LEN>
__global__ __launch_bounds__(256)
void softmax_split(const float* __restrict__ buf,
                   bf16* __restrict__ oh, bf16* __restrict__ ol) {
    constexpr int V = LEN / 256;
    const long base = (long)blockIdx.x * LEN;
    const float* row = buf + base;
    const int tid = threadIdx.x, lane = tid & 31, wid = tid >> 5;
    __shared__ float sred[8];
    float v[V];
    float mx = -3.0e38f;
    #pragma unroll
    for (int j = 0; j < V; j++) { v[j] = row[tid + j * 256]; mx = fmaxf(mx, v[j]); }
    mx = warpMax(mx);
    if (lane == 0) sred[wid] = mx;
    __syncthreads();
    if (tid == 0) {
        float m = sred[0];
        #pragma unroll
        for (int i = 1; i < 8; i++) m = fmaxf(m, sred[i]);
        sred[0] = m;
    }
    __syncthreads();
    mx = sred[0];
    __syncthreads();
    float s = 0.f;
    #pragma unroll
    for (int j = 0; j < V; j++) { v[j] = __expf(v[j] - mx); s += v[j]; }
    s = warpSum(s);
    if (lane == 0) sred[wid] = s;
    __syncthreads();
    if (tid == 0) {
        float m = 0.f;
        #pragma unroll
        for (int i = 0; i < 8; i++) m += sred[i];
        sred[0] = m;
    }
    __syncthreads();
    const float inv = 1.0f / sred[0];
    #pragma unroll
    for (int j = 0; j < V; j++)
        split_store(oh, ol, base + tid + j * 256, v[j] * inv);
}

// ---------------- launch --------------------------------------------------------
extern "C" void kernel_launch(void* const* d_in, const int* in_sizes, int n_in,
                              void* d_out, int out_size) {
    const float* x     = (const float*)d_in[0];
    const float* w1    = (const float*)d_in[1];
    const float* b1    = (const float*)d_in[2];
    const float* w2    = (const float*)d_in[3];
    const float* b2    = (const float*)d_in[4];
    const float* w3    = (const float*)d_in[5];
    const float* b3    = (const float*)d_in[6];
    const float* alpha = (const float*)d_in[7];
    const float* beta  = (const float*)d_in[8];
    const float* wf    = (const float*)d_in[9];
    const float* bf    = (const float*)d_in[10];
    float* out = (float*)d_out;

    cudaFuncSetAttribute(mma_gemm<false,true, 0,false>, cudaFuncAttributeMaxDynamicSharedMemorySize, GEMM_SMEM);
    cudaFuncSetAttribute(mma_gemm<true, true, 0,false>, cudaFuncAttributeMaxDynamicSharedMemorySize, GEMM_SMEM);
    cudaFuncSetAttribute(mma_gemm<false,false,0,false>, cudaFuncAttributeMaxDynamicSharedMemorySize, GEMM_SMEM);
    cudaFuncSetAttribute(mma_gemm<false,false,1,false>, cudaFuncAttributeMaxDynamicSharedMemorySize, GEMM_SMEM);
    cudaFuncSetAttribute(mma_gemm<true, true, 1,false>, cudaFuncAttributeMaxDynamicSharedMemorySize, GEMM_SMEM);
    cudaFuncSetAttribute(mma_gemm<false,true, 0,true >, cudaFuncAttributeMaxDynamicSharedMemorySize, GEMM_SMEM);

    bf16 *Vh, *Vl, *U1h, *U1l, *U2h, *U2l, *U3h, *U3l, *wfh, *wfl;
    bf16 *Ah, *Al, *Bmh, *Bml, *Dh, *Dl, *xh, *xl, *Mh, *Ml, *Sh, *Sl;
    bf16 *spath, *spatl, *chanh, *chanl;
    float *Mw, *Mb, *Sb;
    cudaGetSymbolAddress((void**)&Vh, g_Vh);    cudaGetSymbolAddress((void**)&Vl, g_Vl);
    cudaGetSymbolAddress((void**)&U1h, g_U1h);  cudaGetSymbolAddress((void**)&U1l, g_U1l);
    cudaGetSymbolAddress((void**)&U2h, g_U2h);  cudaGetSymbolAddress((void**)&U2l, g_U2l);
    cudaGetSymbolAddress((void**)&U3h, g_U3h);  cudaGetSymbolAddress((void**)&U3l, g_U3l);
    cudaGetSymbolAddress((void**)&Mw, g_Mw);
    cudaGetSymbolAddress((void**)&wfh, g_wfh);  cudaGetSymbolAddress((void**)&wfl, g_wfl);
    cudaGetSymbolAddress((void**)&Ah,  g_Ah);   cudaGetSymbolAddress((void**)&Al,  g_Al);
    cudaGetSymbolAddress((void**)&Bmh, g_Bmh);  cudaGetSymbolAddress((void**)&Bml, g_Bml);
    cudaGetSymbolAddress((void**)&Dh,  g_Dh);   cudaGetSymbolAddress((void**)&Dl,  g_Dl);
    cudaGetSymbolAddress((void**)&xh,  g_xh);   cudaGetSymbolAddress((void**)&xl,  g_xl);
    cudaGetSymbolAddress((void**)&Mb,  g_M);
    cudaGetSymbolAddress((void**)&Mh,  g_Mh);   cudaGetSymbolAddress((void**)&Ml,  g_Ml);
    cudaGetSymbolAddress((void**)&Sb,  g_S);
    cudaGetSymbolAddress((void**)&Sh,  g_Sh);   cudaGetSymbolAddress((void**)&Sl,  g_Sl);
    cudaGetSymbolAddress((void**)&spath, g_spath); cudaGetSymbolAddress((void**)&spatl, g_spatl);
    cudaGetSymbolAddress((void**)&chanh, g_chanh); cudaGetSymbolAddress((void**)&chanl, g_chanl);

    const long sX  = (long)CC * NN;
    const long sM  = (long)NN * NN;
    const long sS  = (long)CC * CC;
    const long sVz = (long)CC * NT;    // per-z stride of V / Mw
    const long sUt = (long)CC * CC;    // per-tap stride of U
    const unsigned ZALL = 0xFFFFFFFFu;

    // 1) transforms + splits
    wino_input<<<(unsigned)((long)BB * CC * NT / 256), 256>>>(x, Vh, Vl);
    wino_weight<<<CC * CC / 256, 256>>>(w1, U1h, U1l);
    wino_weight<<<CC * CC / 256, 256>>>(w2, U2h, U2l);
    wino_weight<<<CC * CC / 256, 256>>>(w3, U3h, U3l);
    split_kernel<<<CC * C3 / 256, 256>>>(wf, wfh, wfl);
    split_kernel<<<(unsigned)((long)BB * sX / 256), 256>>>(x, xh, xl);

    // 2) three convs via Winograd: per z=(b,t): Mw[co][tile] = U_t[co][:] . V_z[:][tile]
    {
        dim3 g(NT / 128, CC / 128, BB * 16);
        const unsigned totw = (unsigned)((long)BB * CC * NT / 256);
        mma_gemm<false,true,0,false><<<g, 256, GEMM_SMEM>>>(
            U1h, U1l, CC, sUt, 15u, Vh, Vl, Vh, Vl, Vh, Vl, NT, sVz,
            Mw, nullptr, nullptr, NT, sVz, nullptr, nullptr, CC);
        wino_output<<<totw, 256>>>(Mw, b1, Ah, Al);
        mma_gemm<false,true,0,false><<<g, 256, GEMM_SMEM>>>(
            U2h, U2l, CC, sUt, 15u, Vh, Vl, Vh, Vl, Vh, Vl, NT, sVz,
            Mw, nullptr, nullptr, NT, sVz, nullptr, nullptr, CC);
        wino_output<<<totw, 256>>>(Mw, b2, Bmh, Bml);
        mma_gemm<false,true,0,false><<<g, 256, GEMM_SMEM>>>(
            U3h, U3l, CC, sUt, 15u, Vh, Vl, Vh, Vl, Vh, Vl, NT, sVz,
            Mw, nullptr, nullptr, NT, sVz, nullptr, nullptr, CC);
        wino_output<<<totw, 256>>>(Mw, b3, Dh, Dl);
    }

    // 3) M[n][m] = sum_c A[c][n]*Bm[c][m]
    {
        dim3 g(NN / 128, NN / 128, BB);
        mma_gemm<true,true,0,false><<<g, 256, GEMM_SMEM>>>(
            Ah, Al, NN, sX, ZALL, Bmh, Bml, Bmh, Bml, Bmh, Bml, NN, sX,
            Mb, nullptr, nullptr, NN, sM, nullptr, nullptr, CC);
    }

    // 4) softmax rows of M -> Mh/Ml
    softmax_split<NN><<<BB * NN, 256>>>(Mb, Mh, Ml);

    // 5) spat[c][n] = sum_m D[c][m]*Msm[n][m]   (epi: alpha -> bf16 split)
    {
        dim3 g(NN / 128, CC / 128, BB);
        mma_gemm<false,false,1,false><<<g, 256, GEMM_SMEM>>>(
            Dh, Dl, NN, sX, ZALL, Mh, Ml, Mh, Ml, Mh, Ml, NN, sM,
            nullptr, spath, spatl, NN, sX, nullptr, alpha, NN);
    }

    // 6) S[c][d] = sum_n x[c][n]*x[d][n]
    {
        dim3 g(CC / 128, CC / 128, BB);
        mma_gemm<false,false,0,false><<<g, 256, GEMM_SMEM>>>(
            xh, xl, NN, sX, ZALL, xh, xl, xh, xl, xh, xl, NN, sX,
            Sb, nullptr, nullptr, CC, sS, nullptr, nullptr, NN);
    }

    // 7) softmax rows of S -> Sh/Sl
    softmax_split<CC><<<BB * CC, 256>>>(Sb, Sh, Sl);

    // 8) chan[c][n] = sum_d Ssm[d][c]*x[d][n]  (epi: beta -> bf16 split)
    {
        dim3 g(NN / 128, CC / 128, BB);
        mma_gemm<true,true,1,false><<<g, 256, GEMM_SMEM>>>(
            Sh, Sl, CC, sS, ZALL, xh, xl, xh, xl, xh, xl, NN, sX,
            nullptr, chanh, chanl, NN, sX, nullptr, beta, CC);
    }

    // 9) fuse: out[c][n] = bf[c] + sum over [x; a*spat; b*chan]
    {
        dim3 g(NN / 128, CC / 128, BB);
        mma_gemm<false,true,0,true><<<g, 256, GEMM_SMEM>>>(
            wfh, wfl, C3, 0, ZALL, xh, xl, spath, spatl, chanh, chanl, NN, sX,
            out, nullptr, nullptr, NN, sX, bf, nullptr, C3);
    }
}

// round 8
// speedup vs baseline: 7.8775x; 1.2466x over previous
#include <cuda_runtime.h>
#include <cuda_bf16.h>
#include <cstdint>

#define BB 16
#define CC 512
#define HH 32
#define WW 32
#define NN 1024
#define C3 1536
#define NT4 64           // F(4x4,3x3) tiles per image (8x8)
#define TCOLS 1024       // BB * NT4 tile-columns
#define TAPS 36

typedef __nv_bfloat16 bf16;

// ---------------- scratch (device globals) -----------------------------------
// Winograd V: [tap][ci][tcol = b*64+tile], bf16 split
__device__ bf16 g_Vh[(size_t)TAPS * CC * TCOLS];
__device__ bf16 g_Vl[(size_t)TAPS * CC * TCOLS];
// Winograd U per conv: [tap][co][ci]
__device__ bf16 g_U1h[TAPS * CC * CC], g_U1l[TAPS * CC * CC];
__device__ bf16 g_U2h[TAPS * CC * CC], g_U2l[TAPS * CC * CC];
__device__ bf16 g_U3h[TAPS * CC * CC], g_U3l[TAPS * CC * CC];
// Winograd M (fp32), reused across the 3 convs: [tap][co][tcol]
__device__ float g_Mw[(size_t)TAPS * CC * TCOLS];
__device__ bf16 g_wfh[CC * C3], g_wfl[CC * C3];
__device__ bf16 g_Ah[(size_t)BB * CC * NN], g_Al[(size_t)BB * CC * NN];
__device__ bf16 g_Bmh[(size_t)BB * CC * NN], g_Bml[(size_t)BB * CC * NN];
__device__ bf16 g_Dh[(size_t)BB * CC * NN], g_Dl[(size_t)BB * CC * NN];
__device__ bf16 g_xh[(size_t)BB * CC * NN], g_xl[(size_t)BB * CC * NN];
__device__ float g_M[(size_t)BB * NN * NN];
__device__ bf16 g_Mh[(size_t)BB * NN * NN], g_Ml[(size_t)BB * NN * NN];
__device__ float g_S[(size_t)BB * CC * CC];
__device__ bf16 g_Sh[(size_t)BB * CC * CC], g_Sl[(size_t)BB * CC * CC];
__device__ bf16 g_spath[(size_t)BB * CC * NN], g_spatl[(size_t)BB * CC * NN];
__device__ bf16 g_chanh[(size_t)BB * CC * NN], g_chanl[(size_t)BB * CC * NN];

// ---------------- helpers ------------------------------------------------------
__device__ __forceinline__ uint32_t smem_u32(const void* p) {
    uint32_t a;
    asm("{ .reg .u64 t; cvta.to.shared.u64 t, %1; cvt.u32.u64 %0, t; }"
        : "=r"(a) : "l"(p));
    return a;
}
__device__ __forceinline__ void ldsm_x4(uint32_t* r, uint32_t addr) {
    asm volatile("ldmatrix.sync.aligned.m8n8.x4.shared.b16 {%0,%1,%2,%3}, [%4];"
                 : "=r"(r[0]), "=r"(r[1]), "=r"(r[2]), "=r"(r[3]) : "r"(addr));
}
__device__ __forceinline__ void ldsm_x4_t(uint32_t* r, uint32_t addr) {
    asm volatile("ldmatrix.sync.aligned.m8n8.x4.trans.shared.b16 {%0,%1,%2,%3}, [%4];"
                 : "=r"(r[0]), "=r"(r[1]), "=r"(r[2]), "=r"(r[3]) : "r"(addr));
}
__device__ __forceinline__ void ldsm_x2(uint32_t* r, uint32_t addr) {
    asm volatile("ldmatrix.sync.aligned.m8n8.x2.shared.b16 {%0,%1}, [%2];"
                 : "=r"(r[0]), "=r"(r[1]) : "r"(addr));
}
__device__ __forceinline__ void ldsm_x2_t(uint32_t* r, uint32_t addr) {
    asm volatile("ldmatrix.sync.aligned.m8n8.x2.trans.shared.b16 {%0,%1}, [%2];"
                 : "=r"(r[0]), "=r"(r[1]) : "r"(addr));
}
__device__ __forceinline__ void mma16816(float* d, const uint32_t* a, const uint32_t* b) {
    asm volatile("mma.sync.aligned.m16n8k16.row.col.f32.bf16.bf16.f32 "
                 "{%0,%1,%2,%3}, {%4,%5,%6,%7}, {%8,%9}, {%0,%1,%2,%3};"
                 : "+f"(d[0]), "+f"(d[1]), "+f"(d[2]), "+f"(d[3])
                 : "r"(a[0]), "r"(a[1]), "r"(a[2]), "r"(a[3]), "r"(b[0]), "r"(b[1]));
}
__device__ __forceinline__ void split_store(bf16* H, bf16* L, long off, float v) {
    bf16 hi = __float2bfloat16(v);
    H[off] = hi;
    L[off] = __float2bfloat16(v - __bfloat162float(hi));
}

// ---------------- GEMM (unchanged core) -----------------------------------------
#define TILEB 8192
#define STAGES 4
#define GEMM_SMEM (STAGES * 4 * TILEB)   // 128 KB

template<bool TR>
__device__ __forceinline__ void load_tile(uint32_t tb, const bf16* __restrict__ S,
                                          long rowbase, long ld, long k0, int tid) {
    if (!TR) {
        #pragma unroll
        for (int p = 0; p < 2; p++) {
            int row = (tid >> 2) + p * 64;
            int ch  = tid & 3;
            const void* g = (const void*)(S + (rowbase + row) * ld + k0 + ch * 8);
            uint32_t dst = tb + (uint32_t)(row * 64 + ((ch ^ ((row >> 1) & 3)) << 4));
            asm volatile("cp.async.cg.shared.global [%0], [%1], 16;"
                         :: "r"(dst), "l"(g) : "memory");
        }
    } else {
        #pragma unroll
        for (int p = 0; p < 2; p++) {
            int row = (tid >> 4) + p * 16;
            int ch  = tid & 15;
            const void* g = (const void*)(S + (k0 + row) * ld + rowbase + ch * 8);
            uint32_t dst = tb + (uint32_t)(row * 256 + ((ch ^ (row & 7)) << 4));
            asm volatile("cp.async.cg.shared.global [%0], [%1], 16;"
                         :: "r"(dst), "l"(g) : "memory");
        }
    }
}

// EPI: 0 = fp32 (+bias), 1 = bf16 hi/lo split (*scale, +bias)
template<bool ATR, bool BTR, int EPI, bool SEG>
__global__ __launch_bounds__(256, 1)
void mma_gemm(const bf16* __restrict__ Ah_, const bf16* __restrict__ Al_,
              long lda, long bsA, unsigned zmA,
              const bf16* __restrict__ B0h, const bf16* __restrict__ B0l,
              const bf16* __restrict__ B1h, const bf16* __restrict__ B1l,
              const bf16* __restrict__ B2h, const bf16* __restrict__ B2l,
              long ldb, long bsB,
              float* __restrict__ Cf, bf16* __restrict__ Ch, bf16* __restrict__ Cl,
              long ldc, long bsC,
              const float* __restrict__ bias, const float* __restrict__ scale, int K)
{
    extern __shared__ char smem[];
    const uint32_t sb = smem_u32(smem);
    const int tid = threadIdx.x;
    const int wid = tid >> 5, lane = tid & 31;
    const int warp_m = wid & 1, warp_n = wid >> 1;
    const long m0 = (long)blockIdx.y * 128, n0 = (long)blockIdx.x * 128;
    const long zA = (long)(blockIdx.z & zmA) * bsA, zB = (long)blockIdx.z * bsB;
    Ah_ += zA;  Al_ += zA;
    B0h += zB;  B0l += zB;  B1h += zB;  B1l += zB;  B2h += zB;  B2l += zB;

    float d[4][4][4];
    #pragma unroll
    for (int i = 0; i < 4; i++)
        #pragma unroll
        for (int j = 0; j < 4; j++)
            #pragma unroll
            for (int q = 0; q < 4; q++) d[i][j][q] = 0.f;

    const int NC = K >> 5;

    auto loadstage = [&](int i) {
        const int s = i & (STAGES - 1);
        const long k0 = (long)i * 32;
        const bf16 *Bh = B0h, *Bl = B0l;
        long kb = k0;
        if (SEG) {
            int seg = (int)(k0 >> 9);
            kb = k0 & 511;
            Bh = (seg == 0) ? B0h : (seg == 1) ? B1h : B2h;
            Bl = (seg == 0) ? B0l : (seg == 1) ? B1l : B2l;
        }
        uint32_t tb = sb + (uint32_t)s * 4 * TILEB;
        load_tile<ATR>(tb,             Ah_, m0, lda, k0, tid);
        load_tile<ATR>(tb + TILEB,     Al_, m0, lda, k0, tid);
        load_tile<BTR>(tb + 2 * TILEB, Bh,  n0, ldb, kb, tid);
        load_tile<BTR>(tb + 3 * TILEB, Bl,  n0, ldb, kb, tid);
        asm volatile("cp.async.commit_group;" ::: "memory");
    };

    for (int i = 0; i < STAGES - 1; i++) {
        if (i < NC) loadstage(i);
        else        asm volatile("cp.async.commit_group;" ::: "memory");
    }

    for (int i = 0; i < NC; i++) {
        asm volatile("cp.async.wait_group %0;" :: "n"(STAGES - 2) : "memory");
        __syncthreads();
        if (i + STAGES - 1 < NC) loadstage(i + STAGES - 1);
        else                     asm volatile("cp.async.commit_group;" ::: "memory");

        const int s = i & (STAGES - 1);
        const uint32_t bAh = sb + (uint32_t)(s * 4 + 0) * TILEB;
        const uint32_t bAl = sb + (uint32_t)(s * 4 + 1) * TILEB;
        const uint32_t bBh = sb + (uint32_t)(s * 4 + 2) * TILEB;
        const uint32_t bBl = sb + (uint32_t)(s * 4 + 3) * TILEB;

        #pragma unroll
        for (int ks = 0; ks < 2; ks++) {
            uint32_t ah[4][4], al[4][4];
            #pragma unroll
            for (int tm = 0; tm < 4; tm++) {
                if (!ATR) {
                    int row = warp_m * 64 + tm * 16 + (lane & 15);
                    int ch  = ks * 2 + (lane >> 4);
                    uint32_t off = (uint32_t)(row * 64 + ((ch ^ ((row >> 1) & 3)) << 4));
                    ldsm_x4(ah[tm], bAh + off);
                    ldsm_x4(al[tm], bAl + off);
                } else {
                    int krow = ks * 16 + (lane & 7) + ((lane >> 4) << 3);
                    int mch  = ((warp_m * 64 + tm * 16) >> 3) + ((lane >> 3) & 1);
                    uint32_t off = (uint32_t)(krow * 256 + ((mch ^ (krow & 7)) << 4));
                    ldsm_x4_t(ah[tm], bAh + off);
                    ldsm_x4_t(al[tm], bAl + off);
                }
            }
            uint32_t bh[4][2], bl[4][2];
            #pragma unroll
            for (int tn = 0; tn < 4; tn++) {
                if (!BTR) {
                    int row = warp_n * 32 + tn * 8 + (lane & 7);
                    int ch  = ks * 2 + ((lane >> 3) & 1);
                    uint32_t off = (uint32_t)(row * 64 + ((ch ^ ((row >> 1) & 3)) << 4));
                    ldsm_x2(bh[tn], bBh + off);
                    ldsm_x2(bl[tn], bBl + off);
                } else {
                    int krow = ks * 16 + (lane & 7) + ((lane >> 3) & 1) * 8;
                    int nch  = (warp_n * 32 + tn * 8) >> 3;
                    uint32_t off = (uint32_t)(krow * 256 + ((nch ^ (krow & 7)) << 4));
                    ldsm_x2_t(bh[tn], bBh + off);
                    ldsm_x2_t(bl[tn], bBl + off);
                }
            }
            #pragma unroll
            for (int q = 0; q < 3; q++)
                #pragma unroll
                for (int tm = 0; tm < 4; tm++)
                    #pragma unroll
                    for (int tn = 0; tn < 4; tn++) {
                        const uint32_t* aa = (q == 2) ? al[tm] : ah[tm];
                        const uint32_t* bb = (q == 1) ? bl[tn] : bh[tn];
                        mma16816(d[tm][tn], aa, bb);
                    }
        }
        __syncthreads();
    }

    if (EPI == 0) {
        float* Cb = Cf + (long)blockIdx.z * bsC;
        #pragma unroll
        for (int tm = 0; tm < 4; tm++) {
            const long m = m0 + warp_m * 64 + tm * 16 + (lane >> 2);
            const float bs0 = bias ? bias[m]     : 0.f;
            const float bs1 = bias ? bias[m + 8] : 0.f;
            #pragma unroll
            for (int tn = 0; tn < 4; tn++) {
                const long n = n0 + warp_n * 32 + tn * 8 + (lane & 3) * 2;
                *(float2*)&Cb[m * ldc + n] =
                    make_float2(d[tm][tn][0] + bs0, d[tm][tn][1] + bs0);
                *(float2*)&Cb[(m + 8) * ldc + n] =
                    make_float2(d[tm][tn][2] + bs1, d[tm][tn][3] + bs1);
            }
        }
    } else {
        bf16* Hb = Ch + (long)blockIdx.z * bsC;
        bf16* Lb = Cl + (long)blockIdx.z * bsC;
        const float sc = scale ? *scale : 1.0f;
        #pragma unroll
        for (int tm = 0; tm < 4; tm++) {
            const long m = m0 + warp_m * 64 + tm * 16 + (lane >> 2);
            const float bs0 = bias ? bias[m]     : 0.f;
            const float bs1 = bias ? bias[m + 8] : 0.f;
            #pragma unroll
            for (int tn = 0; tn < 4; tn++) {
                const long n = n0 + warp_n * 32 + tn * 8 + (lane & 3) * 2;
                float v0 = d[tm][tn][0] * sc + bs0;
                float v1 = d[tm][tn][1] * sc + bs0;
                float v2 = d[tm][tn][2] * sc + bs1;
                float v3 = d[tm][tn][3] * sc + bs1;
                __nv_bfloat162 hv0, lv0, hv1, lv1;
                hv0.x = __float2bfloat16(v0);
                hv0.y = __float2bfloat16(v1);
                lv0.x = __float2bfloat16(v0 - __bfloat162float(hv0.x));
                lv0.y = __float2bfloat16(v1 - __bfloat162float(hv0.y));
                hv1.x = __float2bfloat16(v2);
                hv1.y = __float2bfloat16(v3);
                lv1.x = __float2bfloat16(v2 - __bfloat162float(hv1.x));
                lv1.y = __float2bfloat16(v3 - __bfloat162float(hv1.y));
                *(__nv_bfloat162*)&Hb[m * ldc + n]       = hv0;
                *(__nv_bfloat162*)&Lb[m * ldc + n]       = lv0;
                *(__nv_bfloat162*)&Hb[(m + 8) * ldc + n] = hv1;
                *(__nv_bfloat162*)&Lb[(m + 8) * ldc + n] = lv1;
            }
        }
    }
}

// ---------------- Winograd F(4x4,3x3) transforms -------------------------------
// Input: V = B^T d B ; V layout [tap][ci][tcol = b*64 + tile]
__global__ __launch_bounds__(256)
void wino_input4(const float* __restrict__ x, bf16* __restrict__ Vh, bf16* __restrict__ Vl) {
    long gid = (long)blockIdx.x * 256 + threadIdx.x;   // b*CC*64 + ci*64 + tile
    int tile = (int)(gid & (NT4 - 1));
    long r = gid >> 6;
    int ci = (int)(r & (CC - 1));
    int b  = (int)(r >> 9);
    int ty = tile >> 3, tx = tile & 7;
    const float* xb = x + ((long)b * CC + ci) * NN;
    const int h0 = 4 * ty - 1, w0 = 4 * tx - 1;

    float dd[6][6];
    #pragma unroll
    for (int i = 0; i < 6; i++) {
        int ih = h0 + i;
        #pragma unroll
        for (int j = 0; j < 6; j++) {
            int iw = w0 + j;
            dd[i][j] = ((unsigned)ih < HH && (unsigned)iw < WW) ? xb[ih * WW + iw] : 0.f;
        }
    }
    float t[6][6];
    #pragma unroll
    for (int j = 0; j < 6; j++) {
        t[0][j] =  4.f*dd[0][j] - 5.f*dd[2][j] + dd[4][j];
        t[1][j] = -4.f*dd[1][j] - 4.f*dd[2][j] + dd[3][j] + dd[4][j];
        t[2][j] =  4.f*dd[1][j] - 4.f*dd[2][j] - dd[3][j] + dd[4][j];
        t[3][j] = -2.f*dd[1][j] -     dd[2][j] + 2.f*dd[3][j] + dd[4][j];
        t[4][j] =  2.f*dd[1][j] -     dd[2][j] - 2.f*dd[3][j] + dd[4][j];
        t[5][j] =  4.f*dd[1][j] - 5.f*dd[3][j] + dd[5][j];
    }
    const long tcol = (long)b * NT4 + tile;
    #pragma unroll
    for (int i = 0; i < 6; i++) {
        float V0 =  4.f*t[i][0] - 5.f*t[i][2] + t[i][4];
        float V1 = -4.f*t[i][1] - 4.f*t[i][2] + t[i][3] + t[i][4];
        float V2 =  4.f*t[i][1] - 4.f*t[i][2] - t[i][3] + t[i][4];
        float V3 = -2.f*t[i][1] -     t[i][2] + 2.f*t[i][3] + t[i][4];
        float V4 =  2.f*t[i][1] -     t[i][2] - 2.f*t[i][3] + t[i][4];
        float V5 =  4.f*t[i][1] - 5.f*t[i][3] + t[i][5];
        float Vv[6] = {V0, V1, V2, V3, V4, V5};
        #pragma unroll
        for (int j = 0; j < 6; j++) {
            long off = ((long)(i * 6 + j) * CC + ci) * TCOLS + tcol;
            split_store(Vh, Vl, off, Vv[j]);
        }
    }
}

// Weight: U = G g G^T ; U layout [tap][co][ci]
__global__ __launch_bounds__(256)
void wino_weight4(const float* __restrict__ w, bf16* __restrict__ Uh, bf16* __restrict__ Ul) {
    int gid = blockIdx.x * 256 + threadIdx.x;   // co*512 + ci
    int ci = gid & (CC - 1), co = gid >> 9;
    const float* g = w + (long)gid * 9;
    float t2[6][3];
    #pragma unroll
    for (int j = 0; j < 3; j++) {
        float g0 = g[0 * 3 + j], g1 = g[1 * 3 + j], g2 = g[2 * 3 + j];
        t2[0][j] = 0.25f * g0;
        t2[1][j] = (-g0 - g1 - g2) * (1.f / 6.f);
        t2[2][j] = (-g0 + g1 - g2) * (1.f / 6.f);
        t2[3][j] = g0 * (1.f / 24.f) + g1 * (1.f / 12.f) + g2 * (1.f / 6.f);
        t2[4][j] = g0 * (1.f / 24.f) - g1 * (1.f / 12.f) + g2 * (1.f / 6.f);
        t2[5][j] = g2;
    }
    #pragma unroll
    for (int i = 0; i < 6; i++) {
        float a = t2[i][0], bq = t2[i][1], c = t2[i][2];
        float Uv[6];
        Uv[0] = 0.25f * a;
        Uv[1] = (-a - bq - c) * (1.f / 6.f);
        Uv[2] = (-a + bq - c) * (1.f / 6.f);
        Uv[3] = a * (1.f / 24.f) + bq * (1.f / 12.f) + c * (1.f / 6.f);
        Uv[4] = a * (1.f / 24.f) - bq * (1.f / 12.f) + c * (1.f / 6.f);
        Uv[5] = c;
        #pragma unroll
        for (int j = 0; j < 6; j++) {
            long off = ((long)(i * 6 + j) * CC + co) * CC + ci;
            split_store(Uh, Ul, off, Uv[j]);
        }
    }
}

// Output: Y = A^T M A + bias -> conv out [b][co][n] split bf16
__global__ __launch_bounds__(256)
void wino_output4(const float* __restrict__ M, const float* __restrict__ bias,
                  bf16* __restrict__ oh, bf16* __restrict__ ol) {
    long gid = (long)blockIdx.x * 256 + threadIdx.x;   // b*CC*64 + co*64 + tile
    int tile = (int)(gid & (NT4 - 1));
    long r = gid >> 6;
    int co = (int)(r & (CC - 1));
    int b  = (int)(r >> 9);
    const long tcol = (long)b * NT4 + tile;

    float m[6][6];
    #pragma unroll
    for (int c = 0; c < 36; c++)
        m[c / 6][c % 6] = M[((long)c * CC + co) * TCOLS + tcol];

    float s[4][6];
    #pragma unroll
    for (int j = 0; j < 6; j++) {
        s[0][j] = m[0][j] + m[1][j] + m[2][j] + m[3][j] + m[4][j];
        s[1][j] = m[1][j] - m[2][j] + 2.f * (m[3][j] - m[4][j]);
        s[2][j] = m[1][j] + m[2][j] + 4.f * (m[3][j] + m[4][j]);
        s[3][j] = m[1][j] - m[2][j] + 8.f * (m[3][j] - m[4][j]) + m[5][j];
    }
    const float bs = bias[co];
    int ty = tile >> 3, tx = tile & 7;
    long base = ((long)b * CC + co) * NN + (4 * ty) * WW + 4 * tx;
    #pragma unroll
    for (int i = 0; i < 4; i++) {
        float Y0 = s[i][0] + s[i][1] + s[i][2] + s[i][3] + s[i][4] + bs;
        float Y1 = s[i][1] - s[i][2] + 2.f * (s[i][3] - s[i][4]) + bs;
        float Y2 = s[i][1] + s[i][2] + 4.f * (s[i][3] + s[i][4]) + bs;
        float Y3 = s[i][1] - s[i][2] + 8.f * (s[i][3] - s[i][4]) + s[i][5] + bs;
        long ro = base + i * WW;
        split_store(oh, ol, ro + 0, Y0);
        split_store(oh, ol, ro + 1, Y1);
        split_store(oh, ol, ro + 2, Y2);
        split_store(oh, ol, ro + 3, Y3);
    }
}

// ---------------- plain split ---------------------------------------------------
__global__ void split_kernel(const float* __restrict__ in,
                             bf16* __restrict__ oh, bf16* __restrict__ ol) {
    long g = (long)blockIdx.x * 256 + threadIdx.x;
    split_store(oh, ol, g, in[g]);
}

// ---------------- softmax -------------------------------------------------------
__device__ __forceinline__ float warpMax(float v) {
    #pragma unroll
    for (int o = 16; o > 0; o >>= 1) v = fmaxf(v, __shfl_xor_sync(0xffffffffu, v, o));
    return v;
}
__device__ __forceinline__ float warpSum(float v) {
    #pragma unroll
    for (int o = 16; o > 0; o >>= 1) v += __shfl_xor_sync(0xffffffffu, v, o);
    return v;
}

template<int LEN>
__global__ __launch_bounds__(256)
void softmax_split(const float* __restrict__ buf,
                   bf16* __restrict__ oh, bf16* __restrict__ ol) {
    constexpr int V = LEN / 256;
    const long base = (long)blockIdx.x * LEN;
    const float* row = buf + base;
    const int tid = threadIdx.x, lane = tid & 31, wid = tid >> 5;
    __shared__ float sred[8];
    float v[V];
    float mx = -3.0e38f;
    #pragma unroll
    for (int j = 0; j < V; j++) { v[j] = row[tid + j * 256]; mx = fmaxf(mx, v[j]); }
    mx = warpMax(mx);
    if (lane == 0) sred[wid] = mx;
    __syncthreads();
    if (tid == 0) {
        float m = sred[0];
        #pragma unroll
        for (int i = 1; i < 8; i++) m = fmaxf(m, sred[i]);
        sred[0] = m;
    }
    __syncthreads();
    mx = sred[0];
    __syncthreads();
    float s = 0.f;
    #pragma unroll
    for (int j = 0; j < V; j++) { v[j] = __expf(v[j] - mx); s += v[j]; }
    s = warpSum(s);
    if (lane == 0) sred[wid] = s;
    __syncthreads();
    if (tid == 0) {
        float m = 0.f;
        #pragma unroll
        for (int i = 0; i < 8; i++) m += sred[i];
        sred[0] = m;
    }
    __syncthreads();
    const float inv = 1.0f / sred[0];
    #pragma unroll
    for (int j = 0; j < V; j++)
        split_store(oh, ol, base + tid + j * 256, v[j] * inv);
}

// ---------------- launch --------------------------------------------------------
extern "C" void kernel_launch(void* const* d_in, const int* in_sizes, int n_in,
                              void* d_out, int out_size) {
    const float* x     = (const float*)d_in[0];
    const float* w1    = (const float*)d_in[1];
    const float* b1    = (const float*)d_in[2];
    const float* w2    = (const float*)d_in[3];
    const float* b2    = (const float*)d_in[4];
    const float* w3    = (const float*)d_in[5];
    const float* b3    = (const float*)d_in[6];
    const float* alpha = (const float*)d_in[7];
    const float* beta  = (const float*)d_in[8];
    const float* wf    = (const float*)d_in[9];
    const float* bf    = (const float*)d_in[10];
    float* out = (float*)d_out;

    cudaFuncSetAttribute(mma_gemm<false,true, 0,false>, cudaFuncAttributeMaxDynamicSharedMemorySize, GEMM_SMEM);
    cudaFuncSetAttribute(mma_gemm<true, true, 0,false>, cudaFuncAttributeMaxDynamicSharedMemorySize, GEMM_SMEM);
    cudaFuncSetAttribute(mma_gemm<false,false,0,false>, cudaFuncAttributeMaxDynamicSharedMemorySize, GEMM_SMEM);
    cudaFuncSetAttribute(mma_gemm<false,false,1,false>, cudaFuncAttributeMaxDynamicSharedMemorySize, GEMM_SMEM);
    cudaFuncSetAttribute(mma_gemm<true, true, 1,false>, cudaFuncAttributeMaxDynamicSharedMemorySize, GEMM_SMEM);
    cudaFuncSetAttribute(mma_gemm<false,true, 0,true >, cudaFuncAttributeMaxDynamicSharedMemorySize, GEMM_SMEM);

    bf16 *Vh, *Vl, *U1h, *U1l, *U2h, *U2l, *U3h, *U3l, *wfh, *wfl;
    bf16 *Ah, *Al, *Bmh, *Bml, *Dh, *Dl, *xh, *xl, *Mh, *Ml, *Sh, *Sl;
    bf16 *spath, *spatl, *chanh, *chanl;
    float *Mw, *Mb, *Sb;
    cudaGetSymbolAddress((void**)&Vh, g_Vh);    cudaGetSymbolAddress((void**)&Vl, g_Vl);
    cudaGetSymbolAddress((void**)&U1h, g_U1h);  cudaGetSymbolAddress((void**)&U1l, g_U1l);
    cudaGetSymbolAddress((void**)&U2h, g_U2h);  cudaGetSymbolAddress((void**)&U2l, g_U2l);
    cudaGetSymbolAddress((void**)&U3h, g_U3h);  cudaGetSymbolAddress((void**)&U3l, g_U3l);
    cudaGetSymbolAddress((void**)&Mw, g_Mw);
    cudaGetSymbolAddress((void**)&wfh, g_wfh);  cudaGetSymbolAddress((void**)&wfl, g_wfl);
    cudaGetSymbolAddress((void**)&Ah,  g_Ah);   cudaGetSymbolAddress((void**)&Al,  g_Al);
    cudaGetSymbolAddress((void**)&Bmh, g_Bmh);  cudaGetSymbolAddress((void**)&Bml, g_Bml);
    cudaGetSymbolAddress((void**)&Dh,  g_Dh);   cudaGetSymbolAddress((void**)&Dl,  g_Dl);
    cudaGetSymbolAddress((void**)&xh,  g_xh);   cudaGetSymbolAddress((void**)&xl,  g_xl);
    cudaGetSymbolAddress((void**)&Mb,  g_M);
    cudaGetSymbolAddress((void**)&Mh,  g_Mh);   cudaGetSymbolAddress((void**)&Ml,  g_Ml);
    cudaGetSymbolAddress((void**)&Sb,  g_S);
    cudaGetSymbolAddress((void**)&Sh,  g_Sh);   cudaGetSymbolAddress((void**)&Sl,  g_Sl);
    cudaGetSymbolAddress((void**)&spath, g_spath); cudaGetSymbolAddress((void**)&spatl, g_spatl);
    cudaGetSymbolAddress((void**)&chanh, g_chanh); cudaGetSymbolAddress((void**)&chanl, g_chanl);

    const long sX  = (long)CC * NN;
    const long sM  = (long)NN * NN;
    const long sS  = (long)CC * CC;
    const long sVt = (long)CC * TCOLS;   // per-tap stride of V / Mw
    const long sUt = (long)CC * CC;      // per-tap stride of U
    const unsigned ZALL = 0xFFFFFFFFu;

    // 1) transforms + splits
    wino_input4<<<(unsigned)((long)BB * CC * NT4 / 256), 256>>>(x, Vh, Vl);
    wino_weight4<<<CC * CC / 256, 256>>>(w1, U1h, U1l);
    wino_weight4<<<CC * CC / 256, 256>>>(w2, U2h, U2l);
    wino_weight4<<<CC * CC / 256, 256>>>(w3, U3h, U3l);
    split_kernel<<<CC * C3 / 256, 256>>>(wf, wfh, wfl);
    split_kernel<<<(unsigned)((long)BB * sX / 256), 256>>>(x, xh, xl);

    // 2) three convs via Winograd F(4,3): per tap t: Mw[t][co][:] = U_t . V_t
    {
        dim3 g(TCOLS / 128, CC / 128, TAPS);
        const unsigned totw = (unsigned)((long)BB * CC * NT4 / 256);
        mma_gemm<false,true,0,false><<<g, 256, GEMM_SMEM>>>(
            U1h, U1l, CC, sUt, ZALL, Vh, Vl, Vh, Vl, Vh, Vl, TCOLS, sVt,
            Mw, nullptr, nullptr, TCOLS, sVt, nullptr, nullptr, CC);
        wino_output4<<<totw, 256>>>(Mw, b1, Ah, Al);
        mma_gemm<false,true,0,false><<<g, 256, GEMM_SMEM>>>(
            U2h, U2l, CC, sUt, ZALL, Vh, Vl, Vh, Vl, Vh, Vl, TCOLS, sVt,
            Mw, nullptr, nullptr, TCOLS, sVt, nullptr, nullptr, CC);
        wino_output4<<<totw, 256>>>(Mw, b2, Bmh, Bml);
        mma_gemm<false,true,0,false><<<g, 256, GEMM_SMEM>>>(
            U3h, U3l, CC, sUt, ZALL, Vh, Vl, Vh, Vl, Vh, Vl, TCOLS, sVt,
            Mw, nullptr, nullptr, TCOLS, sVt, nullptr, nullptr, CC);
        wino_output4<<<totw, 256>>>(Mw, b3, Dh, Dl);
    }

    // 3) M[n][m] = sum_c A[c][n]*Bm[c][m]
    {
        dim3 g(NN / 128, NN / 128, BB);
        mma_gemm<true,true,0,false><<<g, 256, GEMM_SMEM>>>(
            Ah, Al, NN, sX, ZALL, Bmh, Bml, Bmh, Bml, Bmh, Bml, NN, sX,
            Mb, nullptr, nullptr, NN, sM, nullptr, nullptr, CC);
    }

    // 4) softmax rows of M -> Mh/Ml
    softmax_split<NN><<<BB * NN, 256>>>(Mb, Mh, Ml);

    // 5) spat[c][n] = sum_m D[c][m]*Msm[n][m]   (epi: alpha -> bf16 split)
    {
        dim3 g(NN / 128, CC / 128, BB);
        mma_gemm<false,false,1,false><<<g, 256, GEMM_SMEM>>>(
            Dh, Dl, NN, sX, ZALL, Mh, Ml, Mh, Ml, Mh, Ml, NN, sM,
            nullptr, spath, spatl, NN, sX, nullptr, alpha, NN);
    }

    // 6) S[c][d] = sum_n x[c][n]*x[d][n]
    {
        dim3 g(CC / 128, CC / 128, BB);
        mma_gemm<false,false,0,false><<<g, 256, GEMM_SMEM>>>(
            xh, xl, NN, sX, ZALL, xh, xl, xh, xl, xh, xl, NN, sX,
            Sb, nullptr, nullptr, CC, sS, nullptr, nullptr, NN);
    }

    // 7) softmax rows of S -> Sh/Sl
    softmax_split<CC><<<BB * CC, 256>>>(Sb, Sh, Sl);

    // 8) chan[c][n] = sum_d Ssm[d][c]*x[d][n]  (epi: beta -> bf16 split)
    {
        dim3 g(NN / 128, CC / 128, BB);
        mma_gemm<true,true,1,false><<<g, 256, GEMM_SMEM>>>(
            Sh, Sl, CC, sS, ZALL, xh, xl, xh, xl, xh, xl, NN, sX,
            nullptr, chanh, chanl, NN, sX, nullptr, beta, CC);
    }

    // 9) fuse: out[c][n] = bf[c] + sum over [x; a*spat; b*chan]
    {
        dim3 g(NN / 128, CC / 128, BB);
        mma_gemm<false,true,0,true><<<g, 256, GEMM_SMEM>>>(
            wfh, wfl, C3, 0, ZALL, xh, xl, spath, spatl, chanh, chanl, NN, sX,
            out, nullptr, nullptr, NN, sX, bf, nullptr, C3);
    }
}

// round 9
// speedup vs baseline: 10.2652x; 1.3031x over previous
#include <cuda_runtime.h>
#include <cuda_fp16.h>
#include <cstdint>

#define BB 16
#define CC 512
#define HH 32
#define WW 32
#define NN 1024
#define C3 1536
#define NT4 64           // F(4x4,3x3) tiles per image (8x8)
#define TCOLS 1024       // BB * NT4 tile-columns
#define TAPS 36

typedef __half fp16;

// ---------------- scratch (device globals) -----------------------------------
__device__ fp16 g_Vh[(size_t)TAPS * CC * TCOLS];                 // B-only: single
__device__ fp16 g_Uh[(size_t)TAPS * C3 * CC], g_Ul[(size_t)TAPS * C3 * CC]; // merged U
__device__ float g_Mw[(size_t)TAPS * C3 * TCOLS];                // conv GEMM out (fp32)
__device__ fp16 g_wfh[CC * C3], g_wfl[CC * C3];
__device__ fp16 g_Ah[(size_t)BB * CC * NN], g_Al[(size_t)BB * CC * NN];   // A-op: split
__device__ fp16 g_Bmh[(size_t)BB * CC * NN];                              // B-only
__device__ fp16 g_Dh[(size_t)BB * CC * NN], g_Dl[(size_t)BB * CC * NN];   // A-op
__device__ fp16 g_xh[(size_t)BB * CC * NN], g_xl[(size_t)BB * CC * NN];   // A in S, B in fuse
__device__ float g_M[(size_t)BB * NN * NN];
__device__ fp16 g_Mh[(size_t)BB * NN * NN];                               // B-only
__device__ float g_S[(size_t)BB * CC * CC];
__device__ fp16 g_Sh[(size_t)BB * CC * CC], g_Sl[(size_t)BB * CC * CC];   // A-op
__device__ fp16 g_spath[(size_t)BB * CC * NN];                            // B-only
__device__ fp16 g_chanh[(size_t)BB * CC * NN];                            // B-only

// ---------------- helpers ------------------------------------------------------
__device__ __forceinline__ uint32_t smem_u32(const void* p) {
    uint32_t a;
    asm("{ .reg .u64 t; cvta.to.shared.u64 t, %1; cvt.u32.u64 %0, t; }"
        : "=r"(a) : "l"(p));
    return a;
}
__device__ __forceinline__ void ldsm_x4(uint32_t* r, uint32_t addr) {
    asm volatile("ldmatrix.sync.aligned.m8n8.x4.shared.b16 {%0,%1,%2,%3}, [%4];"
                 : "=r"(r[0]), "=r"(r[1]), "=r"(r[2]), "=r"(r[3]) : "r"(addr));
}
__device__ __forceinline__ void ldsm_x4_t(uint32_t* r, uint32_t addr) {
    asm volatile("ldmatrix.sync.aligned.m8n8.x4.trans.shared.b16 {%0,%1,%2,%3}, [%4];"
                 : "=r"(r[0]), "=r"(r[1]), "=r"(r[2]), "=r"(r[3]) : "r"(addr));
}
__device__ __forceinline__ void ldsm_x2(uint32_t* r, uint32_t addr) {
    asm volatile("ldmatrix.sync.aligned.m8n8.x2.shared.b16 {%0,%1}, [%2];"
                 : "=r"(r[0]), "=r"(r[1]) : "r"(addr));
}
__device__ __forceinline__ void ldsm_x2_t(uint32_t* r, uint32_t addr) {
    asm volatile("ldmatrix.sync.aligned.m8n8.x2.trans.shared.b16 {%0,%1}, [%2];"
                 : "=r"(r[0]), "=r"(r[1]) : "r"(addr));
}
__device__ __forceinline__ void mma16816(float* d, const uint32_t* a, const uint32_t* b) {
    asm volatile("mma.sync.aligned.m16n8k16.row.col.f32.f16.f16.f32 "
                 "{%0,%1,%2,%3}, {%4,%5,%6,%7}, {%8,%9}, {%0,%1,%2,%3};"
                 : "+f"(d[0]), "+f"(d[1]), "+f"(d[2]), "+f"(d[3])
                 : "r"(a[0]), "r"(a[1]), "r"(a[2]), "r"(a[3]), "r"(b[0]), "r"(b[1]));
}
__device__ __forceinline__ void split_store(fp16* H, fp16* L, long off, float v) {
    fp16 hi = __float2half_rn(v);
    H[off] = hi;
    L[off] = __float2half_rn(v - __half2float(hi));
}

// ---------------- GEMM ----------------------------------------------------------
// Block 128x128, BK=32, 8 warps (2Mx4N), warp tile 64x32.
// A split (Ah+Al), B single. 2 MMAs per tile-pair: Ah*B + Al*B.
#define TILEB 8192
#define STAGES 4
#define GEMM_SMEM (STAGES * 3 * TILEB)   // 96 KB

template<bool TR>
__device__ __forceinline__ void load_tile(uint32_t tb, const fp16* __restrict__ S,
                                          long rowbase, long ld, long k0, int tid) {
    if (!TR) {
        #pragma unroll
        for (int p = 0; p < 2; p++) {
            int row = (tid >> 2) + p * 64;
            int ch  = tid & 3;
            const void* g = (const void*)(S + (rowbase + row) * ld + k0 + ch * 8);
            uint32_t dst = tb + (uint32_t)(row * 64 + ((ch ^ ((row >> 1) & 3)) << 4));
            asm volatile("cp.async.cg.shared.global [%0], [%1], 16;"
                         :: "r"(dst), "l"(g) : "memory");
        }
    } else {
        #pragma unroll
        for (int p = 0; p < 2; p++) {
            int row = (tid >> 4) + p * 16;
            int ch  = tid & 15;
            const void* g = (const void*)(S + (k0 + row) * ld + rowbase + ch * 8);
            uint32_t dst = tb + (uint32_t)(row * 256 + ((ch ^ (row & 7)) << 4));
            asm volatile("cp.async.cg.shared.global [%0], [%1], 16;"
                         :: "r"(dst), "l"(g) : "memory");
        }
    }
}

// EPI: 0 = fp32 (+bias), 2 = single fp16 (*scale, +bias)
template<bool ATR, bool BTR, int EPI, bool SEG>
__global__ __launch_bounds__(256, 1)
void mma_gemm(const fp16* __restrict__ Ah_, const fp16* __restrict__ Al_,
              long lda, long bsA, unsigned zmA,
              const fp16* __restrict__ B0, const fp16* __restrict__ B1,
              const fp16* __restrict__ B2, long ldb, long bsB,
              float* __restrict__ Cf, fp16* __restrict__ Ch,
              long ldc, long bsC,
              const float* __restrict__ bias, const float* __restrict__ scale, int K)
{
    extern __shared__ char smem[];
    const uint32_t sb = smem_u32(smem);
    const int tid = threadIdx.x;
    const int wid = tid >> 5, lane = tid & 31;
    const int warp_m = wid & 1, warp_n = wid >> 1;
    const long m0 = (long)blockIdx.y * 128, n0 = (long)blockIdx.x * 128;
    const long zA = (long)(blockIdx.z & zmA) * bsA, zB = (long)blockIdx.z * bsB;
    Ah_ += zA;  Al_ += zA;
    B0 += zB;  B1 += zB;  B2 += zB;

    float d[4][4][4];
    #pragma unroll
    for (int i = 0; i < 4; i++)
        #pragma unroll
        for (int j = 0; j < 4; j++)
            #pragma unroll
            for (int q = 0; q < 4; q++) d[i][j][q] = 0.f;

    const int NC = K >> 5;

    auto loadstage = [&](int i) {
        const int s = i & (STAGES - 1);
        const long k0 = (long)i * 32;
        const fp16* Bp = B0;
        long kb = k0;
        if (SEG) {
            int seg = (int)(k0 >> 9);
            kb = k0 & 511;
            Bp = (seg == 0) ? B0 : (seg == 1) ? B1 : B2;
        }
        uint32_t tb = sb + (uint32_t)s * 3 * TILEB;
        load_tile<ATR>(tb,             Ah_, m0, lda, k0, tid);
        load_tile<ATR>(tb + TILEB,     Al_, m0, lda, k0, tid);
        load_tile<BTR>(tb + 2 * TILEB, Bp,  n0, ldb, kb, tid);
        asm volatile("cp.async.commit_group;" ::: "memory");
    };

    for (int i = 0; i < STAGES - 1; i++) {
        if (i < NC) loadstage(i);
        else        asm volatile("cp.async.commit_group;" ::: "memory");
    }

    for (int i = 0; i < NC; i++) {
        asm volatile("cp.async.wait_group %0;" :: "n"(STAGES - 2) : "memory");
        __syncthreads();
        if (i + STAGES - 1 < NC) loadstage(i + STAGES - 1);
        else                     asm volatile("cp.async.commit_group;" ::: "memory");

        const int s = i & (STAGES - 1);
        const uint32_t bAh = sb + (uint32_t)(s * 3 + 0) * TILEB;
        const uint32_t bAl = sb + (uint32_t)(s * 3 + 1) * TILEB;
        const uint32_t bBh = sb + (uint32_t)(s * 3 + 2) * TILEB;

        #pragma unroll
        for (int ks = 0; ks < 2; ks++) {
            uint32_t ah[4][4], al[4][4];
            #pragma unroll
            for (int tm = 0; tm < 4; tm++) {
                if (!ATR) {
                    int row = warp_m * 64 + tm * 16 + (lane & 15);
                    int ch  = ks * 2 + (lane >> 4);
                    uint32_t off = (uint32_t)(row * 64 + ((ch ^ ((row >> 1) & 3)) << 4));
                    ldsm_x4(ah[tm], bAh + off);
                    ldsm_x4(al[tm], bAl + off);
                } else {
                    int krow = ks * 16 + (lane & 7) + ((lane >> 4) << 3);
                    int mch  = ((warp_m * 64 + tm * 16) >> 3) + ((lane >> 3) & 1);
                    uint32_t off = (uint32_t)(krow * 256 + ((mch ^ (krow & 7)) << 4));
                    ldsm_x4_t(ah[tm], bAh + off);
                    ldsm_x4_t(al[tm], bAl + off);
                }
            }
            uint32_t bh[4][2];
            #pragma unroll
            for (int tn = 0; tn < 4; tn++) {
                if (!BTR) {
                    int row = warp_n * 32 + tn * 8 + (lane & 7);
                    int ch  = ks * 2 + ((lane >> 3) & 1);
                    uint32_t off = (uint32_t)(row * 64 + ((ch ^ ((row >> 1) & 3)) << 4));
                    ldsm_x2(bh[tn], bBh + off);
                } else {
                    int krow = ks * 16 + (lane & 7) + ((lane >> 3) & 1) * 8;
                    int nch  = (warp_n * 32 + tn * 8) >> 3;
                    uint32_t off = (uint32_t)(krow * 256 + ((nch ^ (krow & 7)) << 4));
                    ldsm_x2_t(bh[tn], bBh + off);
                }
            }
            // per-accumulator order: Ah*B then Al*B (deterministic)
            #pragma unroll
            for (int q = 0; q < 2; q++)
                #pragma unroll
                for (int tm = 0; tm < 4; tm++)
                    #pragma unroll
                    for (int tn = 0; tn < 4; tn++)
                        mma16816(d[tm][tn], q ? al[tm] : ah[tm], bh[tn]);
        }
        __syncthreads();
    }

    if (EPI == 0) {
        float* Cb = Cf + (long)blockIdx.z * bsC;
        #pragma unroll
        for (int tm = 0; tm < 4; tm++) {
            const long m = m0 + warp_m * 64 + tm * 16 + (lane >> 2);
            const float bs0 = bias ? bias[m]     : 0.f;
            const float bs1 = bias ? bias[m + 8] : 0.f;
            #pragma unroll
            for (int tn = 0; tn < 4; tn++) {
                const long n = n0 + warp_n * 32 + tn * 8 + (lane & 3) * 2;
                *(float2*)&Cb[m * ldc + n] =
                    make_float2(d[tm][tn][0] + bs0, d[tm][tn][1] + bs0);
                *(float2*)&Cb[(m + 8) * ldc + n] =
                    make_float2(d[tm][tn][2] + bs1, d[tm][tn][3] + bs1);
            }
        }
    } else {
        fp16* Hb = Ch + (long)blockIdx.z * bsC;
        const float sc = scale ? *scale : 1.0f;
        #pragma unroll
        for (int tm = 0; tm < 4; tm++) {
            const long m = m0 + warp_m * 64 + tm * 16 + (lane >> 2);
            const float bs0 = bias ? bias[m]     : 0.f;
            const float bs1 = bias ? bias[m + 8] : 0.f;
            #pragma unroll
            for (int tn = 0; tn < 4; tn++) {
                const long n = n0 + warp_n * 32 + tn * 8 + (lane & 3) * 2;
                __half2 p0 = __floats2half2_rn(d[tm][tn][0] * sc + bs0,
                                               d[tm][tn][1] * sc + bs0);
                __half2 p1 = __floats2half2_rn(d[tm][tn][2] * sc + bs1,
                                               d[tm][tn][3] * sc + bs1);
                *(__half2*)&Hb[m * ldc + n]       = p0;
                *(__half2*)&Hb[(m + 8) * ldc + n] = p1;
            }
        }
    }
}

// ---------------- Winograd F(4x4,3x3) transforms -------------------------------
__global__ __launch_bounds__(256)
void wino_input4(const float* __restrict__ x, fp16* __restrict__ Vh) {
    long gid = (long)blockIdx.x * 256 + threadIdx.x;
    int tile = (int)(gid & (NT4 - 1));
    long r = gid >> 6;
    int ci = (int)(r & (CC - 1));
    int b  = (int)(r >> 9);
    int ty = tile >> 3, tx = tile & 7;
    const float* xb = x + ((long)b * CC + ci) * NN;
    const int h0 = 4 * ty - 1, w0 = 4 * tx - 1;

    float dd[6][6];
    #pragma unroll
    for (int i = 0; i < 6; i++) {
        int ih = h0 + i;
        #pragma unroll
        for (int j = 0; j < 6; j++) {
            int iw = w0 + j;
            dd[i][j] = ((unsigned)ih < HH && (unsigned)iw < WW) ? xb[ih * WW + iw] : 0.f;
        }
    }
    float t[6][6];
    #pragma unroll
    for (int j = 0; j < 6; j++) {
        t[0][j] =  4.f*dd[0][j] - 5.f*dd[2][j] + dd[4][j];
        t[1][j] = -4.f*dd[1][j] - 4.f*dd[2][j] + dd[3][j] + dd[4][j];
        t[2][j] =  4.f*dd[1][j] - 4.f*dd[2][j] - dd[3][j] + dd[4][j];
        t[3][j] = -2.f*dd[1][j] -     dd[2][j] + 2.f*dd[3][j] + dd[4][j];
        t[4][j] =  2.f*dd[1][j] -     dd[2][j] - 2.f*dd[3][j] + dd[4][j];
        t[5][j] =  4.f*dd[1][j] - 5.f*dd[3][j] + dd[5][j];
    }
    const long tcol = (long)b * NT4 + tile;
    #pragma unroll
    for (int i = 0; i < 6; i++) {
        float V0 =  4.f*t[i][0] - 5.f*t[i][2] + t[i][4];
        float V1 = -4.f*t[i][1] - 4.f*t[i][2] + t[i][3] + t[i][4];
        float V2 =  4.f*t[i][1] - 4.f*t[i][2] - t[i][3] + t[i][4];
        float V3 = -2.f*t[i][1] -     t[i][2] + 2.f*t[i][3] + t[i][4];
        float V4 =  2.f*t[i][1] -     t[i][2] - 2.f*t[i][3] + t[i][4];
        float V5 =  4.f*t[i][1] - 5.f*t[i][3] + t[i][5];
        float Vv[6] = {V0, V1, V2, V3, V4, V5};
        #pragma unroll
        for (int j = 0; j < 6; j++)
            Vh[((long)(i * 6 + j) * CC + ci) * TCOLS + tcol] = __float2half_rn(Vv[j]);
    }
}

// Weight: U = G g G^T ; merged layout [tap][co3 = co_base+co][ci]
__global__ __launch_bounds__(256)
void wino_weight4(const float* __restrict__ w, fp16* __restrict__ Uh, fp16* __restrict__ Ul,
                  int co_base) {
    int gid = blockIdx.x * 256 + threadIdx.x;   // co*512 + ci
    int ci = gid & (CC - 1), co = gid >> 9;
    const float* g = w + (long)gid * 9;
    float t2[6][3];
    #pragma unroll
    for (int j = 0; j < 3; j++) {
        float g0 = g[0 * 3 + j], g1 = g[1 * 3 + j], g2 = g[2 * 3 + j];
        t2[0][j] = 0.25f * g0;
        t2[1][j] = (-g0 - g1 - g2) * (1.f / 6.f);
        t2[2][j] = (-g0 + g1 - g2) * (1.f / 6.f);
        t2[3][j] = g0 * (1.f / 24.f) + g1 * (1.f / 12.f) + g2 * (1.f / 6.f);
        t2[4][j] = g0 * (1.f / 24.f) - g1 * (1.f / 12.f) + g2 * (1.f / 6.f);
        t2[5][j] = g2;
    }
    #pragma unroll
    for (int i = 0; i < 6; i++) {
        float a = t2[i][0], bq = t2[i][1], c = t2[i][2];
        float Uv[6];
        Uv[0] = 0.25f * a;
        Uv[1] = (-a - bq - c) * (1.f / 6.f);
        Uv[2] = (-a + bq - c) * (1.f / 6.f);
        Uv[3] = a * (1.f / 24.f) + bq * (1.f / 12.f) + c * (1.f / 6.f);
        Uv[4] = a * (1.f / 24.f) - bq * (1.f / 12.f) + c * (1.f / 6.f);
        Uv[5] = c;
        #pragma unroll
        for (int j = 0; j < 6; j++) {
            long off = ((long)(i * 6 + j) * C3 + co_base + co) * CC + ci;
            split_store(Uh, Ul, off, Uv[j]);
        }
    }
}

// Output transform for the merged 3-conv GEMM. Mw[tap][co3][tcol].
// seg0 -> A (split), seg1 -> Bm (single), seg2 -> D (split)
__global__ __launch_bounds__(256)
void wino_output4(const float* __restrict__ M,
                  const float* __restrict__ b1, const float* __restrict__ b2,
                  const float* __restrict__ b3,
                  fp16* __restrict__ Ah, fp16* __restrict__ Al,
                  fp16* __restrict__ Bmh,
                  fp16* __restrict__ Dh, fp16* __restrict__ Dl) {
    long gid = (long)blockIdx.x * 256 + threadIdx.x;   // b*C3*64 + co3*64 + tile
    int tile = (int)(gid & (NT4 - 1));
    long r = gid >> 6;
    int co3 = (int)(r % C3);
    int b   = (int)(r / C3);
    const long tcol = (long)b * NT4 + tile;
    const int seg = co3 >> 9, co = co3 & (CC - 1);

    float m[6][6];
    #pragma unroll
    for (int c = 0; c < 36; c++)
        m[c / 6][c % 6] = M[((long)c * C3 + co3) * TCOLS + tcol];

    float s[4][6];
    #pragma unroll
    for (int j = 0; j < 6; j++) {
        s[0][j] = m[0][j] + m[1][j] + m[2][j] + m[3][j] + m[4][j];
        s[1][j] = m[1][j] - m[2][j] + 2.f * (m[3][j] - m[4][j]);
        s[2][j] = m[1][j] + m[2][j] + 4.f * (m[3][j] + m[4][j]);
        s[3][j] = m[1][j] - m[2][j] + 8.f * (m[3][j] - m[4][j]) + m[5][j];
    }
    const float bs = (seg == 0) ? b1[co] : (seg == 1) ? b2[co] : b3[co];
    int ty = tile >> 3, tx = tile & 7;
    long base = ((long)b * CC + co) * NN + (4 * ty) * WW + 4 * tx;
    #pragma unroll
    for (int i = 0; i < 4; i++) {
        float Y[4];
        Y[0] = s[i][0] + s[i][1] + s[i][2] + s[i][3] + s[i][4] + bs;
        Y[1] = s[i][1] - s[i][2] + 2.f * (s[i][3] - s[i][4]) + bs;
        Y[2] = s[i][1] + s[i][2] + 4.f * (s[i][3] + s[i][4]) + bs;
        Y[3] = s[i][1] - s[i][2] + 8.f * (s[i][3] - s[i][4]) + s[i][5] + bs;
        long ro = base + i * WW;
        #pragma unroll
        for (int j = 0; j < 4; j++) {
            if (seg == 0)      split_store(Ah, Al, ro + j, Y[j]);
            else if (seg == 2) split_store(Dh, Dl, ro + j, Y[j]);
            else               Bmh[ro + j] = __float2half_rn(Y[j]);
        }
    }
}

// ---------------- plain split ---------------------------------------------------
__global__ void split_kernel(const float* __restrict__ in,
                             fp16* __restrict__ oh, fp16* __restrict__ ol) {
    long g = (long)blockIdx.x * 256 + threadIdx.x;
    split_store(oh, ol, g, in[g]);
}

// ---------------- softmax -------------------------------------------------------
__device__ __forceinline__ float warpMax(float v) {
    #pragma unroll
    for (int o = 16; o > 0; o >>= 1) v = fmaxf(v, __shfl_xor_sync(0xffffffffu, v, o));
    return v;
}
__device__ __forceinline__ float warpSum(float v) {
    #pragma unroll
    for (int o = 16; o > 0; o >>= 1) v += __shfl_xor_sync(0xffffffffu, v, o);
    return v;
}

template<int LEN, bool LO>
__global__ __launch_bounds__(256)
void softmax_fp16(const float* __restrict__ buf,
                  fp16* __restrict__ oh, fp16* __restrict__ ol) {
    constexpr int V = LEN / 256;
    const long base = (long)blockIdx.x * LEN;
    const float* row = buf + base;
    const int tid = threadIdx.x, lane = tid & 31, wid = tid >> 5;
    __shared__ float sred[8];
    float v[V];
    float mx = -3.0e38f;
    #pragma unroll
    for (int j = 0; j < V; j++) { v[j] = row[tid + j * 256]; mx = fmaxf(mx, v[j]); }
    mx = warpMax(mx);
    if (lane == 0) sred[wid] = mx;
    __syncthreads();
    if (tid == 0) {
        float m = sred[0];
        #pragma unroll
        for (int i = 1; i < 8; i++) m = fmaxf(m, sred[i]);
        sred[0] = m;
    }
    __syncthreads();
    mx = sred[0];
    __syncthreads();
    float s = 0.f;
    #pragma unroll
    for (int j = 0; j < V; j++) { v[j] = __expf(v[j] - mx); s += v[j]; }
    s = warpSum(s);
    if (lane == 0) sred[wid] = s;
    __syncthreads();
    if (tid == 0) {
        float m = 0.f;
        #pragma unroll
        for (int i = 0; i < 8; i++) m += sred[i];
        sred[0] = m;
    }
    __syncthreads();
    const float inv = 1.0f / sred[0];
    #pragma unroll
    for (int j = 0; j < V; j++) {
        float w = v[j] * inv;
        if (LO) split_store(oh, ol, base + tid + j * 256, w);
        else    oh[base + tid + j * 256] = __float2half_rn(w);
    }
}

// ---------------- launch --------------------------------------------------------
extern "C" void kernel_launch(void* const* d_in, const int* in_sizes, int n_in,
                              void* d_out, int out_size) {
    const float* x     = (const float*)d_in[0];
    const float* w1    = (const float*)d_in[1];
    const float* b1    = (const float*)d_in[2];
    const float* w2    = (const float*)d_in[3];
    const float* b2    = (const float*)d_in[4];
    const float* w3    = (const float*)d_in[5];
    const float* b3    = (const float*)d_in[6];
    const float* alpha = (const float*)d_in[7];
    const float* beta  = (const float*)d_in[8];
    const float* wf    = (const float*)d_in[9];
    const float* bf    = (const float*)d_in[10];
    float* out = (float*)d_out;

    cudaFuncSetAttribute(mma_gemm<false,true, 0,false>, cudaFuncAttributeMaxDynamicSharedMemorySize, GEMM_SMEM);
    cudaFuncSetAttribute(mma_gemm<true, true, 0,false>, cudaFuncAttributeMaxDynamicSharedMemorySize, GEMM_SMEM);
    cudaFuncSetAttribute(mma_gemm<false,false,2,false>, cudaFuncAttributeMaxDynamicSharedMemorySize, GEMM_SMEM);
    cudaFuncSetAttribute(mma_gemm<false,false,0,false>, cudaFuncAttributeMaxDynamicSharedMemorySize, GEMM_SMEM);
    cudaFuncSetAttribute(mma_gemm<true, true, 2,false>, cudaFuncAttributeMaxDynamicSharedMemorySize, GEMM_SMEM);
    cudaFuncSetAttribute(mma_gemm<false,true, 0,true >, cudaFuncAttributeMaxDynamicSharedMemorySize, GEMM_SMEM);

    fp16 *Vh, *Uh, *Ul, *wfh, *wfl;
    fp16 *Ah, *Al, *Bmh, *Dh, *Dl, *xh, *xl, *Mh, *Sh, *Sl, *spath, *chanh;
    float *Mw, *Mb, *Sb;
    cudaGetSymbolAddress((void**)&Vh, g_Vh);
    cudaGetSymbolAddress((void**)&Uh, g_Uh);    cudaGetSymbolAddress((void**)&Ul, g_Ul);
    cudaGetSymbolAddress((void**)&Mw, g_Mw);
    cudaGetSymbolAddress((void**)&wfh, g_wfh);  cudaGetSymbolAddress((void**)&wfl, g_wfl);
    cudaGetSymbolAddress((void**)&Ah,  g_Ah);   cudaGetSymbolAddress((void**)&Al,  g_Al);
    cudaGetSymbolAddress((void**)&Bmh, g_Bmh);
    cudaGetSymbolAddress((void**)&Dh,  g_Dh);   cudaGetSymbolAddress((void**)&Dl,  g_Dl);
    cudaGetSymbolAddress((void**)&xh,  g_xh);   cudaGetSymbolAddress((void**)&xl,  g_xl);
    cudaGetSymbolAddress((void**)&Mb,  g_M);
    cudaGetSymbolAddress((void**)&Mh,  g_Mh);
    cudaGetSymbolAddress((void**)&Sb,  g_S);
    cudaGetSymbolAddress((void**)&Sh,  g_Sh);   cudaGetSymbolAddress((void**)&Sl,  g_Sl);
    cudaGetSymbolAddress((void**)&spath, g_spath);
    cudaGetSymbolAddress((void**)&chanh, g_chanh);

    const long sX  = (long)CC * NN;
    const long sM  = (long)NN * NN;
    const long sS  = (long)CC * CC;
    const long sVt = (long)CC * TCOLS;   // per-tap stride of V
    const long sUt = (long)C3 * CC;      // per-tap stride of merged U
    const long sMwt = (long)C3 * TCOLS;  // per-tap stride of Mw
    const unsigned ZALL = 0xFFFFFFFFu;

    // 1) transforms + splits
    wino_input4<<<(unsigned)((long)BB * CC * NT4 / 256), 256>>>(x, Vh);
    wino_weight4<<<CC * CC / 256, 256>>>(w1, Uh, Ul, 0);
    wino_weight4<<<CC * CC / 256, 256>>>(w2, Uh, Ul, CC);
    wino_weight4<<<CC * CC / 256, 256>>>(w3, Uh, Ul, 2 * CC);
    split_kernel<<<CC * C3 / 256, 256>>>(wf, wfh, wfl);
    split_kernel<<<(unsigned)((long)BB * sX / 256), 256>>>(x, xh, xl);

    // 2) merged 3-conv Winograd GEMM: per tap t: Mw[t] = U[t] . V[t]
    {
        dim3 g(TCOLS / 128, C3 / 128, TAPS);
        mma_gemm<false,true,0,false><<<g, 256, GEMM_SMEM>>>(
            Uh, Ul, CC, sUt, ZALL, Vh, Vh, Vh, TCOLS, sVt,
            Mw, nullptr, TCOLS, sMwt, nullptr, nullptr, CC);
        wino_output4<<<(unsigned)((long)BB * C3 * NT4 / 256), 256>>>(
            Mw, b1, b2, b3, Ah, Al, Bmh, Dh, Dl);
    }

    // 3) M[n][m] = sum_c A[c][n]*Bm[c][m]
    {
        dim3 g(NN / 128, NN / 128, BB);
        mma_gemm<true,true,0,false><<<g, 256, GEMM_SMEM>>>(
            Ah, Al, NN, sX, ZALL, Bmh, Bmh, Bmh, NN, sX,
            Mb, nullptr, NN, sM, nullptr, nullptr, CC);
    }

    // 4) softmax rows of M -> Mh (single fp16)
    softmax_fp16<NN, false><<<BB * NN, 256>>>(Mb, Mh, nullptr);

    // 5) spat[c][n] = sum_m D[c][m]*Msm[n][m]   (epi: alpha -> single fp16)
    {
        dim3 g(NN / 128, CC / 128, BB);
        mma_gemm<false,false,2,false><<<g, 256, GEMM_SMEM>>>(
            Dh, Dl, NN, sX, ZALL, Mh, Mh, Mh, NN, sM,
            nullptr, spath, NN, sX, nullptr, alpha, NN);
    }

    // 6) S[c][d] = sum_n x[c][n]*x[d][n]
    {
        dim3 g(CC / 128, CC / 128, BB);
        mma_gemm<false,false,0,false><<<g, 256, GEMM_SMEM>>>(
            xh, xl, NN, sX, ZALL, xh, xh, xh, NN, sX,
            Sb, nullptr, CC, sS, nullptr, nullptr, NN);
    }

    // 7) softmax rows of S -> Sh/Sl (split, A-operand of chan)
    softmax_fp16<CC, true><<<BB * CC, 256>>>(Sb, Sh, Sl);

    // 8) chan[c][n] = sum_d Ssm[d][c]*x[d][n]  (epi: beta -> single fp16)
    {
        dim3 g(NN / 128, CC / 128, BB);
        mma_gemm<true,true,2,false><<<g, 256, GEMM_SMEM>>>(
            Sh, Sl, CC, sS, ZALL, xh, xh, xh, NN, sX,
            nullptr, chanh, NN, sX, nullptr, beta, CC);
    }

    // 9) fuse: out[c][n] = bf[c] + wf . [x; a*spat; b*chan]
    {
        dim3 g(NN / 128, CC / 128, BB);
        mma_gemm<false,true,0,true><<<g, 256, GEMM_SMEM>>>(
            wfh, wfl, C3, 0, ZALL, xh, spath, chanh, NN, sX,
            out, nullptr, NN, sX, bf, nullptr, C3);
    }
}

// round 10
// speedup vs baseline: 14.5831x; 1.4206x over previous
#include <cuda_runtime.h>
#include <cuda_fp16.h>
#include <cstdint>

#define BB 16
#define CC 512
#define HH 32
#define WW 32
#define NN 1024
#define C3 1536
#define NT4 64           // F(4x4,3x3) tiles per image (8x8)
#define TCOLS 1024       // BB * NT4 tile-columns
#define TAPS 36

typedef __half fp16;

// ---------------- scratch (device globals) -----------------------------------
__device__ fp16 g_Vh[(size_t)TAPS * CC * TCOLS];
__device__ fp16 g_Uh[(size_t)TAPS * C3 * CC];          // merged U (3 convs)
__device__ float g_Mw[(size_t)TAPS * C3 * TCOLS];      // conv GEMM out (fp32)
__device__ fp16 g_wfh[CC * C3];
__device__ fp16 g_Ah[(size_t)BB * CC * NN];
__device__ fp16 g_Bmh[(size_t)BB * CC * NN];
__device__ fp16 g_Dh[(size_t)BB * CC * NN];
__device__ fp16 g_xh[(size_t)BB * CC * NN];
__device__ float g_M[(size_t)BB * NN * NN];
__device__ fp16 g_Mh[(size_t)BB * NN * NN];
__device__ float g_S[(size_t)BB * CC * CC];
__device__ fp16 g_Sh[(size_t)BB * CC * CC];
__device__ fp16 g_spath[(size_t)BB * CC * NN];
__device__ fp16 g_chanh[(size_t)BB * CC * NN];

// ---------------- helpers ------------------------------------------------------
__device__ __forceinline__ uint32_t smem_u32(const void* p) {
    uint32_t a;
    asm("{ .reg .u64 t; cvta.to.shared.u64 t, %1; cvt.u32.u64 %0, t; }"
        : "=r"(a) : "l"(p));
    return a;
}
__device__ __forceinline__ void ldsm_x4(uint32_t* r, uint32_t addr) {
    asm volatile("ldmatrix.sync.aligned.m8n8.x4.shared.b16 {%0,%1,%2,%3}, [%4];"
                 : "=r"(r[0]), "=r"(r[1]), "=r"(r[2]), "=r"(r[3]) : "r"(addr));
}
__device__ __forceinline__ void ldsm_x4_t(uint32_t* r, uint32_t addr) {
    asm volatile("ldmatrix.sync.aligned.m8n8.x4.trans.shared.b16 {%0,%1,%2,%3}, [%4];"
                 : "=r"(r[0]), "=r"(r[1]), "=r"(r[2]), "=r"(r[3]) : "r"(addr));
}
__device__ __forceinline__ void ldsm_x2(uint32_t* r, uint32_t addr) {
    asm volatile("ldmatrix.sync.aligned.m8n8.x2.shared.b16 {%0,%1}, [%2];"
                 : "=r"(r[0]), "=r"(r[1]) : "r"(addr));
}
__device__ __forceinline__ void ldsm_x2_t(uint32_t* r, uint32_t addr) {
    asm volatile("ldmatrix.sync.aligned.m8n8.x2.trans.shared.b16 {%0,%1}, [%2];"
                 : "=r"(r[0]), "=r"(r[1]) : "r"(addr));
}
__device__ __forceinline__ void mma16816(float* d, const uint32_t* a, const uint32_t* b) {
    asm volatile("mma.sync.aligned.m16n8k16.row.col.f32.f16.f16.f32 "
                 "{%0,%1,%2,%3}, {%4,%5,%6,%7}, {%8,%9}, {%0,%1,%2,%3};"
                 : "+f"(d[0]), "+f"(d[1]), "+f"(d[2]), "+f"(d[3])
                 : "r"(a[0]), "r"(a[1]), "r"(a[2]), "r"(a[3]), "r"(b[0]), "r"(b[1]));
}

// ---------------- GEMM ----------------------------------------------------------
// Block 128x128, BK=32, 8 warps (2Mx4N), warp tile 64x32. Pure fp16 operands.
#define TILEB 8192
#define STAGES 4
#define GEMM_SMEM (STAGES * 2 * TILEB)   // 64 KB

template<bool TR>
__device__ __forceinline__ void load_tile(uint32_t tb, const fp16* __restrict__ S,
                                          long rowbase, long ld, long k0, int tid) {
    if (!TR) {
        #pragma unroll
        for (int p = 0; p < 2; p++) {
            int row = (tid >> 2) + p * 64;
            int ch  = tid & 3;
            const void* g = (const void*)(S + (rowbase + row) * ld + k0 + ch * 8);
            uint32_t dst = tb + (uint32_t)(row * 64 + ((ch ^ ((row >> 1) & 3)) << 4));
            asm volatile("cp.async.cg.shared.global [%0], [%1], 16;"
                         :: "r"(dst), "l"(g) : "memory");
        }
    } else {
        #pragma unroll
        for (int p = 0; p < 2; p++) {
            int row = (tid >> 4) + p * 16;
            int ch  = tid & 15;
            const void* g = (const void*)(S + (k0 + row) * ld + rowbase + ch * 8);
            uint32_t dst = tb + (uint32_t)(row * 256 + ((ch ^ (row & 7)) << 4));
            asm volatile("cp.async.cg.shared.global [%0], [%1], 16;"
                         :: "r"(dst), "l"(g) : "memory");
        }
    }
}

// EPI: 0 = fp32 (+bias), 2 = fp16 (*scale, +bias)
template<bool ATR, bool BTR, int EPI, bool SEG>
__global__ __launch_bounds__(256, 1)
void mma_gemm(const fp16* __restrict__ A_, long lda, long bsA, unsigned zmA,
              const fp16* __restrict__ B0, const fp16* __restrict__ B1,
              const fp16* __restrict__ B2, long ldb, long bsB,
              float* __restrict__ Cf, fp16* __restrict__ Ch,
              long ldc, long bsC,
              const float* __restrict__ bias, const float* __restrict__ scale, int K)
{
    extern __shared__ char smem[];
    const uint32_t sb = smem_u32(smem);
    const int tid = threadIdx.x;
    const int wid = tid >> 5, lane = tid & 31;
    const int warp_m = wid & 1, warp_n = wid >> 1;
    const long m0 = (long)blockIdx.y * 128, n0 = (long)blockIdx.x * 128;
    const long zA = (long)(blockIdx.z & zmA) * bsA, zB = (long)blockIdx.z * bsB;
    A_ += zA;
    B0 += zB;  B1 += zB;  B2 += zB;

    float d[4][4][4];
    #pragma unroll
    for (int i = 0; i < 4; i++)
        #pragma unroll
        for (int j = 0; j < 4; j++)
            #pragma unroll
            for (int q = 0; q < 4; q++) d[i][j][q] = 0.f;

    const int NC = K >> 5;

    auto loadstage = [&](int i) {
        const int s = i & (STAGES - 1);
        const long k0 = (long)i * 32;
        const fp16* Bp = B0;
        long kb = k0;
        if (SEG) {
            int seg = (int)(k0 >> 9);
            kb = k0 & 511;
            Bp = (seg == 0) ? B0 : (seg == 1) ? B1 : B2;
        }
        uint32_t tb = sb + (uint32_t)s * 2 * TILEB;
        load_tile<ATR>(tb,         A_, m0, lda, k0, tid);
        load_tile<BTR>(tb + TILEB, Bp, n0, ldb, kb, tid);
        asm volatile("cp.async.commit_group;" ::: "memory");
    };

    for (int i = 0; i < STAGES - 1; i++) {
        if (i < NC) loadstage(i);
        else        asm volatile("cp.async.commit_group;" ::: "memory");
    }

    for (int i = 0; i < NC; i++) {
        asm volatile("cp.async.wait_group %0;" :: "n"(STAGES - 2) : "memory");
        __syncthreads();
        if (i + STAGES - 1 < NC) loadstage(i + STAGES - 1);
        else                     asm volatile("cp.async.commit_group;" ::: "memory");

        const int s = i & (STAGES - 1);
        const uint32_t bA = sb + (uint32_t)(s * 2 + 0) * TILEB;
        const uint32_t bB = sb + (uint32_t)(s * 2 + 1) * TILEB;

        #pragma unroll
        for (int ks = 0; ks < 2; ks++) {
            uint32_t ah[4][4];
            #pragma unroll
            for (int tm = 0; tm < 4; tm++) {
                if (!ATR) {
                    int row = warp_m * 64 + tm * 16 + (lane & 15);
                    int ch  = ks * 2 + (lane >> 4);
                    uint32_t off = (uint32_t)(row * 64 + ((ch ^ ((row >> 1) & 3)) << 4));
                    ldsm_x4(ah[tm], bA + off);
                } else {
                    int krow = ks * 16 + (lane & 7) + ((lane >> 4) << 3);
                    int mch  = ((warp_m * 64 + tm * 16) >> 3) + ((lane >> 3) & 1);
                    uint32_t off = (uint32_t)(krow * 256 + ((mch ^ (krow & 7)) << 4));
                    ldsm_x4_t(ah[tm], bA + off);
                }
            }
            uint32_t bh[4][2];
            #pragma unroll
            for (int tn = 0; tn < 4; tn++) {
                if (!BTR) {
                    int row = warp_n * 32 + tn * 8 + (lane & 7);
                    int ch  = ks * 2 + ((lane >> 3) & 1);
                    uint32_t off = (uint32_t)(row * 64 + ((ch ^ ((row >> 1) & 3)) << 4));
                    ldsm_x2(bh[tn], bB + off);
                } else {
                    int krow = ks * 16 + (lane & 7) + ((lane >> 3) & 1) * 8;
                    int nch  = (warp_n * 32 + tn * 8) >> 3;
                    uint32_t off = (uint32_t)(krow * 256 + ((nch ^ (krow & 7)) << 4));
                    ldsm_x2_t(bh[tn], bB + off);
                }
            }
            #pragma unroll
            for (int tm = 0; tm < 4; tm++)
                #pragma unroll
                for (int tn = 0; tn < 4; tn++)
                    mma16816(d[tm][tn], ah[tm], bh[tn]);
        }
        __syncthreads();
    }

    if (EPI == 0) {
        float* Cb = Cf + (long)blockIdx.z * bsC;
        #pragma unroll
        for (int tm = 0; tm < 4; tm++) {
            const long m = m0 + warp_m * 64 + tm * 16 + (lane >> 2);
            const float bs0 = bias ? bias[m]     : 0.f;
            const float bs1 = bias ? bias[m + 8] : 0.f;
            #pragma unroll
            for (int tn = 0; tn < 4; tn++) {
                const long n = n0 + warp_n * 32 + tn * 8 + (lane & 3) * 2;
                *(float2*)&Cb[m * ldc + n] =
                    make_float2(d[tm][tn][0] + bs0, d[tm][tn][1] + bs0);
                *(float2*)&Cb[(m + 8) * ldc + n] =
                    make_float2(d[tm][tn][2] + bs1, d[tm][tn][3] + bs1);
            }
        }
    } else {
        fp16* Hb = Ch + (long)blockIdx.z * bsC;
        const float sc = scale ? *scale : 1.0f;
        #pragma unroll
        for (int tm = 0; tm < 4; tm++) {
            const long m = m0 + warp_m * 64 + tm * 16 + (lane >> 2);
            const float bs0 = bias ? bias[m]     : 0.f;
            const float bs1 = bias ? bias[m + 8] : 0.f;
            #pragma unroll
            for (int tn = 0; tn < 4; tn++) {
                const long n = n0 + warp_n * 32 + tn * 8 + (lane & 3) * 2;
                __half2 p0 = __floats2half2_rn(d[tm][tn][0] * sc + bs0,
                                               d[tm][tn][1] * sc + bs0);
                __half2 p1 = __floats2half2_rn(d[tm][tn][2] * sc + bs1,
                                               d[tm][tn][3] * sc + bs1);
                *(__half2*)&Hb[m * ldc + n]       = p0;
                *(__half2*)&Hb[(m + 8) * ldc + n] = p1;
            }
        }
    }
}

// ---------------- Winograd F(4x4,3x3) transforms -------------------------------
__global__ __launch_bounds__(256)
void wino_input4(const float* __restrict__ x, fp16* __restrict__ Vh) {
    long gid = (long)blockIdx.x * 256 + threadIdx.x;
    int tile = (int)(gid & (NT4 - 1));
    long r = gid >> 6;
    int ci = (int)(r & (CC - 1));
    int b  = (int)(r >> 9);
    int ty = tile >> 3, tx = tile & 7;
    const float* xb = x + ((long)b * CC + ci) * NN;
    const int h0 = 4 * ty - 1, w0 = 4 * tx - 1;

    float dd[6][6];
    #pragma unroll
    for (int i = 0; i < 6; i++) {
        int ih = h0 + i;
        #pragma unroll
        for (int j = 0; j < 6; j++) {
            int iw = w0 + j;
            dd[i][j] = ((unsigned)ih < HH && (unsigned)iw < WW) ? xb[ih * WW + iw] : 0.f;
        }
    }
    float t[6][6];
    #pragma unroll
    for (int j = 0; j < 6; j++) {
        t[0][j] =  4.f*dd[0][j] - 5.f*dd[2][j] + dd[4][j];
        t[1][j] = -4.f*dd[1][j] - 4.f*dd[2][j] + dd[3][j] + dd[4][j];
        t[2][j] =  4.f*dd[1][j] - 4.f*dd[2][j] - dd[3][j] + dd[4][j];
        t[3][j] = -2.f*dd[1][j] -     dd[2][j] + 2.f*dd[3][j] + dd[4][j];
        t[4][j] =  2.f*dd[1][j] -     dd[2][j] - 2.f*dd[3][j] + dd[4][j];
        t[5][j] =  4.f*dd[1][j] - 5.f*dd[3][j] + dd[5][j];
    }
    const long tcol = (long)b * NT4 + tile;
    #pragma unroll
    for (int i = 0; i < 6; i++) {
        float V0 =  4.f*t[i][0] - 5.f*t[i][2] + t[i][4];
        float V1 = -4.f*t[i][1] - 4.f*t[i][2] + t[i][3] + t[i][4];
        float V2 =  4.f*t[i][1] - 4.f*t[i][2] - t[i][3] + t[i][4];
        float V3 = -2.f*t[i][1] -     t[i][2] + 2.f*t[i][3] + t[i][4];
        float V4 =  2.f*t[i][1] -     t[i][2] - 2.f*t[i][3] + t[i][4];
        float V5 =  4.f*t[i][1] - 5.f*t[i][3] + t[i][5];
        float Vv[6] = {V0, V1, V2, V3, V4, V5};
        #pragma unroll
        for (int j = 0; j < 6; j++)
            Vh[((long)(i * 6 + j) * CC + ci) * TCOLS + tcol] = __float2half_rn(Vv[j]);
    }
}

// Weight: U = G g G^T ; merged layout [tap][co3 = co_base+co][ci]
__global__ __launch_bounds__(256)
void wino_weight4(const float* __restrict__ w, fp16* __restrict__ Uh, int co_base) {
    int gid = blockIdx.x * 256 + threadIdx.x;   // co*512 + ci
    int ci = gid & (CC - 1), co = gid >> 9;
    const float* g = w + (long)gid * 9;
    float t2[6][3];
    #pragma unroll
    for (int j = 0; j < 3; j++) {
        float g0 = g[0 * 3 + j], g1 = g[1 * 3 + j], g2 = g[2 * 3 + j];
        t2[0][j] = 0.25f * g0;
        t2[1][j] = (-g0 - g1 - g2) * (1.f / 6.f);
        t2[2][j] = (-g0 + g1 - g2) * (1.f / 6.f);
        t2[3][j] = g0 * (1.f / 24.f) + g1 * (1.f / 12.f) + g2 * (1.f / 6.f);
        t2[4][j] = g0 * (1.f / 24.f) - g1 * (1.f / 12.f) + g2 * (1.f / 6.f);
        t2[5][j] = g2;
    }
    #pragma unroll
    for (int i = 0; i < 6; i++) {
        float a = t2[i][0], bq = t2[i][1], c = t2[i][2];
        float Uv[6];
        Uv[0] = 0.25f * a;
        Uv[1] = (-a - bq - c) * (1.f / 6.f);
        Uv[2] = (-a + bq - c) * (1.f / 6.f);
        Uv[3] = a * (1.f / 24.f) + bq * (1.f / 12.f) + c * (1.f / 6.f);
        Uv[4] = a * (1.f / 24.f) - bq * (1.f / 12.f) + c * (1.f / 6.f);
        Uv[5] = c;
        #pragma unroll
        for (int j = 0; j < 6; j++)
            Uh[((long)(i * 6 + j) * C3 + co_base + co) * CC + ci] = __float2half_rn(Uv[j]);
    }
}

// Output transform for the merged 3-conv GEMM. Mw[tap][co3][tcol].
__global__ __launch_bounds__(256)
void wino_output4(const float* __restrict__ M,
                  const float* __restrict__ b1, const float* __restrict__ b2,
                  const float* __restrict__ b3,
                  fp16* __restrict__ Ah, fp16* __restrict__ Bmh,
                  fp16* __restrict__ Dh) {
    long gid = (long)blockIdx.x * 256 + threadIdx.x;   // b*C3*64 + co3*64 + tile
    int tile = (int)(gid & (NT4 - 1));
    long r = gid >> 6;
    int co3 = (int)(r % C3);
    int b   = (int)(r / C3);
    const long tcol = (long)b * NT4 + tile;
    const int seg = co3 >> 9, co = co3 & (CC - 1);

    float m[6][6];
    #pragma unroll
    for (int c = 0; c < 36; c++)
        m[c / 6][c % 6] = M[((long)c * C3 + co3) * TCOLS + tcol];

    float s[4][6];
    #pragma unroll
    for (int j = 0; j < 6; j++) {
        s[0][j] = m[0][j] + m[1][j] + m[2][j] + m[3][j] + m[4][j];
        s[1][j] = m[1][j] - m[2][j] + 2.f * (m[3][j] - m[4][j]);
        s[2][j] = m[1][j] + m[2][j] + 4.f * (m[3][j] + m[4][j]);
        s[3][j] = m[1][j] - m[2][j] + 8.f * (m[3][j] - m[4][j]) + m[5][j];
    }
    const float bs = (seg == 0) ? b1[co] : (seg == 1) ? b2[co] : b3[co];
    fp16* O = (seg == 0) ? Ah : (seg == 1) ? Bmh : Dh;
    int ty = tile >> 3, tx = tile & 7;
    long base = ((long)b * CC + co) * NN + (4 * ty) * WW + 4 * tx;
    #pragma unroll
    for (int i = 0; i < 4; i++) {
        float Y[4];
        Y[0] = s[i][0] + s[i][1] + s[i][2] + s[i][3] + s[i][4] + bs;
        Y[1] = s[i][1] - s[i][2] + 2.f * (s[i][3] - s[i][4]) + bs;
        Y[2] = s[i][1] + s[i][2] + 4.f * (s[i][3] + s[i][4]) + bs;
        Y[3] = s[i][1] - s[i][2] + 8.f * (s[i][3] - s[i][4]) + s[i][5] + bs;
        long ro = base + i * WW;
        #pragma unroll
        for (int j = 0; j < 4; j++)
            O[ro + j] = __float2half_rn(Y[j]);
    }
}

// ---------------- fp32 -> fp16 convert ------------------------------------------
__global__ void cvt_kernel(const float* __restrict__ in, fp16* __restrict__ oh) {
    long g = (long)blockIdx.x * 256 + threadIdx.x;
    oh[g] = __float2half_rn(in[g]);
}

// ---------------- softmax -------------------------------------------------------
__device__ __forceinline__ float warpMax(float v) {
    #pragma unroll
    for (int o = 16; o > 0; o >>= 1) v = fmaxf(v, __shfl_xor_sync(0xffffffffu, v, o));
    return v;
}
__device__ __forceinline__ float warpSum(float v) {
    #pragma unroll
    for (int o = 16; o > 0; o >>= 1) v += __shfl_xor_sync(0xffffffffu, v, o);
    return v;
}

template<int LEN>
__global__ __launch_bounds__(256)
void softmax_fp16(const float* __restrict__ buf, fp16* __restrict__ oh) {
    constexpr int V = LEN / 256;
    const long base = (long)blockIdx.x * LEN;
    const float* row = buf + base;
    const int tid = threadIdx.x, lane = tid & 31, wid = tid >> 5;
    __shared__ float sred[8];
    float v[V];
    float mx = -3.0e38f;
    #pragma unroll
    for (int j = 0; j < V; j++) { v[j] = row[tid + j * 256]; mx = fmaxf(mx, v[j]); }
    mx = warpMax(mx);
    if (lane == 0) sred[wid] = mx;
    __syncthreads();
    if (tid == 0) {
        float m = sred[0];
        #pragma unroll
        for (int i = 1; i < 8; i++) m = fmaxf(m, sred[i]);
        sred[0] = m;
    }
    __syncthreads();
    mx = sred[0];
    __syncthreads();
    float s = 0.f;
    #pragma unroll
    for (int j = 0; j < V; j++) { v[j] = __expf(v[j] - mx); s += v[j]; }
    s = warpSum(s);
    if (lane == 0) sred[wid] = s;
    __syncthreads();
    if (tid == 0) {
        float m = 0.f;
        #pragma unroll
        for (int i = 0; i < 8; i++) m += sred[i];
        sred[0] = m;
    }
    __syncthreads();
    const float inv = 1.0f / sred[0];
    #pragma unroll
    for (int j = 0; j < V; j++)
        oh[base + tid + j * 256] = __float2half_rn(v[j] * inv);
}

// ---------------- launch --------------------------------------------------------
extern "C" void kernel_launch(void* const* d_in, const int* in_sizes, int n_in,
                              void* d_out, int out_size) {
    const float* x     = (const float*)d_in[0];
    const float* w1    = (const float*)d_in[1];
    const float* b1    = (const float*)d_in[2];
    const float* w2    = (const float*)d_in[3];
    const float* b2    = (const float*)d_in[4];
    const float* w3    = (const float*)d_in[5];
    const float* b3    = (const float*)d_in[6];
    const float* alpha = (const float*)d_in[7];
    const float* beta  = (const float*)d_in[8];
    const float* wf    = (const float*)d_in[9];
    const float* bf    = (const float*)d_in[10];
    float* out = (float*)d_out;

    cudaFuncSetAttribute(mma_gemm<false,true, 0,false>, cudaFuncAttributeMaxDynamicSharedMemorySize, GEMM_SMEM);
    cudaFuncSetAttribute(mma_gemm<true, true, 0,false>, cudaFuncAttributeMaxDynamicSharedMemorySize, GEMM_SMEM);
    cudaFuncSetAttribute(mma_gemm<false,false,2,false>, cudaFuncAttributeMaxDynamicSharedMemorySize, GEMM_SMEM);
    cudaFuncSetAttribute(mma_gemm<false,false,0,false>, cudaFuncAttributeMaxDynamicSharedMemorySize, GEMM_SMEM);
    cudaFuncSetAttribute(mma_gemm<true, true, 2,false>, cudaFuncAttributeMaxDynamicSharedMemorySize, GEMM_SMEM);
    cudaFuncSetAttribute(mma_gemm<false,true, 0,true >, cudaFuncAttributeMaxDynamicSharedMemorySize, GEMM_SMEM);

    fp16 *Vh, *Uh, *wfh, *Ah, *Bmh, *Dh, *xh, *Mh, *Sh, *spath, *chanh;
    float *Mw, *Mb, *Sb;
    cudaGetSymbolAddress((void**)&Vh, g_Vh);
    cudaGetSymbolAddress((void**)&Uh, g_Uh);
    cudaGetSymbolAddress((void**)&Mw, g_Mw);
    cudaGetSymbolAddress((void**)&wfh, g_wfh);
    cudaGetSymbolAddress((void**)&Ah,  g_Ah);
    cudaGetSymbolAddress((void**)&Bmh, g_Bmh);
    cudaGetSymbolAddress((void**)&Dh,  g_Dh);
    cudaGetSymbolAddress((void**)&xh,  g_xh);
    cudaGetSymbolAddress((void**)&Mb,  g_M);
    cudaGetSymbolAddress((void**)&Mh,  g_Mh);
    cudaGetSymbolAddress((void**)&Sb,  g_S);
    cudaGetSymbolAddress((void**)&Sh,  g_Sh);
    cudaGetSymbolAddress((void**)&spath, g_spath);
    cudaGetSymbolAddress((void**)&chanh, g_chanh);

    const long sX  = (long)CC * NN;
    const long sM  = (long)NN * NN;
    const long sS  = (long)CC * CC;
    const long sVt = (long)CC * TCOLS;   // per-tap stride of V
    const long sUt = (long)C3 * CC;      // per-tap stride of merged U
    const long sMwt = (long)C3 * TCOLS;  // per-tap stride of Mw
    const unsigned ZALL = 0xFFFFFFFFu;

    // 1) transforms + converts
    wino_input4<<<(unsigned)((long)BB * CC * NT4 / 256), 256>>>(x, Vh);
    wino_weight4<<<CC * CC / 256, 256>>>(w1, Uh, 0);
    wino_weight4<<<CC * CC / 256, 256>>>(w2, Uh, CC);
    wino_weight4<<<CC * CC / 256, 256>>>(w3, Uh, 2 * CC);
    cvt_kernel<<<CC * C3 / 256, 256>>>(wf, wfh);
    cvt_kernel<<<(unsigned)((long)BB * sX / 256), 256>>>(x, xh);

    // 2) merged 3-conv Winograd GEMM: per tap t: Mw[t] = U[t] . V[t]
    {
        dim3 g(TCOLS / 128, C3 / 128, TAPS);
        mma_gemm<false,true,0,false><<<g, 256, GEMM_SMEM>>>(
            Uh, CC, sUt, ZALL, Vh, Vh, Vh, TCOLS, sVt,
            Mw, nullptr, TCOLS, sMwt, nullptr, nullptr, CC);
        wino_output4<<<(unsigned)((long)BB * C3 * NT4 / 256), 256>>>(
            Mw, b1, b2, b3, Ah, Bmh, Dh);
    }

    // 3) M[n][m] = sum_c A[c][n]*Bm[c][m]
    {
        dim3 g(NN / 128, NN / 128, BB);
        mma_gemm<true,true,0,false><<<g, 256, GEMM_SMEM>>>(
            Ah, NN, sX, ZALL, Bmh, Bmh, Bmh, NN, sX,
            Mb, nullptr, NN, sM, nullptr, nullptr, CC);
    }

    // 4) softmax rows of M -> Mh
    softmax_fp16<NN><<<BB * NN, 256>>>(Mb, Mh);

    // 5) spat[c][n] = sum_m D[c][m]*Msm[n][m]   (epi: alpha -> fp16)
    {
        dim3 g(NN / 128, CC / 128, BB);
        mma_gemm<false,false,2,false><<<g, 256, GEMM_SMEM>>>(
            Dh, NN, sX, ZALL, Mh, Mh, Mh, NN, sM,
            nullptr, spath, NN, sX, nullptr, alpha, NN);
    }

    // 6) S[c][d] = sum_n x[c][n]*x[d][n]
    {
        dim3 g(CC / 128, CC / 128, BB);
        mma_gemm<false,false,0,false><<<g, 256, GEMM_SMEM>>>(
            xh, NN, sX, ZALL, xh, xh, xh, NN, sX,
            Sb, nullptr, CC, sS, nullptr, nullptr, NN);
    }

    // 7) softmax rows of S -> Sh
    softmax_fp16<CC><<<BB * CC, 256>>>(Sb, Sh);

    // 8) chan[c][n] = sum_d Ssm[d][c]*x[d][n]  (epi: beta -> fp16)
    {
        dim3 g(NN / 128, CC / 128, BB);
        mma_gemm<true,true,2,false><<<g, 256, GEMM_SMEM>>>(
            Sh, CC, sS, ZALL, xh, xh, xh, NN, sX,
            nullptr, chanh, NN, sX, nullptr, beta, CC);
    }

    // 9) fuse: out[c][n] = bf[c] + wf . [x; a*spat; b*chan]
    {
        dim3 g(NN / 128, CC / 128, BB);
        mma_gemm<false,true,0,true><<<g, 256, GEMM_SMEM>>>(
            wfh, C3, 0, ZALL, xh, spath, chanh, NN, sX,
            out, nullptr, NN, sX, bf, nullptr, C3);
    }
}

// round 11
// speedup vs baseline: 17.5801x; 1.2055x over previous
#include <cuda_runtime.h>
#include <cuda_fp16.h>
#include <cstdint>

#define BB 16
#define CC 512
#define HH 32
#define WW 32
#define NN 1024
#define C3 1536
#define NT4 64           // F(4x4,3x3) tiles per image (8x8)
#define TCOLS 1024       // BB * NT4 tile-columns
#define TAPS 36

typedef __half fp16;

// ---------------- scratch (device globals) -----------------------------------
__device__ fp16 g_Vh[(size_t)TAPS * CC * TCOLS];
__device__ fp16 g_Uh[(size_t)TAPS * C3 * CC];          // merged U (3 convs)
__device__ fp16 g_Mw[(size_t)TAPS * C3 * TCOLS];       // conv GEMM out (fp16)
__device__ fp16 g_wfh[CC * C3];
__device__ fp16 g_Ah[(size_t)BB * CC * NN];
__device__ fp16 g_Bmh[(size_t)BB * CC * NN];
__device__ fp16 g_Dh[(size_t)BB * CC * NN];
__device__ fp16 g_xh[(size_t)BB * CC * NN];
__device__ float g_M[(size_t)BB * NN * NN];
__device__ fp16 g_Mh[(size_t)BB * NN * NN];
__device__ float g_S[(size_t)BB * CC * CC];
__device__ fp16 g_Sh[(size_t)BB * CC * CC];
__device__ fp16 g_spath[(size_t)BB * CC * NN];
__device__ fp16 g_chanh[(size_t)BB * CC * NN];

// ---------------- helpers ------------------------------------------------------
__device__ __forceinline__ uint32_t smem_u32(const void* p) {
    uint32_t a;
    asm("{ .reg .u64 t; cvta.to.shared.u64 t, %1; cvt.u32.u64 %0, t; }"
        : "=r"(a) : "l"(p));
    return a;
}
__device__ __forceinline__ void ldsm_x4(uint32_t* r, uint32_t addr) {
    asm volatile("ldmatrix.sync.aligned.m8n8.x4.shared.b16 {%0,%1,%2,%3}, [%4];"
                 : "=r"(r[0]), "=r"(r[1]), "=r"(r[2]), "=r"(r[3]) : "r"(addr));
}
__device__ __forceinline__ void ldsm_x4_t(uint32_t* r, uint32_t addr) {
    asm volatile("ldmatrix.sync.aligned.m8n8.x4.trans.shared.b16 {%0,%1,%2,%3}, [%4];"
                 : "=r"(r[0]), "=r"(r[1]), "=r"(r[2]), "=r"(r[3]) : "r"(addr));
}
__device__ __forceinline__ void mma16816(float* d, const uint32_t* a, const uint32_t* b) {
    asm volatile("mma.sync.aligned.m16n8k16.row.col.f32.f16.f16.f32 "
                 "{%0,%1,%2,%3}, {%4,%5,%6,%7}, {%8,%9}, {%0,%1,%2,%3};"
                 : "+f"(d[0]), "+f"(d[1]), "+f"(d[2]), "+f"(d[3])
                 : "r"(a[0]), "r"(a[1]), "r"(a[2]), "r"(a[3]), "r"(b[0]), "r"(b[1]));
}

// ---------------- GEMM ----------------------------------------------------------
// Block 128(M) x 256(N), BK=32. 8 warps: 2(M) x 4(N), warp tile 64x64.
// A tile: 8 KB (K-major: 128r x 64B; MN-major: 32kr x 256B).
// B tile: 16 KB (K-major: 256r x 64B; MN-major: 32kr x 512B).
#define ATILE 8192
#define BTILE 16384
#define STGB  (ATILE + BTILE)            // 24 KB
#define STAGES 4
#define GEMM_SMEM (STAGES * STGB)        // 96 KB

template<bool TR>
__device__ __forceinline__ void load_tile_a(uint32_t tb, const fp16* __restrict__ S,
                                            long rowbase, long ld, long k0, int tid) {
    if (!TR) {
        #pragma unroll
        for (int p = 0; p < 2; p++) {
            int row = (tid >> 2) + p * 64;
            int ch  = tid & 3;
            const void* g = (const void*)(S + (rowbase + row) * ld + k0 + ch * 8);
            uint32_t dst = tb + (uint32_t)(row * 64 + ((ch ^ ((row >> 1) & 3)) << 4));
            asm volatile("cp.async.cg.shared.global [%0], [%1], 16;"
                         :: "r"(dst), "l"(g) : "memory");
        }
    } else {
        #pragma unroll
        for (int p = 0; p < 2; p++) {
            int row = (tid >> 4) + p * 16;     // krow 0..31
            int ch  = tid & 15;                // 16 chunks (256B row)
            const void* g = (const void*)(S + (k0 + row) * ld + rowbase + ch * 8);
            uint32_t dst = tb + (uint32_t)(row * 256 + ((ch ^ (row & 7)) << 4));
            asm volatile("cp.async.cg.shared.global [%0], [%1], 16;"
                         :: "r"(dst), "l"(g) : "memory");
        }
    }
}

template<bool TR>
__device__ __forceinline__ void load_tile_b(uint32_t tb, const fp16* __restrict__ S,
                                            long rowbase, long ld, long k0, int tid) {
    if (!TR) {
        #pragma unroll
        for (int p = 0; p < 4; p++) {
            int row = (tid >> 2) + p * 64;     // 256 rows
            int ch  = tid & 3;
            const void* g = (const void*)(S + (rowbase + row) * ld + k0 + ch * 8);
            uint32_t dst = tb + (uint32_t)(row * 64 + ((ch ^ ((row >> 1) & 3)) << 4));
            asm volatile("cp.async.cg.shared.global [%0], [%1], 16;"
                         :: "r"(dst), "l"(g) : "memory");
        }
    } else {
        #pragma unroll
        for (int p = 0; p < 4; p++) {
            int row = (tid >> 5) + p * 8;      // krow 0..31
            int ch  = tid & 31;                // 32 chunks (512B row)
            const void* g = (const void*)(S + (k0 + row) * ld + rowbase + ch * 8);
            uint32_t dst = tb + (uint32_t)(row * 512 + ((ch ^ (row & 7)) << 4));
            asm volatile("cp.async.cg.shared.global [%0], [%1], 16;"
                         :: "r"(dst), "l"(g) : "memory");
        }
    }
}

// EPI: 0 = fp32 (+bias), 2 = fp16 (*scale, +bias)
template<bool ATR, bool BTR, int EPI, bool SEG>
__global__ __launch_bounds__(256, 1)
void mma_gemm(const fp16* __restrict__ A_, long lda, long bsA, unsigned zmA,
              const fp16* __restrict__ B0, const fp16* __restrict__ B1,
              const fp16* __restrict__ B2, long ldb, long bsB,
              float* __restrict__ Cf, fp16* __restrict__ Ch,
              long ldc, long bsC,
              const float* __restrict__ bias, const float* __restrict__ scale, int K)
{
    extern __shared__ char smem[];
    const uint32_t sb = smem_u32(smem);
    const int tid = threadIdx.x;
    const int wid = tid >> 5, lane = tid & 31;
    const int warp_m = wid & 1, warp_n = wid >> 1;
    const long m0 = (long)blockIdx.y * 128, n0 = (long)blockIdx.x * 256;
    const long zA = (long)(blockIdx.z & zmA) * bsA, zB = (long)blockIdx.z * bsB;
    A_ += zA;
    B0 += zB;  B1 += zB;  B2 += zB;

    float d[4][8][4];
    #pragma unroll
    for (int i = 0; i < 4; i++)
        #pragma unroll
        for (int j = 0; j < 8; j++)
            #pragma unroll
            for (int q = 0; q < 4; q++) d[i][j][q] = 0.f;

    const int NC = K >> 5;

    auto loadstage = [&](int i) {
        const int s = i & (STAGES - 1);
        const long k0 = (long)i * 32;
        const fp16* Bp = B0;
        long kb = k0;
        if (SEG) {
            int seg = (int)(k0 >> 9);
            kb = k0 & 511;
            Bp = (seg == 0) ? B0 : (seg == 1) ? B1 : B2;
        }
        uint32_t tb = sb + (uint32_t)s * STGB;
        load_tile_a<ATR>(tb,         A_, m0, lda, k0, tid);
        load_tile_b<BTR>(tb + ATILE, Bp, n0, ldb, kb, tid);
        asm volatile("cp.async.commit_group;" ::: "memory");
    };

    for (int i = 0; i < STAGES - 1; i++) {
        if (i < NC) loadstage(i);
        else        asm volatile("cp.async.commit_group;" ::: "memory");
    }

    for (int i = 0; i < NC; i++) {
        asm volatile("cp.async.wait_group %0;" :: "n"(STAGES - 2) : "memory");
        __syncthreads();
        if (i + STAGES - 1 < NC) loadstage(i + STAGES - 1);
        else                     asm volatile("cp.async.commit_group;" ::: "memory");

        const int s = i & (STAGES - 1);
        const uint32_t bA = sb + (uint32_t)s * STGB;
        const uint32_t bB = bA + ATILE;

        #pragma unroll
        for (int ks = 0; ks < 2; ks++) {
            uint32_t ah[4][4];
            #pragma unroll
            for (int tm = 0; tm < 4; tm++) {
                if (!ATR) {
                    int row = warp_m * 64 + tm * 16 + (lane & 15);
                    int ch  = ks * 2 + (lane >> 4);
                    uint32_t off = (uint32_t)(row * 64 + ((ch ^ ((row >> 1) & 3)) << 4));
                    ldsm_x4(ah[tm], bA + off);
                } else {
                    int krow = ks * 16 + (lane & 7) + ((lane >> 4) << 3);
                    int mch  = ((warp_m * 64 + tm * 16) >> 3) + ((lane >> 3) & 1);
                    uint32_t off = (uint32_t)(krow * 256 + ((mch ^ (krow & 7)) << 4));
                    ldsm_x4_t(ah[tm], bA + off);
                }
            }
            uint32_t bh[4][4];   // per tn-pair: {b0,b1} for tn, {b2,b3} for tn+1
            #pragma unroll
            for (int tp = 0; tp < 4; tp++) {
                if (!BTR) {
                    int row = warp_n * 64 + tp * 16 + (lane & 7) + ((lane >> 4) << 3);
                    int ch  = ks * 2 + ((lane >> 3) & 1);
                    uint32_t off = (uint32_t)(row * 64 + ((ch ^ ((row >> 1) & 3)) << 4));
                    ldsm_x4(bh[tp], bB + off);
                } else {
                    int krow = ks * 16 + (lane & 7) + ((lane >> 3) & 1) * 8;
                    int nch  = ((warp_n * 64 + tp * 16) >> 3) + (lane >> 4);
                    uint32_t off = (uint32_t)(krow * 512 + ((nch ^ (krow & 7)) << 4));
                    ldsm_x4_t(bh[tp], bB + off);
                }
            }
            #pragma unroll
            for (int tm = 0; tm < 4; tm++)
                #pragma unroll
                for (int tp = 0; tp < 4; tp++) {
                    mma16816(d[tm][tp * 2 + 0], ah[tm], bh[tp] + 0);
                    mma16816(d[tm][tp * 2 + 1], ah[tm], bh[tp] + 2);
                }
        }
        __syncthreads();
    }

    if (EPI == 0) {
        float* Cb = Cf + (long)blockIdx.z * bsC;
        #pragma unroll
        for (int tm = 0; tm < 4; tm++) {
            const long m = m0 + warp_m * 64 + tm * 16 + (lane >> 2);
            const float bs0 = bias ? bias[m]     : 0.f;
            const float bs1 = bias ? bias[m + 8] : 0.f;
            #pragma unroll
            for (int tn = 0; tn < 8; tn++) {
                const long n = n0 + warp_n * 64 + tn * 8 + (lane & 3) * 2;
                *(float2*)&Cb[m * ldc + n] =
                    make_float2(d[tm][tn][0] + bs0, d[tm][tn][1] + bs0);
                *(float2*)&Cb[(m + 8) * ldc + n] =
                    make_float2(d[tm][tn][2] + bs1, d[tm][tn][3] + bs1);
            }
        }
    } else {
        fp16* Hb = Ch + (long)blockIdx.z * bsC;
        const float sc = scale ? *scale : 1.0f;
        #pragma unroll
        for (int tm = 0; tm < 4; tm++) {
            const long m = m0 + warp_m * 64 + tm * 16 + (lane >> 2);
            const float bs0 = bias ? bias[m]     : 0.f;
            const float bs1 = bias ? bias[m + 8] : 0.f;
            #pragma unroll
            for (int tn = 0; tn < 8; tn++) {
                const long n = n0 + warp_n * 64 + tn * 8 + (lane & 3) * 2;
                __half2 p0 = __floats2half2_rn(d[tm][tn][0] * sc + bs0,
                                               d[tm][tn][1] * sc + bs0);
                __half2 p1 = __floats2half2_rn(d[tm][tn][2] * sc + bs1,
                                               d[tm][tn][3] * sc + bs1);
                *(__half2*)&Hb[m * ldc + n]       = p0;
                *(__half2*)&Hb[(m + 8) * ldc + n] = p1;
            }
        }
    }
}

// ---------------- Winograd F(4x4,3x3) transforms -------------------------------
__global__ __launch_bounds__(256)
void wino_input4(const float* __restrict__ x, fp16* __restrict__ Vh) {
    long gid = (long)blockIdx.x * 256 + threadIdx.x;
    int tile = (int)(gid & (NT4 - 1));
    long r = gid >> 6;
    int ci = (int)(r & (CC - 1));
    int b  = (int)(r >> 9);
    int ty = tile >> 3, tx = tile & 7;
    const float* xb = x + ((long)b * CC + ci) * NN;
    const int h0 = 4 * ty - 1, w0 = 4 * tx - 1;

    float dd[6][6];
    #pragma unroll
    for (int i = 0; i < 6; i++) {
        int ih = h0 + i;
        #pragma unroll
        for (int j = 0; j < 6; j++) {
            int iw = w0 + j;
            dd[i][j] = ((unsigned)ih < HH && (unsigned)iw < WW) ? xb[ih * WW + iw] : 0.f;
        }
    }
    float t[6][6];
    #pragma unroll
    for (int j = 0; j < 6; j++) {
        t[0][j] =  4.f*dd[0][j] - 5.f*dd[2][j] + dd[4][j];
        t[1][j] = -4.f*dd[1][j] - 4.f*dd[2][j] + dd[3][j] + dd[4][j];
        t[2][j] =  4.f*dd[1][j] - 4.f*dd[2][j] - dd[3][j] + dd[4][j];
        t[3][j] = -2.f*dd[1][j] -     dd[2][j] + 2.f*dd[3][j] + dd[4][j];
        t[4][j] =  2.f*dd[1][j] -     dd[2][j] - 2.f*dd[3][j] + dd[4][j];
        t[5][j] =  4.f*dd[1][j] - 5.f*dd[3][j] + dd[5][j];
    }
    const long tcol = (long)b * NT4 + tile;
    #pragma unroll
    for (int i = 0; i < 6; i++) {
        float V0 =  4.f*t[i][0] - 5.f*t[i][2] + t[i][4];
        float V1 = -4.f*t[i][1] - 4.f*t[i][2] + t[i][3] + t[i][4];
        float V2 =  4.f*t[i][1] - 4.f*t[i][2] - t[i][3] + t[i][4];
        float V3 = -2.f*t[i][1] -     t[i][2] + 2.f*t[i][3] + t[i][4];
        float V4 =  2.f*t[i][1] -     t[i][2] - 2.f*t[i][3] + t[i][4];
        float V5 =  4.f*t[i][1] - 5.f*t[i][3] + t[i][5];
        float Vv[6] = {V0, V1, V2, V3, V4, V5};
        #pragma unroll
        for (int j = 0; j < 6; j++)
            Vh[((long)(i * 6 + j) * CC + ci) * TCOLS + tcol] = __float2half_rn(Vv[j]);
    }
}

__global__ __launch_bounds__(256)
void wino_weight4(const float* __restrict__ w, fp16* __restrict__ Uh, int co_base) {
    int gid = blockIdx.x * 256 + threadIdx.x;   // co*512 + ci
    int ci = gid & (CC - 1), co = gid >> 9;
    const float* g = w + (long)gid * 9;
    float t2[6][3];
    #pragma unroll
    for (int j = 0; j < 3; j++) {
        float g0 = g[0 * 3 + j], g1 = g[1 * 3 + j], g2 = g[2 * 3 + j];
        t2[0][j] = 0.25f * g0;
        t2[1][j] = (-g0 - g1 - g2) * (1.f / 6.f);
        t2[2][j] = (-g0 + g1 - g2) * (1.f / 6.f);
        t2[3][j] = g0 * (1.f / 24.f) + g1 * (1.f / 12.f) + g2 * (1.f / 6.f);
        t2[4][j] = g0 * (1.f / 24.f) - g1 * (1.f / 12.f) + g2 * (1.f / 6.f);
        t2[5][j] = g2;
    }
    #pragma unroll
    for (int i = 0; i < 6; i++) {
        float a = t2[i][0], bq = t2[i][1], c = t2[i][2];
        float Uv[6];
        Uv[0] = 0.25f * a;
        Uv[1] = (-a - bq - c) * (1.f / 6.f);
        Uv[2] = (-a + bq - c) * (1.f / 6.f);
        Uv[3] = a * (1.f / 24.f) + bq * (1.f / 12.f) + c * (1.f / 6.f);
        Uv[4] = a * (1.f / 24.f) - bq * (1.f / 12.f) + c * (1.f / 6.f);
        Uv[5] = c;
        #pragma unroll
        for (int j = 0; j < 6; j++)
            Uh[((long)(i * 6 + j) * C3 + co_base + co) * CC + ci] = __float2half_rn(Uv[j]);
    }
}

// Output transform; Mw fp16 [tap][co3][tcol]
__global__ __launch_bounds__(256)
void wino_output4(const fp16* __restrict__ M,
                  const float* __restrict__ b1, const float* __restrict__ b2,
                  const float* __restrict__ b3,
                  fp16* __restrict__ Ah, fp16* __restrict__ Bmh,
                  fp16* __restrict__ Dh) {
    long gid = (long)blockIdx.x * 256 + threadIdx.x;
    int tile = (int)(gid & (NT4 - 1));
    long r = gid >> 6;
    int co3 = (int)(r % C3);
    int b   = (int)(r / C3);
    const long tcol = (long)b * NT4 + tile;
    const int seg = co3 >> 9, co = co3 & (CC - 1);

    float m[6][6];
    #pragma unroll
    for (int c = 0; c < 36; c++)
        m[c / 6][c % 6] = __half2float(M[((long)c * C3 + co3) * TCOLS + tcol]);

    float s[4][6];
    #pragma unroll
    for (int j = 0; j < 6; j++) {
        s[0][j] = m[0][j] + m[1][j] + m[2][j] + m[3][j] + m[4][j];
        s[1][j] = m[1][j] - m[2][j] + 2.f * (m[3][j] - m[4][j]);
        s[2][j] = m[1][j] + m[2][j] + 4.f * (m[3][j] + m[4][j]);
        s[3][j] = m[1][j] - m[2][j] + 8.f * (m[3][j] - m[4][j]) + m[5][j];
    }
    const float bs = (seg == 0) ? b1[co] : (seg == 1) ? b2[co] : b3[co];
    fp16* O = (seg == 0) ? Ah : (seg == 1) ? Bmh : Dh;
    int ty = tile >> 3, tx = tile & 7;
    long base = ((long)b * CC + co) * NN + (4 * ty) * WW + 4 * tx;
    #pragma unroll
    for (int i = 0; i < 4; i++) {
        float Y[4];
        Y[0] = s[i][0] + s[i][1] + s[i][2] + s[i][3] + s[i][4] + bs;
        Y[1] = s[i][1] - s[i][2] + 2.f * (s[i][3] - s[i][4]) + bs;
        Y[2] = s[i][1] + s[i][2] + 4.f * (s[i][3] + s[i][4]) + bs;
        Y[3] = s[i][1] - s[i][2] + 8.f * (s[i][3] - s[i][4]) + s[i][5] + bs;
        long ro = base + i * WW;
        #pragma unroll
        for (int j = 0; j < 4; j++)
            O[ro + j] = __float2half_rn(Y[j]);
    }
}

// ---------------- fp32 -> fp16 convert ------------------------------------------
__global__ void cvt_kernel(const float* __restrict__ in, fp16* __restrict__ oh) {
    long g = (long)blockIdx.x * 256 + threadIdx.x;
    oh[g] = __float2half_rn(in[g]);
}

// ---------------- softmax -------------------------------------------------------
__device__ __forceinline__ float warpMax(float v) {
    #pragma unroll
    for (int o = 16; o > 0; o >>= 1) v = fmaxf(v, __shfl_xor_sync(0xffffffffu, v, o));
    return v;
}
__device__ __forceinline__ float warpSum(float v) {
    #pragma unroll
    for (int o = 16; o > 0; o >>= 1) v += __shfl_xor_sync(0xffffffffu, v, o);
    return v;
}

template<int LEN>
__global__ __launch_bounds__(256)
void softmax_fp16(const float* __restrict__ buf, fp16* __restrict__ oh) {
    constexpr int V = LEN / 256;
    const long base = (long)blockIdx.x * LEN;
    const float* row = buf + base;
    const int tid = threadIdx.x, lane = tid & 31, wid = tid >> 5;
    __shared__ float sred[8];
    float v[V];
    float mx = -3.0e38f;
    #pragma unroll
    for (int j = 0; j < V; j++) { v[j] = row[tid + j * 256]; mx = fmaxf(mx, v[j]); }
    mx = warpMax(mx);
    if (lane == 0) sred[wid] = mx;
    __syncthreads();
    if (tid == 0) {
        float m = sred[0];
        #pragma unroll
        for (int i = 1; i < 8; i++) m = fmaxf(m, sred[i]);
        sred[0] = m;
    }
    __syncthreads();
    mx = sred[0];
    __syncthreads();
    float s = 0.f;
    #pragma unroll
    for (int j = 0; j < V; j++) { v[j] = __expf(v[j] - mx); s += v[j]; }
    s = warpSum(s);
    if (lane == 0) sred[wid] = s;
    __syncthreads();
    if (tid == 0) {
        float m = 0.f;
        #pragma unroll
        for (int i = 0; i < 8; i++) m += sred[i];
        sred[0] = m;
    }
    __syncthreads();
    const float inv = 1.0f / sred[0];
    #pragma unroll
    for (int j = 0; j < V; j++)
        oh[base + tid + j * 256] = __float2half_rn(v[j] * inv);
}

// ---------------- launch --------------------------------------------------------
extern "C" void kernel_launch(void* const* d_in, const int* in_sizes, int n_in,
                              void* d_out, int out_size) {
    const float* x     = (const float*)d_in[0];
    const float* w1    = (const float*)d_in[1];
    const float* b1    = (const float*)d_in[2];
    const float* w2    = (const float*)d_in[3];
    const float* b2    = (const float*)d_in[4];
    const float* w3    = (const float*)d_in[5];
    const float* b3    = (const float*)d_in[6];
    const float* alpha = (const float*)d_in[7];
    const float* beta  = (const float*)d_in[8];
    const float* wf    = (const float*)d_in[9];
    const float* bf    = (const float*)d_in[10];
    float* out = (float*)d_out;

    cudaFuncSetAttribute(mma_gemm<false,true, 2,false>, cudaFuncAttributeMaxDynamicSharedMemorySize, GEMM_SMEM);
    cudaFuncSetAttribute(mma_gemm<true, true, 0,false>, cudaFuncAttributeMaxDynamicSharedMemorySize, GEMM_SMEM);
    cudaFuncSetAttribute(mma_gemm<false,false,2,false>, cudaFuncAttributeMaxDynamicSharedMemorySize, GEMM_SMEM);
    cudaFuncSetAttribute(mma_gemm<false,false,0,false>, cudaFuncAttributeMaxDynamicSharedMemorySize, GEMM_SMEM);
    cudaFuncSetAttribute(mma_gemm<true, true, 2,false>, cudaFuncAttributeMaxDynamicSharedMemorySize, GEMM_SMEM);
    cudaFuncSetAttribute(mma_gemm<false,true, 0,true >, cudaFuncAttributeMaxDynamicSharedMemorySize, GEMM_SMEM);

    fp16 *Vh, *Uh, *Mw16, *wfh, *Ah, *Bmh, *Dh, *xh, *Mh, *Sh, *spath, *chanh;
    float *Mb, *Sb;
    cudaGetSymbolAddress((void**)&Vh, g_Vh);
    cudaGetSymbolAddress((void**)&Uh, g_Uh);
    cudaGetSymbolAddress((void**)&Mw16, g_Mw);
    cudaGetSymbolAddress((void**)&wfh, g_wfh);
    cudaGetSymbolAddress((void**)&Ah,  g_Ah);
    cudaGetSymbolAddress((void**)&Bmh, g_Bmh);
    cudaGetSymbolAddress((void**)&Dh,  g_Dh);
    cudaGetSymbolAddress((void**)&xh,  g_xh);
    cudaGetSymbolAddress((void**)&Mb,  g_M);
    cudaGetSymbolAddress((void**)&Mh,  g_Mh);
    cudaGetSymbolAddress((void**)&Sb,  g_S);
    cudaGetSymbolAddress((void**)&Sh,  g_Sh);
    cudaGetSymbolAddress((void**)&spath, g_spath);
    cudaGetSymbolAddress((void**)&chanh, g_chanh);

    const long sX  = (long)CC * NN;
    const long sM  = (long)NN * NN;
    const long sS  = (long)CC * CC;
    const long sVt = (long)CC * TCOLS;   // per-tap stride of V
    const long sUt = (long)C3 * CC;      // per-tap stride of merged U
    const long sMwt = (long)C3 * TCOLS;  // per-tap stride of Mw
    const unsigned ZALL = 0xFFFFFFFFu;

    // 1) transforms + converts
    wino_input4<<<(unsigned)((long)BB * CC * NT4 / 256), 256>>>(x, Vh);
    wino_weight4<<<CC * CC / 256, 256>>>(w1, Uh, 0);
    wino_weight4<<<CC * CC / 256, 256>>>(w2, Uh, CC);
    wino_weight4<<<CC * CC / 256, 256>>>(w3, Uh, 2 * CC);
    cvt_kernel<<<CC * C3 / 256, 256>>>(wf, wfh);
    cvt_kernel<<<(unsigned)((long)BB * sX / 256), 256>>>(x, xh);

    // 2) merged 3-conv Winograd GEMM: per tap t: Mw[t] = U[t] . V[t]  (fp16 out)
    {
        dim3 g(TCOLS / 256, C3 / 128, TAPS);
        mma_gemm<false,true,2,false><<<g, 256, GEMM_SMEM>>>(
            Uh, CC, sUt, ZALL, Vh, Vh, Vh, TCOLS, sVt,
            nullptr, Mw16, TCOLS, sMwt, nullptr, nullptr, CC);
        wino_output4<<<(unsigned)((long)BB * C3 * NT4 / 256), 256>>>(
            Mw16, b1, b2, b3, Ah, Bmh, Dh);
    }

    // 3) M[n][m] = sum_c A[c][n]*Bm[c][m]
    {
        dim3 g(NN / 256, NN / 128, BB);
        mma_gemm<true,true,0,false><<<g, 256, GEMM_SMEM>>>(
            Ah, NN, sX, ZALL, Bmh, Bmh, Bmh, NN, sX,
            Mb, nullptr, NN, sM, nullptr, nullptr, CC);
    }

    // 4) softmax rows of M -> Mh
    softmax_fp16<NN><<<BB * NN, 256>>>(Mb, Mh);

    // 5) spat[c][n] = sum_m D[c][m]*Msm[n][m]   (epi: alpha -> fp16)
    {
        dim3 g(NN / 256, CC / 128, BB);
        mma_gemm<false,false,2,false><<<g, 256, GEMM_SMEM>>>(
            Dh, NN, sX, ZALL, Mh, Mh, Mh, NN, sM,
            nullptr, spath, NN, sX, nullptr, alpha, NN);
    }

    // 6) S[c][d] = sum_n x[c][n]*x[d][n]
    {
        dim3 g(CC / 256, CC / 128, BB);
        mma_gemm<false,false,0,false><<<g, 256, GEMM_SMEM>>>(
            xh, NN, sX, ZALL, xh, xh, xh, NN, sX,
            Sb, nullptr, CC, sS, nullptr, nullptr, NN);
    }

    // 7) softmax rows of S -> Sh
    softmax_fp16<CC><<<BB * CC, 256>>>(Sb, Sh);

    // 8) chan[c][n] = sum_d Ssm[d][c]*x[d][n]  (epi: beta -> fp16)
    {
        dim3 g(NN / 256, CC / 128, BB);
        mma_gemm<true,true,2,false><<<g, 256, GEMM_SMEM>>>(
            Sh, CC, sS, ZALL, xh, xh, xh, NN, sX,
            nullptr, chanh, NN, sX, nullptr, beta, CC);
    }

    // 9) fuse: out[c][n] = bf[c] + wf . [x; a*spat; b*chan]
    {
        dim3 g(NN / 256, CC / 128, BB);
        mma_gemm<false,true,0,true><<<g, 256, GEMM_SMEM>>>(
            wfh, C3, 0, ZALL, xh, spath, chanh, NN, sX,
            out, nullptr, NN, sX, bf, nullptr, C3);
    }
}

// round 12
// speedup vs baseline: 19.4743x; 1.1077x over previous
#include <cuda_runtime.h>
#include <cuda_fp16.h>
#include <cstdint>

#define BB 16
#define CC 512
#define HH 32
#define WW 32
#define NN 1024
#define C3 1536
#define NT4 64           // F(4x4,3x3) tiles per image (8x8)
#define TCOLS 1024       // BB * NT4 tile-columns
#define TAPS 36

typedef __half fp16;

// ---------------- scratch (device globals) -----------------------------------
__device__ fp16 g_Vh[(size_t)TAPS * CC * TCOLS];
__device__ fp16 g_Uh[(size_t)TAPS * C3 * CC];          // merged U (3 convs)
__device__ fp16 g_Mw[(size_t)TAPS * C3 * TCOLS];       // conv GEMM out (fp16)
__device__ fp16 g_wfh[CC * C3];
__device__ fp16 g_Ah[(size_t)BB * CC * NN];
__device__ fp16 g_Bmh[(size_t)BB * CC * NN];
__device__ fp16 g_Dh[(size_t)BB * CC * NN];
__device__ fp16 g_xh[(size_t)BB * CC * NN];
__device__ float g_M[(size_t)BB * NN * NN];
__device__ fp16 g_Mh[(size_t)BB * NN * NN];
__device__ float g_S[(size_t)BB * CC * CC];
__device__ fp16 g_Sh[(size_t)BB * CC * CC];
__device__ fp16 g_spath[(size_t)BB * CC * NN];
__device__ fp16 g_chanh[(size_t)BB * CC * NN];

// ---------------- helpers ------------------------------------------------------
__device__ __forceinline__ uint32_t smem_u32(const void* p) {
    uint32_t a;
    asm("{ .reg .u64 t; cvta.to.shared.u64 t, %1; cvt.u32.u64 %0, t; }"
        : "=r"(a) : "l"(p));
    return a;
}
__device__ __forceinline__ void ldsm_x4(uint32_t* r, uint32_t addr) {
    asm volatile("ldmatrix.sync.aligned.m8n8.x4.shared.b16 {%0,%1,%2,%3}, [%4];"
                 : "=r"(r[0]), "=r"(r[1]), "=r"(r[2]), "=r"(r[3]) : "r"(addr));
}
__device__ __forceinline__ void ldsm_x4_t(uint32_t* r, uint32_t addr) {
    asm volatile("ldmatrix.sync.aligned.m8n8.x4.trans.shared.b16 {%0,%1,%2,%3}, [%4];"
                 : "=r"(r[0]), "=r"(r[1]), "=r"(r[2]), "=r"(r[3]) : "r"(addr));
}
__device__ __forceinline__ void mma16816(float* d, const uint32_t* a, const uint32_t* b) {
    asm volatile("mma.sync.aligned.m16n8k16.row.col.f32.f16.f16.f32 "
                 "{%0,%1,%2,%3}, {%4,%5,%6,%7}, {%8,%9}, {%0,%1,%2,%3};"
                 : "+f"(d[0]), "+f"(d[1]), "+f"(d[2]), "+f"(d[3])
                 : "r"(a[0]), "r"(a[1]), "r"(a[2]), "r"(a[3]), "r"(b[0]), "r"(b[1]));
}

// ---------------- GEMM ----------------------------------------------------------
// Block tile 128(M) x 128(N), BK=32. 128 threads, 4 warps: 2(M) x 2(N),
// warp tile 64x64. Two CTAs co-resident per SM (independent barriers).
// Tiles: 8 KB each (K-major: 128r x 64B; MN-major: 32kr x 256B).
#define TILEB 8192
#define STGB  (2 * TILEB)                // 16 KB
#define STAGES 4
#define GEMM_SMEM (STAGES * STGB)        // 64 KB

template<bool TR>
__device__ __forceinline__ void load_tile(uint32_t tb, const fp16* __restrict__ S,
                                          long rowbase, long ld, long k0, int tid) {
    if (!TR) {
        #pragma unroll
        for (int p = 0; p < 4; p++) {
            int row = (tid >> 2) + p * 32;     // 128 rows
            int ch  = tid & 3;
            const void* g = (const void*)(S + (rowbase + row) * ld + k0 + ch * 8);
            uint32_t dst = tb + (uint32_t)(row * 64 + ((ch ^ ((row >> 1) & 3)) << 4));
            asm volatile("cp.async.cg.shared.global [%0], [%1], 16;"
                         :: "r"(dst), "l"(g) : "memory");
        }
    } else {
        #pragma unroll
        for (int p = 0; p < 4; p++) {
            int row = (tid >> 4) + p * 8;      // krow 0..31
            int ch  = tid & 15;                // 16 chunks (256B row)
            const void* g = (const void*)(S + (k0 + row) * ld + rowbase + ch * 8);
            uint32_t dst = tb + (uint32_t)(row * 256 + ((ch ^ (row & 7)) << 4));
            asm volatile("cp.async.cg.shared.global [%0], [%1], 16;"
                         :: "r"(dst), "l"(g) : "memory");
        }
    }
}

// EPI: 0 = fp32 (+bias), 2 = fp16 (*scale, +bias)
template<bool ATR, bool BTR, int EPI, bool SEG>
__global__ __launch_bounds__(128, 2)
void mma_gemm(const fp16* __restrict__ A_, long lda, long bsA, unsigned zmA,
              const fp16* __restrict__ B0, const fp16* __restrict__ B1,
              const fp16* __restrict__ B2, long ldb, long bsB,
              float* __restrict__ Cf, fp16* __restrict__ Ch,
              long ldc, long bsC,
              const float* __restrict__ bias, const float* __restrict__ scale, int K)
{
    extern __shared__ char smem[];
    const uint32_t sb = smem_u32(smem);
    const int tid = threadIdx.x;
    const int wid = tid >> 5, lane = tid & 31;
    const int warp_m = wid & 1, warp_n = wid >> 1;   // 2 x 2
    const long m0 = (long)blockIdx.y * 128, n0 = (long)blockIdx.x * 128;
    const long zA = (long)(blockIdx.z & zmA) * bsA, zB = (long)blockIdx.z * bsB;
    A_ += zA;
    B0 += zB;  B1 += zB;  B2 += zB;

    float d[4][8][4];
    #pragma unroll
    for (int i = 0; i < 4; i++)
        #pragma unroll
        for (int j = 0; j < 8; j++)
            #pragma unroll
            for (int q = 0; q < 4; q++) d[i][j][q] = 0.f;

    const int NC = K >> 5;

    auto loadstage = [&](int i) {
        const int s = i & (STAGES - 1);
        const long k0 = (long)i * 32;
        const fp16* Bp = B0;
        long kb = k0;
        if (SEG) {
            int seg = (int)(k0 >> 9);
            kb = k0 & 511;
            Bp = (seg == 0) ? B0 : (seg == 1) ? B1 : B2;
        }
        uint32_t tb = sb + (uint32_t)s * STGB;
        load_tile<ATR>(tb,         A_, m0, lda, k0, tid);
        load_tile<BTR>(tb + TILEB, Bp, n0, ldb, kb, tid);
        asm volatile("cp.async.commit_group;" ::: "memory");
    };

    for (int i = 0; i < STAGES - 1; i++) {
        if (i < NC) loadstage(i);
        else        asm volatile("cp.async.commit_group;" ::: "memory");
    }

    for (int i = 0; i < NC; i++) {
        asm volatile("cp.async.wait_group %0;" :: "n"(STAGES - 2) : "memory");
        __syncthreads();
        if (i + STAGES - 1 < NC) loadstage(i + STAGES - 1);
        else                     asm volatile("cp.async.commit_group;" ::: "memory");

        const int s = i & (STAGES - 1);
        const uint32_t bA = sb + (uint32_t)s * STGB;
        const uint32_t bB = bA + TILEB;

        #pragma unroll
        for (int ks = 0; ks < 2; ks++) {
            uint32_t ah[4][4];
            #pragma unroll
            for (int tm = 0; tm < 4; tm++) {
                if (!ATR) {
                    int row = warp_m * 64 + tm * 16 + (lane & 15);
                    int ch  = ks * 2 + (lane >> 4);
                    uint32_t off = (uint32_t)(row * 64 + ((ch ^ ((row >> 1) & 3)) << 4));
                    ldsm_x4(ah[tm], bA + off);
                } else {
                    int krow = ks * 16 + (lane & 7) + ((lane >> 4) << 3);
                    int mch  = ((warp_m * 64 + tm * 16) >> 3) + ((lane >> 3) & 1);
                    uint32_t off = (uint32_t)(krow * 256 + ((mch ^ (krow & 7)) << 4));
                    ldsm_x4_t(ah[tm], bA + off);
                }
            }
            uint32_t bh[4][4];   // per tp: {b0,b1} for tn=2tp, {b2,b3} for tn=2tp+1
            #pragma unroll
            for (int tp = 0; tp < 4; tp++) {
                if (!BTR) {
                    int row = warp_n * 64 + tp * 16 + (lane & 7) + ((lane >> 4) << 3);
                    int ch  = ks * 2 + ((lane >> 3) & 1);
                    uint32_t off = (uint32_t)(row * 64 + ((ch ^ ((row >> 1) & 3)) << 4));
                    ldsm_x4(bh[tp], bB + off);
                } else {
                    int krow = ks * 16 + (lane & 7) + ((lane >> 3) & 1) * 8;
                    int nch  = ((warp_n * 64 + tp * 16) >> 3) + (lane >> 4);
                    uint32_t off = (uint32_t)(krow * 256 + ((nch ^ (krow & 7)) << 4));
                    ldsm_x4_t(bh[tp], bB + off);
                }
            }
            #pragma unroll
            for (int tm = 0; tm < 4; tm++)
                #pragma unroll
                for (int tp = 0; tp < 4; tp++) {
                    mma16816(d[tm][tp * 2 + 0], ah[tm], bh[tp] + 0);
                    mma16816(d[tm][tp * 2 + 1], ah[tm], bh[tp] + 2);
                }
        }
        __syncthreads();
    }

    if (EPI == 0) {
        float* Cb = Cf + (long)blockIdx.z * bsC;
        #pragma unroll
        for (int tm = 0; tm < 4; tm++) {
            const long m = m0 + warp_m * 64 + tm * 16 + (lane >> 2);
            const float bs0 = bias ? bias[m]     : 0.f;
            const float bs1 = bias ? bias[m + 8] : 0.f;
            #pragma unroll
            for (int tn = 0; tn < 8; tn++) {
                const long n = n0 + warp_n * 64 + tn * 8 + (lane & 3) * 2;
                *(float2*)&Cb[m * ldc + n] =
                    make_float2(d[tm][tn][0] + bs0, d[tm][tn][1] + bs0);
                *(float2*)&Cb[(m + 8) * ldc + n] =
                    make_float2(d[tm][tn][2] + bs1, d[tm][tn][3] + bs1);
            }
        }
    } else {
        fp16* Hb = Ch + (long)blockIdx.z * bsC;
        const float sc = scale ? *scale : 1.0f;
        #pragma unroll
        for (int tm = 0; tm < 4; tm++) {
            const long m = m0 + warp_m * 64 + tm * 16 + (lane >> 2);
            const float bs0 = bias ? bias[m]     : 0.f;
            const float bs1 = bias ? bias[m + 8] : 0.f;
            #pragma unroll
            for (int tn = 0; tn < 8; tn++) {
                const long n = n0 + warp_n * 64 + tn * 8 + (lane & 3) * 2;
                __half2 p0 = __floats2half2_rn(d[tm][tn][0] * sc + bs0,
                                               d[tm][tn][1] * sc + bs0);
                __half2 p1 = __floats2half2_rn(d[tm][tn][2] * sc + bs1,
                                               d[tm][tn][3] * sc + bs1);
                *(__half2*)&Hb[m * ldc + n]       = p0;
                *(__half2*)&Hb[(m + 8) * ldc + n] = p1;
            }
        }
    }
}

// ---------------- Winograd F(4x4,3x3) transforms -------------------------------
__global__ __launch_bounds__(256)
void wino_input4(const float* __restrict__ x, fp16* __restrict__ Vh) {
    long gid = (long)blockIdx.x * 256 + threadIdx.x;
    int tile = (int)(gid & (NT4 - 1));
    long r = gid >> 6;
    int ci = (int)(r & (CC - 1));
    int b  = (int)(r >> 9);
    int ty = tile >> 3, tx = tile & 7;
    const float* xb = x + ((long)b * CC + ci) * NN;
    const int h0 = 4 * ty - 1, w0 = 4 * tx - 1;

    float dd[6][6];
    #pragma unroll
    for (int i = 0; i < 6; i++) {
        int ih = h0 + i;
        #pragma unroll
        for (int j = 0; j < 6; j++) {
            int iw = w0 + j;
            dd[i][j] = ((unsigned)ih < HH && (unsigned)iw < WW) ? xb[ih * WW + iw] : 0.f;
        }
    }
    float t[6][6];
    #pragma unroll
    for (int j = 0; j < 6; j++) {
        t[0][j] =  4.f*dd[0][j] - 5.f*dd[2][j] + dd[4][j];
        t[1][j] = -4.f*dd[1][j] - 4.f*dd[2][j] + dd[3][j] + dd[4][j];
        t[2][j] =  4.f*dd[1][j] - 4.f*dd[2][j] - dd[3][j] + dd[4][j];
        t[3][j] = -2.f*dd[1][j] -     dd[2][j] + 2.f*dd[3][j] + dd[4][j];
        t[4][j] =  2.f*dd[1][j] -     dd[2][j] - 2.f*dd[3][j] + dd[4][j];
        t[5][j] =  4.f*dd[1][j] - 5.f*dd[3][j] + dd[5][j];
    }
    const long tcol = (long)b * NT4 + tile;
    #pragma unroll
    for (int i = 0; i < 6; i++) {
        float V0 =  4.f*t[i][0] - 5.f*t[i][2] + t[i][4];
        float V1 = -4.f*t[i][1] - 4.f*t[i][2] + t[i][3] + t[i][4];
        float V2 =  4.f*t[i][1] - 4.f*t[i][2] - t[i][3] + t[i][4];
        float V3 = -2.f*t[i][1] -     t[i][2] + 2.f*t[i][3] + t[i][4];
        float V4 =  2.f*t[i][1] -     t[i][2] - 2.f*t[i][3] + t[i][4];
        float V5 =  4.f*t[i][1] - 5.f*t[i][3] + t[i][5];
        float Vv[6] = {V0, V1, V2, V3, V4, V5};
        #pragma unroll
        for (int j = 0; j < 6; j++)
            Vh[((long)(i * 6 + j) * CC + ci) * TCOLS + tcol] = __float2half_rn(Vv[j]);
    }
}

__global__ __launch_bounds__(256)
void wino_weight4(const float* __restrict__ w, fp16* __restrict__ Uh, int co_base) {
    int gid = blockIdx.x * 256 + threadIdx.x;   // co*512 + ci
    int ci = gid & (CC - 1), co = gid >> 9;
    const float* g = w + (long)gid * 9;
    float t2[6][3];
    #pragma unroll
    for (int j = 0; j < 3; j++) {
        float g0 = g[0 * 3 + j], g1 = g[1 * 3 + j], g2 = g[2 * 3 + j];
        t2[0][j] = 0.25f * g0;
        t2[1][j] = (-g0 - g1 - g2) * (1.f / 6.f);
        t2[2][j] = (-g0 + g1 - g2) * (1.f / 6.f);
        t2[3][j] = g0 * (1.f / 24.f) + g1 * (1.f / 12.f) + g2 * (1.f / 6.f);
        t2[4][j] = g0 * (1.f / 24.f) - g1 * (1.f / 12.f) + g2 * (1.f / 6.f);
        t2[5][j] = g2;
    }
    #pragma unroll
    for (int i = 0; i < 6; i++) {
        float a = t2[i][0], bq = t2[i][1], c = t2[i][2];
        float Uv[6];
        Uv[0] = 0.25f * a;
        Uv[1] = (-a - bq - c) * (1.f / 6.f);
        Uv[2] = (-a + bq - c) * (1.f / 6.f);
        Uv[3] = a * (1.f / 24.f) + bq * (1.f / 12.f) + c * (1.f / 6.f);
        Uv[4] = a * (1.f / 24.f) - bq * (1.f / 12.f) + c * (1.f / 6.f);
        Uv[5] = c;
        #pragma unroll
        for (int j = 0; j < 6; j++)
            Uh[((long)(i * 6 + j) * C3 + co_base + co) * CC + ci] = __float2half_rn(Uv[j]);
    }
}

// Output transform; Mw fp16 [tap][co3][tcol]
__global__ __launch_bounds__(256)
void wino_output4(const fp16* __restrict__ M,
                  const float* __restrict__ b1, const float* __restrict__ b2,
                  const float* __restrict__ b3,
                  fp16* __restrict__ Ah, fp16* __restrict__ Bmh,
                  fp16* __restrict__ Dh) {
    long gid = (long)blockIdx.x * 256 + threadIdx.x;
    int tile = (int)(gid & (NT4 - 1));
    long r = gid >> 6;
    int co3 = (int)(r % C3);
    int b   = (int)(r / C3);
    const long tcol = (long)b * NT4 + tile;
    const int seg = co3 >> 9, co = co3 & (CC - 1);

    float m[6][6];
    #pragma unroll
    for (int c = 0; c < 36; c++)
        m[c / 6][c % 6] = __half2float(M[((long)c * C3 + co3) * TCOLS + tcol]);

    float s[4][6];
    #pragma unroll
    for (int j = 0; j < 6; j++) {
        s[0][j] = m[0][j] + m[1][j] + m[2][j] + m[3][j] + m[4][j];
        s[1][j] = m[1][j] - m[2][j] + 2.f * (m[3][j] - m[4][j]);
        s[2][j] = m[1][j] + m[2][j] + 4.f * (m[3][j] + m[4][j]);
        s[3][j] = m[1][j] - m[2][j] + 8.f * (m[3][j] - m[4][j]) + m[5][j];
    }
    const float bs = (seg == 0) ? b1[co] : (seg == 1) ? b2[co] : b3[co];
    fp16* O = (seg == 0) ? Ah : (seg == 1) ? Bmh : Dh;
    int ty = tile >> 3, tx = tile & 7;
    long base = ((long)b * CC + co) * NN + (4 * ty) * WW + 4 * tx;
    #pragma unroll
    for (int i = 0; i < 4; i++) {
        float Y[4];
        Y[0] = s[i][0] + s[i][1] + s[i][2] + s[i][3] + s[i][4] + bs;
        Y[1] = s[i][1] - s[i][2] + 2.f * (s[i][3] - s[i][4]) + bs;
        Y[2] = s[i][1] + s[i][2] + 4.f * (s[i][3] + s[i][4]) + bs;
        Y[3] = s[i][1] - s[i][2] + 8.f * (s[i][3] - s[i][4]) + s[i][5] + bs;
        long ro = base + i * WW;
        #pragma unroll
        for (int j = 0; j < 4; j++)
            O[ro + j] = __float2half_rn(Y[j]);
    }
}

// ---------------- fp32 -> fp16 convert ------------------------------------------
__global__ void cvt_kernel(const float* __restrict__ in, fp16* __restrict__ oh) {
    long g = (long)blockIdx.x * 256 + threadIdx.x;
    oh[g] = __float2half_rn(in[g]);
}

// ---------------- softmax -------------------------------------------------------
__device__ __forceinline__ float warpMax(float v) {
    #pragma unroll
    for (int o = 16; o > 0; o >>= 1) v = fmaxf(v, __shfl_xor_sync(0xffffffffu, v, o));
    return v;
}
__device__ __forceinline__ float warpSum(float v) {
    #pragma unroll
    for (int o = 16; o > 0; o >>= 1) v += __shfl_xor_sync(0xffffffffu, v, o);
    return v;
}

template<int LEN>
__global__ __launch_bounds__(256)
void softmax_fp16(const float* __restrict__ buf, fp16* __restrict__ oh) {
    constexpr int V = LEN / 256;
    const long base = (long)blockIdx.x * LEN;
    const float* row = buf + base;
    const int tid = threadIdx.x, lane = tid & 31, wid = tid >> 5;
    __shared__ float sred[8];
    float v[V];
    float mx = -3.0e38f;
    #pragma unroll
    for (int j = 0; j < V; j++) { v[j] = row[tid + j * 256]; mx = fmaxf(mx, v[j]); }
    mx = warpMax(mx);
    if (lane == 0) sred[wid] = mx;
    __syncthreads();
    if (tid == 0) {
        float m = sred[0];
        #pragma unroll
        for (int i = 1; i < 8; i++) m = fmaxf(m, sred[i]);
        sred[0] = m;
    }
    __syncthreads();
    mx = sred[0];
    __syncthreads();
    float s = 0.f;
    #pragma unroll
    for (int j = 0; j < V; j++) { v[j] = __expf(v[j] - mx); s += v[j]; }
    s = warpSum(s);
    if (lane == 0) sred[wid] = s;
    __syncthreads();
    if (tid == 0) {
        float m = 0.f;
        #pragma unroll
        for (int i = 0; i < 8; i++) m += sred[i];
        sred[0] = m;
    }
    __syncthreads();
    const float inv = 1.0f / sred[0];
    #pragma unroll
    for (int j = 0; j < V; j++)
        oh[base + tid + j * 256] = __float2half_rn(v[j] * inv);
}

// ---------------- launch --------------------------------------------------------
extern "C" void kernel_launch(void* const* d_in, const int* in_sizes, int n_in,
                              void* d_out, int out_size) {
    const float* x     = (const float*)d_in[0];
    const float* w1    = (const float*)d_in[1];
    const float* b1    = (const float*)d_in[2];
    const float* w2    = (const float*)d_in[3];
    const float* b2    = (const float*)d_in[4];
    const float* w3    = (const float*)d_in[5];
    const float* b3    = (const float*)d_in[6];
    const float* alpha = (const float*)d_in[7];
    const float* beta  = (const float*)d_in[8];
    const float* wf    = (const float*)d_in[9];
    const float* bf    = (const float*)d_in[10];
    float* out = (float*)d_out;

    cudaFuncSetAttribute(mma_gemm<false,true, 2,false>, cudaFuncAttributeMaxDynamicSharedMemorySize, GEMM_SMEM);
    cudaFuncSetAttribute(mma_gemm<true, true, 0,false>, cudaFuncAttributeMaxDynamicSharedMemorySize, GEMM_SMEM);
    cudaFuncSetAttribute(mma_gemm<false,false,2,false>, cudaFuncAttributeMaxDynamicSharedMemorySize, GEMM_SMEM);
    cudaFuncSetAttribute(mma_gemm<false,false,0,false>, cudaFuncAttributeMaxDynamicSharedMemorySize, GEMM_SMEM);
    cudaFuncSetAttribute(mma_gemm<true, true, 2,false>, cudaFuncAttributeMaxDynamicSharedMemorySize, GEMM_SMEM);
    cudaFuncSetAttribute(mma_gemm<false,true, 0,true >, cudaFuncAttributeMaxDynamicSharedMemorySize, GEMM_SMEM);

    fp16 *Vh, *Uh, *Mw16, *wfh, *Ah, *Bmh, *Dh, *xh, *Mh, *Sh, *spath, *chanh;
    float *Mb, *Sb;
    cudaGetSymbolAddress((void**)&Vh, g_Vh);
    cudaGetSymbolAddress((void**)&Uh, g_Uh);
    cudaGetSymbolAddress((void**)&Mw16, g_Mw);
    cudaGetSymbolAddress((void**)&wfh, g_wfh);
    cudaGetSymbolAddress((void**)&Ah,  g_Ah);
    cudaGetSymbolAddress((void**)&Bmh, g_Bmh);
    cudaGetSymbolAddress((void**)&Dh,  g_Dh);
    cudaGetSymbolAddress((void**)&xh,  g_xh);
    cudaGetSymbolAddress((void**)&Mb,  g_M);
    cudaGetSymbolAddress((void**)&Mh,  g_Mh);
    cudaGetSymbolAddress((void**)&Sb,  g_S);
    cudaGetSymbolAddress((void**)&Sh,  g_Sh);
    cudaGetSymbolAddress((void**)&spath, g_spath);
    cudaGetSymbolAddress((void**)&chanh, g_chanh);

    const long sX  = (long)CC * NN;
    const long sM  = (long)NN * NN;
    const long sS  = (long)CC * CC;
    const long sVt = (long)CC * TCOLS;   // per-tap stride of V
    const long sUt = (long)C3 * CC;      // per-tap stride of merged U
    const long sMwt = (long)C3 * TCOLS;  // per-tap stride of Mw
    const unsigned ZALL = 0xFFFFFFFFu;

    // 1) transforms + converts
    wino_input4<<<(unsigned)((long)BB * CC * NT4 / 256), 256>>>(x, Vh);
    wino_weight4<<<CC * CC / 256, 256>>>(w1, Uh, 0);
    wino_weight4<<<CC * CC / 256, 256>>>(w2, Uh, CC);
    wino_weight4<<<CC * CC / 256, 256>>>(w3, Uh, 2 * CC);
    cvt_kernel<<<CC * C3 / 256, 256>>>(wf, wfh);
    cvt_kernel<<<(unsigned)((long)BB * sX / 256), 256>>>(x, xh);

    // 2) merged 3-conv Winograd GEMM: per tap t: Mw[t] = U[t] . V[t]  (fp16 out)
    {
        dim3 g(TCOLS / 128, C3 / 128, TAPS);
        mma_gemm<false,true,2,false><<<g, 128, GEMM_SMEM>>>(
            Uh, CC, sUt, ZALL, Vh, Vh, Vh, TCOLS, sVt,
            nullptr, Mw16, TCOLS, sMwt, nullptr, nullptr, CC);
        wino_output4<<<(unsigned)((long)BB * C3 * NT4 / 256), 256>>>(
            Mw16, b1, b2, b3, Ah, Bmh, Dh);
    }

    // 3) M[n][m] = sum_c A[c][n]*Bm[c][m]
    {
        dim3 g(NN / 128, NN / 128, BB);
        mma_gemm<true,true,0,false><<<g, 128, GEMM_SMEM>>>(
            Ah, NN, sX, ZALL, Bmh, Bmh, Bmh, NN, sX,
            Mb, nullptr, NN, sM, nullptr, nullptr, CC);
    }

    // 4) softmax rows of M -> Mh
    softmax_fp16<NN><<<BB * NN, 256>>>(Mb, Mh);

    // 5) spat[c][n] = sum_m D[c][m]*Msm[n][m]   (epi: alpha -> fp16)
    {
        dim3 g(NN / 128, CC / 128, BB);
        mma_gemm<false,false,2,false><<<g, 128, GEMM_SMEM>>>(
            Dh, NN, sX, ZALL, Mh, Mh, Mh, NN, sM,
            nullptr, spath, NN, sX, nullptr, alpha, NN);
    }

    // 6) S[c][d] = sum_n x[c][n]*x[d][n]
    {
        dim3 g(CC / 128, CC / 128, BB);
        mma_gemm<false,false,0,false><<<g, 128, GEMM_SMEM>>>(
            xh, NN, sX, ZALL, xh, xh, xh, NN, sX,
            Sb, nullptr, CC, sS, nullptr, nullptr, NN);
    }

    // 7) softmax rows of S -> Sh
    softmax_fp16<CC><<<BB * CC, 256>>>(Sb, Sh);

    // 8) chan[c][n] = sum_d Ssm[d][c]*x[d][n]  (epi: beta -> fp16)
    {
        dim3 g(NN / 128, CC / 128, BB);
        mma_gemm<true,true,2,false><<<g, 128, GEMM_SMEM>>>(
            Sh, CC, sS, ZALL, xh, xh, xh, NN, sX,
            nullptr, chanh, NN, sX, nullptr, beta, CC);
    }

    // 9) fuse: out[c][n] = bf[c] + wf . [x; a*spat; b*chan]
    {
        dim3 g(NN / 128, CC / 128, BB);
        mma_gemm<false,true,0,true><<<g, 128, GEMM_SMEM>>>(
            wfh, C3, 0, ZALL, xh, spath, chanh, NN, sX,
            out, nullptr, NN, sX, bf, nullptr, C3);
    }
}

// round 13
// speedup vs baseline: 21.7193x; 1.1153x over previous
#include <cuda_runtime.h>
#include <cuda_fp16.h>
#include <cstdint>

#define BB 16
#define CC 512
#define HH 32
#define WW 32
#define NN 1024
#define C3 1536
#define NT4 64           // F(4x4,3x3) tiles per image (8x8)
#define TCOLS 1024       // BB * NT4 tile-columns
#define TAPS 36

typedef __half fp16;

// ---------------- scratch (device globals) -----------------------------------
__device__ fp16 g_Vh[(size_t)TAPS * CC * TCOLS];
__device__ fp16 g_Uh[(size_t)TAPS * C3 * CC];          // merged U (3 convs)
__device__ fp16 g_Mw[(size_t)TAPS * C3 * TCOLS];       // conv GEMM out (fp16)
__device__ fp16 g_wfh[CC * C3];
__device__ fp16 g_Ah[(size_t)BB * CC * NN];
__device__ fp16 g_Bmh[(size_t)BB * CC * NN];
__device__ fp16 g_Dh[(size_t)BB * CC * NN];
__device__ fp16 g_xh[(size_t)BB * CC * NN];
__device__ float g_M[(size_t)BB * NN * NN];
__device__ fp16 g_Mh[(size_t)BB * NN * NN];
__device__ float g_S[(size_t)BB * CC * CC];
__device__ fp16 g_Sh[(size_t)BB * CC * CC];
__device__ fp16 g_spath[(size_t)BB * CC * NN];
__device__ fp16 g_chanh[(size_t)BB * CC * NN];

// ---------------- helpers ------------------------------------------------------
__device__ __forceinline__ uint32_t smem_u32(const void* p) {
    uint32_t a;
    asm("{ .reg .u64 t; cvta.to.shared.u64 t, %1; cvt.u32.u64 %0, t; }"
        : "=r"(a) : "l"(p));
    return a;
}
__device__ __forceinline__ void ldsm_x4(uint32_t* r, uint32_t addr) {
    asm volatile("ldmatrix.sync.aligned.m8n8.x4.shared.b16 {%0,%1,%2,%3}, [%4];"
                 : "=r"(r[0]), "=r"(r[1]), "=r"(r[2]), "=r"(r[3]) : "r"(addr));
}
__device__ __forceinline__ void ldsm_x4_t(uint32_t* r, uint32_t addr) {
    asm volatile("ldmatrix.sync.aligned.m8n8.x4.trans.shared.b16 {%0,%1,%2,%3}, [%4];"
                 : "=r"(r[0]), "=r"(r[1]), "=r"(r[2]), "=r"(r[3]) : "r"(addr));
}
__device__ __forceinline__ void mma16816(float* d, const uint32_t* a, const uint32_t* b) {
    asm volatile("mma.sync.aligned.m16n8k16.row.col.f32.f16.f16.f32 "
                 "{%0,%1,%2,%3}, {%4,%5,%6,%7}, {%8,%9}, {%0,%1,%2,%3};"
                 : "+f"(d[0]), "+f"(d[1]), "+f"(d[2]), "+f"(d[3])
                 : "r"(a[0]), "r"(a[1]), "r"(a[2]), "r"(a[3]), "r"(b[0]), "r"(b[1]));
}

// ---------------- GEMM ----------------------------------------------------------
// Block tile 128x128, BK=32, 128 threads (4 warps 2x2), warp tile 64x64.
// Two CTAs co-resident per SM. Tiles 8 KB each.
#define TILEB 8192
#define STGB  (2 * TILEB)                // 16 KB
#define STAGES 4
#define GEMM_SMEM (STAGES * STGB)        // 64 KB

template<bool TR>
__device__ __forceinline__ void load_tile(uint32_t tb, const fp16* __restrict__ S,
                                          long rowbase, long ld, long k0, int tid) {
    if (!TR) {
        #pragma unroll
        for (int p = 0; p < 4; p++) {
            int row = (tid >> 2) + p * 32;     // 128 rows
            int ch  = tid & 3;
            const void* g = (const void*)(S + (rowbase + row) * ld + k0 + ch * 8);
            uint32_t dst = tb + (uint32_t)(row * 64 + ((ch ^ ((row >> 1) & 3)) << 4));
            asm volatile("cp.async.cg.shared.global [%0], [%1], 16;"
                         :: "r"(dst), "l"(g) : "memory");
        }
    } else {
        #pragma unroll
        for (int p = 0; p < 4; p++) {
            int row = (tid >> 4) + p * 8;      // krow 0..31
            int ch  = tid & 15;                // 16 chunks (256B row)
            const void* g = (const void*)(S + (k0 + row) * ld + rowbase + ch * 8);
            uint32_t dst = tb + (uint32_t)(row * 256 + ((ch ^ (row & 7)) << 4));
            asm volatile("cp.async.cg.shared.global [%0], [%1], 16;"
                         :: "r"(dst), "l"(g) : "memory");
        }
    }
}

// EPI: 0 = fp32 (+bias), 2 = fp16 (*scale, +bias)
template<bool ATR, bool BTR, int EPI, bool SEG>
__global__ __launch_bounds__(128, 2)
void mma_gemm(const fp16* __restrict__ A_, long lda, long bsA, unsigned zmA,
              const fp16* __restrict__ B0, const fp16* __restrict__ B1,
              const fp16* __restrict__ B2, long ldb, long bsB,
              float* __restrict__ Cf, fp16* __restrict__ Ch,
              long ldc, long bsC,
              const float* __restrict__ bias, const float* __restrict__ scale, int K)
{
    extern __shared__ char smem[];
    const uint32_t sb = smem_u32(smem);
    const int tid = threadIdx.x;
    const int wid = tid >> 5, lane = tid & 31;
    const int warp_m = wid & 1, warp_n = wid >> 1;   // 2 x 2
    const long m0 = (long)blockIdx.y * 128, n0 = (long)blockIdx.x * 128;
    const long zA = (long)(blockIdx.z & zmA) * bsA, zB = (long)blockIdx.z * bsB;
    A_ += zA;
    B0 += zB;  B1 += zB;  B2 += zB;

    float d[4][8][4];
    #pragma unroll
    for (int i = 0; i < 4; i++)
        #pragma unroll
        for (int j = 0; j < 8; j++)
            #pragma unroll
            for (int q = 0; q < 4; q++) d[i][j][q] = 0.f;

    const int NC = K >> 5;

    auto loadstage = [&](int i) {
        const int s = i & (STAGES - 1);
        const long k0 = (long)i * 32;
        const fp16* Bp = B0;
        long kb = k0;
        if (SEG) {
            int seg = (int)(k0 >> 9);
            kb = k0 & 511;
            Bp = (seg == 0) ? B0 : (seg == 1) ? B1 : B2;
        }
        uint32_t tb = sb + (uint32_t)s * STGB;
        load_tile<ATR>(tb,         A_, m0, lda, k0, tid);
        load_tile<BTR>(tb + TILEB, Bp, n0, ldb, kb, tid);
        asm volatile("cp.async.commit_group;" ::: "memory");
    };

    for (int i = 0; i < STAGES - 1; i++) {
        if (i < NC) loadstage(i);
        else        asm volatile("cp.async.commit_group;" ::: "memory");
    }

    for (int i = 0; i < NC; i++) {
        asm volatile("cp.async.wait_group %0;" :: "n"(STAGES - 2) : "memory");
        __syncthreads();
        if (i + STAGES - 1 < NC) loadstage(i + STAGES - 1);
        else                     asm volatile("cp.async.commit_group;" ::: "memory");

        const int s = i & (STAGES - 1);
        const uint32_t bA = sb + (uint32_t)s * STGB;
        const uint32_t bB = bA + TILEB;

        #pragma unroll
        for (int ks = 0; ks < 2; ks++) {
            uint32_t ah[4][4];
            #pragma unroll
            for (int tm = 0; tm < 4; tm++) {
                if (!ATR) {
                    int row = warp_m * 64 + tm * 16 + (lane & 15);
                    int ch  = ks * 2 + (lane >> 4);
                    uint32_t off = (uint32_t)(row * 64 + ((ch ^ ((row >> 1) & 3)) << 4));
                    ldsm_x4(ah[tm], bA + off);
                } else {
                    int krow = ks * 16 + (lane & 7) + ((lane >> 4) << 3);
                    int mch  = ((warp_m * 64 + tm * 16) >> 3) + ((lane >> 3) & 1);
                    uint32_t off = (uint32_t)(krow * 256 + ((mch ^ (krow & 7)) << 4));
                    ldsm_x4_t(ah[tm], bA + off);
                }
            }
            uint32_t bh[4][4];
            #pragma unroll
            for (int tp = 0; tp < 4; tp++) {
                if (!BTR) {
                    int row = warp_n * 64 + tp * 16 + (lane & 7) + ((lane >> 4) << 3);
                    int ch  = ks * 2 + ((lane >> 3) & 1);
                    uint32_t off = (uint32_t)(row * 64 + ((ch ^ ((row >> 1) & 3)) << 4));
                    ldsm_x4(bh[tp], bB + off);
                } else {
                    int krow = ks * 16 + (lane & 7) + ((lane >> 3) & 1) * 8;
                    int nch  = ((warp_n * 64 + tp * 16) >> 3) + (lane >> 4);
                    uint32_t off = (uint32_t)(krow * 256 + ((nch ^ (krow & 7)) << 4));
                    ldsm_x4_t(bh[tp], bB + off);
                }
            }
            #pragma unroll
            for (int tm = 0; tm < 4; tm++)
                #pragma unroll
                for (int tp = 0; tp < 4; tp++) {
                    mma16816(d[tm][tp * 2 + 0], ah[tm], bh[tp] + 0);
                    mma16816(d[tm][tp * 2 + 1], ah[tm], bh[tp] + 2);
                }
        }
        __syncthreads();
    }

    if (EPI == 0) {
        float* Cb = Cf + (long)blockIdx.z * bsC;
        #pragma unroll
        for (int tm = 0; tm < 4; tm++) {
            const long m = m0 + warp_m * 64 + tm * 16 + (lane >> 2);
            const float bs0 = bias ? bias[m]     : 0.f;
            const float bs1 = bias ? bias[m + 8] : 0.f;
            #pragma unroll
            for (int tn = 0; tn < 8; tn++) {
                const long n = n0 + warp_n * 64 + tn * 8 + (lane & 3) * 2;
                *(float2*)&Cb[m * ldc + n] =
                    make_float2(d[tm][tn][0] + bs0, d[tm][tn][1] + bs0);
                *(float2*)&Cb[(m + 8) * ldc + n] =
                    make_float2(d[tm][tn][2] + bs1, d[tm][tn][3] + bs1);
            }
        }
    } else {
        fp16* Hb = Ch + (long)blockIdx.z * bsC;
        const float sc = scale ? *scale : 1.0f;
        #pragma unroll
        for (int tm = 0; tm < 4; tm++) {
            const long m = m0 + warp_m * 64 + tm * 16 + (lane >> 2);
            const float bs0 = bias ? bias[m]     : 0.f;
            const float bs1 = bias ? bias[m + 8] : 0.f;
            #pragma unroll
            for (int tn = 0; tn < 8; tn++) {
                const long n = n0 + warp_n * 64 + tn * 8 + (lane & 3) * 2;
                __half2 p0 = __floats2half2_rn(d[tm][tn][0] * sc + bs0,
                                               d[tm][tn][1] * sc + bs0);
                __half2 p1 = __floats2half2_rn(d[tm][tn][2] * sc + bs1,
                                               d[tm][tn][3] * sc + bs1);
                *(__half2*)&Hb[m * ldc + n]       = p0;
                *(__half2*)&Hb[(m + 8) * ldc + n] = p1;
            }
        }
    }
}

// ---------------- Winograd F(4x4,3x3) transforms -------------------------------
// Input transform + xh conversion (center 4x4 of the 6x6 patch = this tile's x)
__global__ __launch_bounds__(256)
void wino_input4(const float* __restrict__ x, fp16* __restrict__ Vh,
                 fp16* __restrict__ xh) {
    long gid = (long)blockIdx.x * 256 + threadIdx.x;
    int tile = (int)(gid & (NT4 - 1));
    long r = gid >> 6;
    int ci = (int)(r & (CC - 1));
    int b  = (int)(r >> 9);
    int ty = tile >> 3, tx = tile & 7;
    const long xoff = ((long)b * CC + ci) * NN;
    const float* xb = x + xoff;
    const int h0 = 4 * ty - 1, w0 = 4 * tx - 1;

    float dd[6][6];
    #pragma unroll
    for (int i = 0; i < 6; i++) {
        int ih = h0 + i;
        #pragma unroll
        for (int j = 0; j < 6; j++) {
            int iw = w0 + j;
            dd[i][j] = ((unsigned)ih < HH && (unsigned)iw < WW) ? xb[ih * WW + iw] : 0.f;
        }
    }
    // write xh for the 4x4 center (exactly covers x across tiles)
    {
        fp16* xo = xh + xoff + (4 * ty) * WW + 4 * tx;
        #pragma unroll
        for (int i = 0; i < 4; i++) {
            __half2 p0 = __floats2half2_rn(dd[i + 1][1], dd[i + 1][2]);
            __half2 p1 = __floats2half2_rn(dd[i + 1][3], dd[i + 1][4]);
            *(__half2*)&xo[i * WW]     = p0;
            *(__half2*)&xo[i * WW + 2] = p1;
        }
    }
    float t[6][6];
    #pragma unroll
    for (int j = 0; j < 6; j++) {
        t[0][j] =  4.f*dd[0][j] - 5.f*dd[2][j] + dd[4][j];
        t[1][j] = -4.f*dd[1][j] - 4.f*dd[2][j] + dd[3][j] + dd[4][j];
        t[2][j] =  4.f*dd[1][j] - 4.f*dd[2][j] - dd[3][j] + dd[4][j];
        t[3][j] = -2.f*dd[1][j] -     dd[2][j] + 2.f*dd[3][j] + dd[4][j];
        t[4][j] =  2.f*dd[1][j] -     dd[2][j] - 2.f*dd[3][j] + dd[4][j];
        t[5][j] =  4.f*dd[1][j] - 5.f*dd[3][j] + dd[5][j];
    }
    const long tcol = (long)b * NT4 + tile;
    #pragma unroll
    for (int i = 0; i < 6; i++) {
        float V0 =  4.f*t[i][0] - 5.f*t[i][2] + t[i][4];
        float V1 = -4.f*t[i][1] - 4.f*t[i][2] + t[i][3] + t[i][4];
        float V2 =  4.f*t[i][1] - 4.f*t[i][2] - t[i][3] + t[i][4];
        float V3 = -2.f*t[i][1] -     t[i][2] + 2.f*t[i][3] + t[i][4];
        float V4 =  2.f*t[i][1] -     t[i][2] - 2.f*t[i][3] + t[i][4];
        float V5 =  4.f*t[i][1] - 5.f*t[i][3] + t[i][5];
        float Vv[6] = {V0, V1, V2, V3, V4, V5};
        #pragma unroll
        for (int j = 0; j < 6; j++)
            Vh[((long)(i * 6 + j) * CC + ci) * TCOLS + tcol] = __float2half_rn(Vv[j]);
    }
}

// Merged weight transform for all 3 convs: blockIdx.y selects the conv.
__global__ __launch_bounds__(256)
void wino_weight4(const float* __restrict__ w1, const float* __restrict__ w2,
                  const float* __restrict__ w3, fp16* __restrict__ Uh) {
    const int conv = blockIdx.y;
    const float* w = (conv == 0) ? w1 : (conv == 1) ? w2 : w3;
    const int co_base = conv * CC;
    int gid = blockIdx.x * 256 + threadIdx.x;   // co*512 + ci
    int ci = gid & (CC - 1), co = gid >> 9;
    const float* g = w + (long)gid * 9;
    float t2[6][3];
    #pragma unroll
    for (int j = 0; j < 3; j++) {
        float g0 = g[0 * 3 + j], g1 = g[1 * 3 + j], g2 = g[2 * 3 + j];
        t2[0][j] = 0.25f * g0;
        t2[1][j] = (-g0 - g1 - g2) * (1.f / 6.f);
        t2[2][j] = (-g0 + g1 - g2) * (1.f / 6.f);
        t2[3][j] = g0 * (1.f / 24.f) + g1 * (1.f / 12.f) + g2 * (1.f / 6.f);
        t2[4][j] = g0 * (1.f / 24.f) - g1 * (1.f / 12.f) + g2 * (1.f / 6.f);
        t2[5][j] = g2;
    }
    #pragma unroll
    for (int i = 0; i < 6; i++) {
        float a = t2[i][0], bq = t2[i][1], c = t2[i][2];
        float Uv[6];
        Uv[0] = 0.25f * a;
        Uv[1] = (-a - bq - c) * (1.f / 6.f);
        Uv[2] = (-a + bq - c) * (1.f / 6.f);
        Uv[3] = a * (1.f / 24.f) + bq * (1.f / 12.f) + c * (1.f / 6.f);
        Uv[4] = a * (1.f / 24.f) - bq * (1.f / 12.f) + c * (1.f / 6.f);
        Uv[5] = c;
        #pragma unroll
        for (int j = 0; j < 6; j++)
            Uh[((long)(i * 6 + j) * C3 + co_base + co) * CC + ci] = __float2half_rn(Uv[j]);
    }
}

// Output transform; Mw fp16 [tap][co3][tcol]
__global__ __launch_bounds__(256)
void wino_output4(const fp16* __restrict__ M,
                  const float* __restrict__ b1, const float* __restrict__ b2,
                  const float* __restrict__ b3,
                  fp16* __restrict__ Ah, fp16* __restrict__ Bmh,
                  fp16* __restrict__ Dh) {
    long gid = (long)blockIdx.x * 256 + threadIdx.x;
    int tile = (int)(gid & (NT4 - 1));
    long r = gid >> 6;
    int co3 = (int)(r % C3);
    int b   = (int)(r / C3);
    const long tcol = (long)b * NT4 + tile;
    const int seg = co3 >> 9, co = co3 & (CC - 1);

    float m[6][6];
    #pragma unroll
    for (int c = 0; c < 36; c++)
        m[c / 6][c % 6] = __half2float(M[((long)c * C3 + co3) * TCOLS + tcol]);

    float s[4][6];
    #pragma unroll
    for (int j = 0; j < 6; j++) {
        s[0][j] = m[0][j] + m[1][j] + m[2][j] + m[3][j] + m[4][j];
        s[1][j] = m[1][j] - m[2][j] + 2.f * (m[3][j] - m[4][j]);
        s[2][j] = m[1][j] + m[2][j] + 4.f * (m[3][j] + m[4][j]);
        s[3][j] = m[1][j] - m[2][j] + 8.f * (m[3][j] - m[4][j]) + m[5][j];
    }
    const float bs = (seg == 0) ? b1[co] : (seg == 1) ? b2[co] : b3[co];
    fp16* O = (seg == 0) ? Ah : (seg == 1) ? Bmh : Dh;
    int ty = tile >> 3, tx = tile & 7;
    long base = ((long)b * CC + co) * NN + (4 * ty) * WW + 4 * tx;
    #pragma unroll
    for (int i = 0; i < 4; i++) {
        float Y[4];
        Y[0] = s[i][0] + s[i][1] + s[i][2] + s[i][3] + s[i][4] + bs;
        Y[1] = s[i][1] - s[i][2] + 2.f * (s[i][3] - s[i][4]) + bs;
        Y[2] = s[i][1] + s[i][2] + 4.f * (s[i][3] + s[i][4]) + bs;
        Y[3] = s[i][1] - s[i][2] + 8.f * (s[i][3] - s[i][4]) + s[i][5] + bs;
        long ro = base + i * WW;
        #pragma unroll
        for (int j = 0; j < 4; j++)
            O[ro + j] = __float2half_rn(Y[j]);
    }
}

// ---------------- fp32 -> fp16 convert ------------------------------------------
__global__ void cvt_kernel(const float* __restrict__ in, fp16* __restrict__ oh) {
    long g = (long)blockIdx.x * 256 + threadIdx.x;
    oh[g] = __float2half_rn(in[g]);
}

// ---------------- softmax -------------------------------------------------------
__device__ __forceinline__ float warpMax(float v) {
    #pragma unroll
    for (int o = 16; o > 0; o >>= 1) v = fmaxf(v, __shfl_xor_sync(0xffffffffu, v, o));
    return v;
}
__device__ __forceinline__ float warpSum(float v) {
    #pragma unroll
    for (int o = 16; o > 0; o >>= 1) v += __shfl_xor_sync(0xffffffffu, v, o);
    return v;
}

template<int LEN>
__global__ __launch_bounds__(256)
void softmax_fp16(const float* __restrict__ buf, fp16* __restrict__ oh) {
    constexpr int V = LEN / 256;
    const long base = (long)blockIdx.x * LEN;
    const float* row = buf + base;
    const int tid = threadIdx.x, lane = tid & 31, wid = tid >> 5;
    __shared__ float sred[8];
    float v[V];
    float mx = -3.0e38f;
    #pragma unroll
    for (int j = 0; j < V; j++) { v[j] = row[tid + j * 256]; mx = fmaxf(mx, v[j]); }
    mx = warpMax(mx);
    if (lane == 0) sred[wid] = mx;
    __syncthreads();
    if (tid == 0) {
        float m = sred[0];
        #pragma unroll
        for (int i = 1; i < 8; i++) m = fmaxf(m, sred[i]);
        sred[0] = m;
    }
    __syncthreads();
    mx = sred[0];
    __syncthreads();
    float s = 0.f;
    #pragma unroll
    for (int j = 0; j < V; j++) { v[j] = __expf(v[j] - mx); s += v[j]; }
    s = warpSum(s);
    if (lane == 0) sred[wid] = s;
    __syncthreads();
    if (tid == 0) {
        float m = 0.f;
        #pragma unroll
        for (int i = 0; i < 8; i++) m += sred[i];
        sred[0] = m;
    }
    __syncthreads();
    const float inv = 1.0f / sred[0];
    #pragma unroll
    for (int j = 0; j < V; j++)
        oh[base + tid + j * 256] = __float2half_rn(v[j] * inv);
}

// ---------------- launch --------------------------------------------------------
extern "C" void kernel_launch(void* const* d_in, const int* in_sizes, int n_in,
                              void* d_out, int out_size) {
    const float* x     = (const float*)d_in[0];
    const float* w1    = (const float*)d_in[1];
    const float* b1    = (const float*)d_in[2];
    const float* w2    = (const float*)d_in[3];
    const float* b2    = (const float*)d_in[4];
    const float* w3    = (const float*)d_in[5];
    const float* b3    = (const float*)d_in[6];
    const float* alpha = (const float*)d_in[7];
    const float* beta  = (const float*)d_in[8];
    const float* wf    = (const float*)d_in[9];
    const float* bf    = (const float*)d_in[10];
    float* out = (float*)d_out;

    cudaFuncSetAttribute(mma_gemm<false,true, 2,false>, cudaFuncAttributeMaxDynamicSharedMemorySize, GEMM_SMEM);
    cudaFuncSetAttribute(mma_gemm<true, true, 0,false>, cudaFuncAttributeMaxDynamicSharedMemorySize, GEMM_SMEM);
    cudaFuncSetAttribute(mma_gemm<false,false,2,false>, cudaFuncAttributeMaxDynamicSharedMemorySize, GEMM_SMEM);
    cudaFuncSetAttribute(mma_gemm<false,false,0,false>, cudaFuncAttributeMaxDynamicSharedMemorySize, GEMM_SMEM);
    cudaFuncSetAttribute(mma_gemm<true, true, 2,false>, cudaFuncAttributeMaxDynamicSharedMemorySize, GEMM_SMEM);
    cudaFuncSetAttribute(mma_gemm<false,true, 0,true >, cudaFuncAttributeMaxDynamicSharedMemorySize, GEMM_SMEM);

    fp16 *Vh, *Uh, *Mw16, *wfh, *Ah, *Bmh, *Dh, *xh, *Mh, *Sh, *spath, *chanh;
    float *Mb, *Sb;
    cudaGetSymbolAddress((void**)&Vh, g_Vh);
    cudaGetSymbolAddress((void**)&Uh, g_Uh);
    cudaGetSymbolAddress((void**)&Mw16, g_Mw);
    cudaGetSymbolAddress((void**)&wfh, g_wfh);
    cudaGetSymbolAddress((void**)&Ah,  g_Ah);
    cudaGetSymbolAddress((void**)&Bmh, g_Bmh);
    cudaGetSymbolAddress((void**)&Dh,  g_Dh);
    cudaGetSymbolAddress((void**)&xh,  g_xh);
    cudaGetSymbolAddress((void**)&Mb,  g_M);
    cudaGetSymbolAddress((void**)&Mh,  g_Mh);
    cudaGetSymbolAddress((void**)&Sb,  g_S);
    cudaGetSymbolAddress((void**)&Sh,  g_Sh);
    cudaGetSymbolAddress((void**)&spath, g_spath);
    cudaGetSymbolAddress((void**)&chanh, g_chanh);

    const long sX  = (long)CC * NN;
    const long sM  = (long)NN * NN;
    const long sS  = (long)CC * CC;
    const long sVt = (long)CC * TCOLS;
    const long sUt = (long)C3 * CC;
    const long sMwt = (long)C3 * TCOLS;
    const unsigned ZALL = 0xFFFFFFFFu;

    // side stream + events for the independent S-chain (fork-join under capture)
    cudaStream_t s2;
    cudaStreamCreateWithFlags(&s2, cudaStreamNonBlocking);
    cudaEvent_t evFork, evJoin;
    cudaEventCreateWithFlags(&evFork, cudaEventDisableTiming);
    cudaEventCreateWithFlags(&evJoin, cudaEventDisableTiming);

    // 1) transforms (wino_input also produces xh)
    wino_input4<<<(unsigned)((long)BB * CC * NT4 / 256), 256>>>(x, Vh, xh);
    wino_weight4<<<dim3(CC * CC / 256, 3), 256>>>(w1, w2, w3, Uh);

    // fork: S-chain depends only on xh (+ wf for its cvt)
    cudaEventRecord(evFork, 0);
    cudaStreamWaitEvent(s2, evFork, 0);

    // --- side stream: cvt wf, S = x.x^T, softmax, chan ---
    cvt_kernel<<<CC * C3 / 256, 256, 0, s2>>>(wf, wfh);
    {
        dim3 g(CC / 128, CC / 128, BB);
        mma_gemm<false,false,0,false><<<g, 128, GEMM_SMEM, s2>>>(
            xh, NN, sX, ZALL, xh, xh, xh, NN, sX,
            Sb, nullptr, CC, sS, nullptr, nullptr, NN);
    }
    softmax_fp16<CC><<<BB * CC, 256, 0, s2>>>(Sb, Sh);
    {
        dim3 g(NN / 128, CC / 128, BB);
        mma_gemm<true,true,2,false><<<g, 128, GEMM_SMEM, s2>>>(
            Sh, CC, sS, ZALL, xh, xh, xh, NN, sX,
            nullptr, chanh, NN, sX, nullptr, beta, CC);
    }
    cudaEventRecord(evJoin, s2);

    // --- main stream: conv chain ---
    // 2) merged 3-conv Winograd GEMM
    {
        dim3 g(TCOLS / 128, C3 / 128, TAPS);
        mma_gemm<false,true,2,false><<<g, 128, GEMM_SMEM>>>(
            Uh, CC, sUt, ZALL, Vh, Vh, Vh, TCOLS, sVt,
            nullptr, Mw16, TCOLS, sMwt, nullptr, nullptr, CC);
        wino_output4<<<(unsigned)((long)BB * C3 * NT4 / 256), 256>>>(
            Mw16, b1, b2, b3, Ah, Bmh, Dh);
    }
    // 3) M = A^T Bm
    {
        dim3 g(NN / 128, NN / 128, BB);
        mma_gemm<true,true,0,false><<<g, 128, GEMM_SMEM>>>(
            Ah, NN, sX, ZALL, Bmh, Bmh, Bmh, NN, sX,
            Mb, nullptr, NN, sM, nullptr, nullptr, CC);
    }
    // 4) softmax rows of M
    softmax_fp16<NN><<<BB * NN, 256>>>(Mb, Mh);
    // 5) spat = alpha * D @ Msm^T
    {
        dim3 g(NN / 128, CC / 128, BB);
        mma_gemm<false,false,2,false><<<g, 128, GEMM_SMEM>>>(
            Dh, NN, sX, ZALL, Mh, Mh, Mh, NN, sM,
            nullptr, spath, NN, sX, nullptr, alpha, NN);
    }

    // join: fuse needs chanh from the side stream
    cudaStreamWaitEvent(0, evJoin, 0);

    // 6) fuse: out = bf + wf . [x; a*spat; b*chan]
    {
        dim3 g(NN / 128, CC / 128, BB);
        mma_gemm<false,true,0,true><<<g, 128, GEMM_SMEM>>>(
            wfh, C3, 0, ZALL, xh, spath, chanh, NN, sX,
            out, nullptr, NN, sX, bf, nullptr, C3);
    }
    // streams/events are host objects (no device allocation); intentionally not
    // destroyed while the surrounding graph capture may still reference them.
}

// round 14
// speedup vs baseline: 22.6014x; 1.0406x over previous
#include <cuda_runtime.h>
#include <cuda_fp16.h>
#include <cstdint>

#define BB 16
#define CC 512
#define HH 32
#define WW 32
#define NN 1024
#define C3 1536
#define NT4 64
#define TCOLS 1024
#define TAPS 36

typedef __half fp16;

// ---------------- scratch (device globals) -----------------------------------
__device__ fp16 g_Vh[(size_t)TAPS * CC * TCOLS];
__device__ fp16 g_Uh[(size_t)TAPS * C3 * CC];
__device__ fp16 g_Mw[(size_t)TAPS * C3 * TCOLS];
__device__ fp16 g_wfh[CC * C3];
__device__ fp16 g_Ah[(size_t)BB * CC * NN];
__device__ fp16 g_Bmh[(size_t)BB * CC * NN];
__device__ fp16 g_Dh[(size_t)BB * CC * NN];
__device__ fp16 g_xh[(size_t)BB * CC * NN];
__device__ float g_M[(size_t)BB * NN * NN];
__device__ fp16 g_Mh[(size_t)BB * NN * NN];
__device__ float g_S[(size_t)BB * CC * CC];
__device__ fp16 g_Sh[(size_t)BB * CC * CC];
__device__ fp16 g_spath[(size_t)BB * CC * NN];
__device__ fp16 g_chanh[(size_t)BB * CC * NN];

// ---------------- helpers ------------------------------------------------------
__device__ __forceinline__ uint32_t smem_u32(const void* p) {
    uint32_t a;
    asm("{ .reg .u64 t; cvta.to.shared.u64 t, %1; cvt.u32.u64 %0, t; }"
        : "=r"(a) : "l"(p));
    return a;
}
__device__ __forceinline__ void ldsm_x4(uint32_t* r, uint32_t addr) {
    asm volatile("ldmatrix.sync.aligned.m8n8.x4.shared.b16 {%0,%1,%2,%3}, [%4];"
                 : "=r"(r[0]), "=r"(r[1]), "=r"(r[2]), "=r"(r[3]) : "r"(addr));
}
__device__ __forceinline__ void ldsm_x4_t(uint32_t* r, uint32_t addr) {
    asm volatile("ldmatrix.sync.aligned.m8n8.x4.trans.shared.b16 {%0,%1,%2,%3}, [%4];"
                 : "=r"(r[0]), "=r"(r[1]), "=r"(r[2]), "=r"(r[3]) : "r"(addr));
}
__device__ __forceinline__ void mma16816(float* d, const uint32_t* a, const uint32_t* b) {
    asm volatile("mma.sync.aligned.m16n8k16.row.col.f32.f16.f16.f32 "
                 "{%0,%1,%2,%3}, {%4,%5,%6,%7}, {%8,%9}, {%0,%1,%2,%3};"
                 : "+f"(d[0]), "+f"(d[1]), "+f"(d[2]), "+f"(d[3])
                 : "r"(a[0]), "r"(a[1]), "r"(a[2]), "r"(a[3]), "r"(b[0]), "r"(b[1]));
}

// ---------------- GEMM ----------------------------------------------------------
// Block tile 128x128, BK=64, 128 threads (4 warps 2x2), warp tile 64x64.
// 3 stages x 32 KB = 96 KB/CTA; 2 CTAs co-resident (192 KB).
// K-major tile: 128 rows x 128B (8 chunks), swizzle ch ^= row&7.
// MN-major tile: 64 krows x 256B (16 chunks), swizzle ch ^= krow&7.
#define TILEB 16384
#define STGB  (2 * TILEB)                // 32 KB
#define STAGES 3
#define GEMM_SMEM (STAGES * STGB)        // 96 KB

template<bool TR>
__device__ __forceinline__ void load_tile(uint32_t tb, const fp16* __restrict__ S,
                                          long rowbase, long ld, long k0, int tid) {
    if (!TR) {
        #pragma unroll
        for (int p = 0; p < 8; p++) {
            int row = (tid >> 3) + p * 16;     // 128 rows
            int ch  = tid & 7;                 // 8 chunks (128B row)
            const void* g = (const void*)(S + (rowbase + row) * ld + k0 + ch * 8);
            uint32_t dst = tb + (uint32_t)(row * 128 + ((ch ^ (row & 7)) << 4));
            asm volatile("cp.async.cg.shared.global [%0], [%1], 16;"
                         :: "r"(dst), "l"(g) : "memory");
        }
    } else {
        #pragma unroll
        for (int p = 0; p < 8; p++) {
            int row = (tid >> 4) + p * 8;      // krow 0..63
            int ch  = tid & 15;                // 16 chunks (256B row)
            const void* g = (const void*)(S + (k0 + row) * ld + rowbase + ch * 8);
            uint32_t dst = tb + (uint32_t)(row * 256 + ((ch ^ (row & 7)) << 4));
            asm volatile("cp.async.cg.shared.global [%0], [%1], 16;"
                         :: "r"(dst), "l"(g) : "memory");
        }
    }
}

// EPI: 0 = fp32 (+bias), 2 = fp16 (*scale, +bias)
template<bool ATR, bool BTR, int EPI, bool SEG>
__global__ __launch_bounds__(128, 2)
void mma_gemm(const fp16* __restrict__ A_, long lda, long bsA, unsigned zmA,
              const fp16* __restrict__ B0, const fp16* __restrict__ B1,
              const fp16* __restrict__ B2, long ldb, long bsB,
              float* __restrict__ Cf, fp16* __restrict__ Ch,
              long ldc, long bsC,
              const float* __restrict__ bias, const float* __restrict__ scale, int K)
{
    extern __shared__ char smem[];
    const uint32_t sb = smem_u32(smem);
    const int tid = threadIdx.x;
    const int wid = tid >> 5, lane = tid & 31;
    const int warp_m = wid & 1, warp_n = wid >> 1;   // 2 x 2
    const long m0 = (long)blockIdx.y * 128, n0 = (long)blockIdx.x * 128;
    const long zA = (long)(blockIdx.z & zmA) * bsA, zB = (long)blockIdx.z * bsB;
    A_ += zA;
    B0 += zB;  B1 += zB;  B2 += zB;

    float d[4][8][4];
    #pragma unroll
    for (int i = 0; i < 4; i++)
        #pragma unroll
        for (int j = 0; j < 8; j++)
            #pragma unroll
            for (int q = 0; q < 4; q++) d[i][j][q] = 0.f;

    const int NC = K >> 6;     // BK = 64

    auto loadstage = [&](int i) {
        const int s = i % STAGES;
        const long k0 = (long)i * 64;
        const fp16* Bp = B0;
        long kb = k0;
        if (SEG) {
            int seg = (int)(k0 >> 9);
            kb = k0 & 511;
            Bp = (seg == 0) ? B0 : (seg == 1) ? B1 : B2;
        }
        uint32_t tb = sb + (uint32_t)s * STGB;
        load_tile<ATR>(tb,         A_, m0, lda, k0, tid);
        load_tile<BTR>(tb + TILEB, Bp, n0, ldb, kb, tid);
        asm volatile("cp.async.commit_group;" ::: "memory");
    };

    for (int i = 0; i < STAGES - 1; i++) {
        if (i < NC) loadstage(i);
        else        asm volatile("cp.async.commit_group;" ::: "memory");
    }

    for (int i = 0; i < NC; i++) {
        asm volatile("cp.async.wait_group %0;" :: "n"(STAGES - 2) : "memory");
        __syncthreads();
        if (i + STAGES - 1 < NC) loadstage(i + STAGES - 1);
        else                     asm volatile("cp.async.commit_group;" ::: "memory");

        const int s = i % STAGES;
        const uint32_t bA = sb + (uint32_t)s * STGB;
        const uint32_t bB = bA + TILEB;

        #pragma unroll
        for (int ks = 0; ks < 4; ks++) {
            uint32_t ah[4][4];
            #pragma unroll
            for (int tm = 0; tm < 4; tm++) {
                if (!ATR) {
                    int row = warp_m * 64 + tm * 16 + (lane & 15);
                    int ch  = ks * 2 + (lane >> 4);
                    uint32_t off = (uint32_t)(row * 128 + ((ch ^ (row & 7)) << 4));
                    ldsm_x4(ah[tm], bA + off);
                } else {
                    int krow = ks * 16 + (lane & 7) + ((lane >> 4) << 3);
                    int mch  = ((warp_m * 64 + tm * 16) >> 3) + ((lane >> 3) & 1);
                    uint32_t off = (uint32_t)(krow * 256 + ((mch ^ (krow & 7)) << 4));
                    ldsm_x4_t(ah[tm], bA + off);
                }
            }
            uint32_t bh[4][4];
            #pragma unroll
            for (int tp = 0; tp < 4; tp++) {
                if (!BTR) {
                    int row = warp_n * 64 + tp * 16 + (lane & 7) + ((lane >> 4) << 3);
                    int ch  = ks * 2 + ((lane >> 3) & 1);
                    uint32_t off = (uint32_t)(row * 128 + ((ch ^ (row & 7)) << 4));
                    ldsm_x4(bh[tp], bB + off);
                } else {
                    int krow = ks * 16 + (lane & 7) + ((lane >> 3) & 1) * 8;
                    int nch  = ((warp_n * 64 + tp * 16) >> 3) + (lane >> 4);
                    uint32_t off = (uint32_t)(krow * 256 + ((nch ^ (krow & 7)) << 4));
                    ldsm_x4_t(bh[tp], bB + off);
                }
            }
            #pragma unroll
            for (int tm = 0; tm < 4; tm++)
                #pragma unroll
                for (int tp = 0; tp < 4; tp++) {
                    mma16816(d[tm][tp * 2 + 0], ah[tm], bh[tp] + 0);
                    mma16816(d[tm][tp * 2 + 1], ah[tm], bh[tp] + 2);
                }
        }
        __syncthreads();
    }

    if (EPI == 0) {
        float* Cb = Cf + (long)blockIdx.z * bsC;
        #pragma unroll
        for (int tm = 0; tm < 4; tm++) {
            const long m = m0 + warp_m * 64 + tm * 16 + (lane >> 2);
            const float bs0 = bias ? bias[m]     : 0.f;
            const float bs1 = bias ? bias[m + 8] : 0.f;
            #pragma unroll
            for (int tn = 0; tn < 8; tn++) {
                const long n = n0 + warp_n * 64 + tn * 8 + (lane & 3) * 2;
                *(float2*)&Cb[m * ldc + n] =
                    make_float2(d[tm][tn][0] + bs0, d[tm][tn][1] + bs0);
                *(float2*)&Cb[(m + 8) * ldc + n] =
                    make_float2(d[tm][tn][2] + bs1, d[tm][tn][3] + bs1);
            }
        }
    } else {
        fp16* Hb = Ch + (long)blockIdx.z * bsC;
        const float sc = scale ? *scale : 1.0f;
        #pragma unroll
        for (int tm = 0; tm < 4; tm++) {
            const long m = m0 + warp_m * 64 + tm * 16 + (lane >> 2);
            const float bs0 = bias ? bias[m]     : 0.f;
            const float bs1 = bias ? bias[m + 8] : 0.f;
            #pragma unroll
            for (int tn = 0; tn < 8; tn++) {
                const long n = n0 + warp_n * 64 + tn * 8 + (lane & 3) * 2;
                __half2 p0 = __floats2half2_rn(d[tm][tn][0] * sc + bs0,
                                               d[tm][tn][1] * sc + bs0);
                __half2 p1 = __floats2half2_rn(d[tm][tn][2] * sc + bs1,
                                               d[tm][tn][3] * sc + bs1);
                *(__half2*)&Hb[m * ldc + n]       = p0;
                *(__half2*)&Hb[(m + 8) * ldc + n] = p1;
            }
        }
    }
}

// ---------------- Winograd F(4x4,3x3) transforms -------------------------------
__global__ __launch_bounds__(256)
void wino_input4(const float* __restrict__ x, fp16* __restrict__ Vh,
                 fp16* __restrict__ xh) {
    long gid = (long)blockIdx.x * 256 + threadIdx.x;
    int tile = (int)(gid & (NT4 - 1));
    long r = gid >> 6;
    int ci = (int)(r & (CC - 1));
    int b  = (int)(r >> 9);
    int ty = tile >> 3, tx = tile & 7;
    const long xoff = ((long)b * CC + ci) * NN;
    const float* xb = x + xoff;
    const int h0 = 4 * ty - 1, w0 = 4 * tx - 1;

    float dd[6][6];
    #pragma unroll
    for (int i = 0; i < 6; i++) {
        int ih = h0 + i;
        #pragma unroll
        for (int j = 0; j < 6; j++) {
            int iw = w0 + j;
            dd[i][j] = ((unsigned)ih < HH && (unsigned)iw < WW) ? xb[ih * WW + iw] : 0.f;
        }
    }
    {
        fp16* xo = xh + xoff + (4 * ty) * WW + 4 * tx;
        #pragma unroll
        for (int i = 0; i < 4; i++) {
            __half2 p0 = __floats2half2_rn(dd[i + 1][1], dd[i + 1][2]);
            __half2 p1 = __floats2half2_rn(dd[i + 1][3], dd[i + 1][4]);
            *(__half2*)&xo[i * WW]     = p0;
            *(__half2*)&xo[i * WW + 2] = p1;
        }
    }
    float t[6][6];
    #pragma unroll
    for (int j = 0; j < 6; j++) {
        t[0][j] =  4.f*dd[0][j] - 5.f*dd[2][j] + dd[4][j];
        t[1][j] = -4.f*dd[1][j] - 4.f*dd[2][j] + dd[3][j] + dd[4][j];
        t[2][j] =  4.f*dd[1][j] - 4.f*dd[2][j] - dd[3][j] + dd[4][j];
        t[3][j] = -2.f*dd[1][j] -     dd[2][j] + 2.f*dd[3][j] + dd[4][j];
        t[4][j] =  2.f*dd[1][j] -     dd[2][j] - 2.f*dd[3][j] + dd[4][j];
        t[5][j] =  4.f*dd[1][j] - 5.f*dd[3][j] + dd[5][j];
    }
    const long tcol = (long)b * NT4 + tile;
    #pragma unroll
    for (int i = 0; i < 6; i++) {
        float V0 =  4.f*t[i][0] - 5.f*t[i][2] + t[i][4];
        float V1 = -4.f*t[i][1] - 4.f*t[i][2] + t[i][3] + t[i][4];
        float V2 =  4.f*t[i][1] - 4.f*t[i][2] - t[i][3] + t[i][4];
        float V3 = -2.f*t[i][1] -     t[i][2] + 2.f*t[i][3] + t[i][4];
        float V4 =  2.f*t[i][1] -     t[i][2] - 2.f*t[i][3] + t[i][4];
        float V5 =  4.f*t[i][1] - 5.f*t[i][3] + t[i][5];
        float Vv[6] = {V0, V1, V2, V3, V4, V5};
        #pragma unroll
        for (int j = 0; j < 6; j++)
            Vh[((long)(i * 6 + j) * CC + ci) * TCOLS + tcol] = __float2half_rn(Vv[j]);
    }
}

__global__ __launch_bounds__(256)
void wino_weight4(const float* __restrict__ w1, const float* __restrict__ w2,
                  const float* __restrict__ w3, fp16* __restrict__ Uh) {
    const int conv = blockIdx.y;
    const float* w = (conv == 0) ? w1 : (conv == 1) ? w2 : w3;
    const int co_base = conv * CC;
    int gid = blockIdx.x * 256 + threadIdx.x;
    int ci = gid & (CC - 1), co = gid >> 9;
    const float* g = w + (long)gid * 9;
    float t2[6][3];
    #pragma unroll
    for (int j = 0; j < 3; j++) {
        float g0 = g[0 * 3 + j], g1 = g[1 * 3 + j], g2 = g[2 * 3 + j];
        t2[0][j] = 0.25f * g0;
        t2[1][j] = (-g0 - g1 - g2) * (1.f / 6.f);
        t2[2][j] = (-g0 + g1 - g2) * (1.f / 6.f);
        t2[3][j] = g0 * (1.f / 24.f) + g1 * (1.f / 12.f) + g2 * (1.f / 6.f);
        t2[4][j] = g0 * (1.f / 24.f) - g1 * (1.f / 12.f) + g2 * (1.f / 6.f);
        t2[5][j] = g2;
    }
    #pragma unroll
    for (int i = 0; i < 6; i++) {
        float a = t2[i][0], bq = t2[i][1], c = t2[i][2];
        float Uv[6];
        Uv[0] = 0.25f * a;
        Uv[1] = (-a - bq - c) * (1.f / 6.f);
        Uv[2] = (-a + bq - c) * (1.f / 6.f);
        Uv[3] = a * (1.f / 24.f) + bq * (1.f / 12.f) + c * (1.f / 6.f);
        Uv[4] = a * (1.f / 24.f) - bq * (1.f / 12.f) + c * (1.f / 6.f);
        Uv[5] = c;
        #pragma unroll
        for (int j = 0; j < 6; j++)
            Uh[((long)(i * 6 + j) * C3 + co_base + co) * CC + ci] = __float2half_rn(Uv[j]);
    }
}

__global__ __launch_bounds__(256)
void wino_output4(const fp16* __restrict__ M,
                  const float* __restrict__ b1, const float* __restrict__ b2,
                  const float* __restrict__ b3,
                  fp16* __restrict__ Ah, fp16* __restrict__ Bmh,
                  fp16* __restrict__ Dh) {
    long gid = (long)blockIdx.x * 256 + threadIdx.x;
    int tile = (int)(gid & (NT4 - 1));
    long r = gid >> 6;
    int co3 = (int)(r % C3);
    int b   = (int)(r / C3);
    const long tcol = (long)b * NT4 + tile;
    const int seg = co3 >> 9, co = co3 & (CC - 1);

    float m[6][6];
    #pragma unroll
    for (int c = 0; c < 36; c++)
        m[c / 6][c % 6] = __half2float(M[((long)c * C3 + co3) * TCOLS + tcol]);

    float s[4][6];
    #pragma unroll
    for (int j = 0; j < 6; j++) {
        s[0][j] = m[0][j] + m[1][j] + m[2][j] + m[3][j] + m[4][j];
        s[1][j] = m[1][j] - m[2][j] + 2.f * (m[3][j] - m[4][j]);
        s[2][j] = m[1][j] + m[2][j] + 4.f * (m[3][j] + m[4][j]);
        s[3][j] = m[1][j] - m[2][j] + 8.f * (m[3][j] - m[4][j]) + m[5][j];
    }
    const float bs = (seg == 0) ? b1[co] : (seg == 1) ? b2[co] : b3[co];
    fp16* O = (seg == 0) ? Ah : (seg == 1) ? Bmh : Dh;
    int ty = tile >> 3, tx = tile & 7;
    long base = ((long)b * CC + co) * NN + (4 * ty) * WW + 4 * tx;
    #pragma unroll
    for (int i = 0; i < 4; i++) {
        float Y[4];
        Y[0] = s[i][0] + s[i][1] + s[i][2] + s[i][3] + s[i][4] + bs;
        Y[1] = s[i][1] - s[i][2] + 2.f * (s[i][3] - s[i][4]) + bs;
        Y[2] = s[i][1] + s[i][2] + 4.f * (s[i][3] + s[i][4]) + bs;
        Y[3] = s[i][1] - s[i][2] + 8.f * (s[i][3] - s[i][4]) + s[i][5] + bs;
        long ro = base + i * WW;
        #pragma unroll
        for (int j = 0; j < 4; j++)
            O[ro + j] = __float2half_rn(Y[j]);
    }
}

// ---------------- fp32 -> fp16 convert ------------------------------------------
__global__ void cvt_kernel(const float* __restrict__ in, fp16* __restrict__ oh) {
    long g = (long)blockIdx.x * 256 + threadIdx.x;
    oh[g] = __float2half_rn(in[g]);
}

// ---------------- softmax -------------------------------------------------------
__device__ __forceinline__ float warpMax(float v) {
    #pragma unroll
    for (int o = 16; o > 0; o >>= 1) v = fmaxf(v, __shfl_xor_sync(0xffffffffu, v, o));
    return v;
}
__device__ __forceinline__ float warpSum(float v) {
    #pragma unroll
    for (int o = 16; o > 0; o >>= 1) v += __shfl_xor_sync(0xffffffffu, v, o);
    return v;
}

template<int LEN>
__global__ __launch_bounds__(256)
void softmax_fp16(const float* __restrict__ buf, fp16* __restrict__ oh) {
    constexpr int V = LEN / 256;
    const long base = (long)blockIdx.x * LEN;
    const float* row = buf + base;
    const int tid = threadIdx.x, lane = tid & 31, wid = tid >> 5;
    __shared__ float sred[8];
    float v[V];
    float mx = -3.0e38f;
    #pragma unroll
    for (int j = 0; j < V; j++) { v[j] = row[tid + j * 256]; mx = fmaxf(mx, v[j]); }
    mx = warpMax(mx);
    if (lane == 0) sred[wid] = mx;
    __syncthreads();
    if (tid == 0) {
        float m = sred[0];
        #pragma unroll
        for (int i = 1; i < 8; i++) m = fmaxf(m, sred[i]);
        sred[0] = m;
    }
    __syncthreads();
    mx = sred[0];
    __syncthreads();
    float s = 0.f;
    #pragma unroll
    for (int j = 0; j < V; j++) { v[j] = __expf(v[j] - mx); s += v[j]; }
    s = warpSum(s);
    if (lane == 0) sred[wid] = s;
    __syncthreads();
    if (tid == 0) {
        float m = 0.f;
        #pragma unroll
        for (int i = 0; i < 8; i++) m += sred[i];
        sred[0] = m;
    }
    __syncthreads();
    const float inv = 1.0f / sred[0];
    #pragma unroll
    for (int j = 0; j < V; j++)
        oh[base + tid + j * 256] = __float2half_rn(v[j] * inv);
}

// ---------------- launch --------------------------------------------------------
extern "C" void kernel_launch(void* const* d_in, const int* in_sizes, int n_in,
                              void* d_out, int out_size) {
    const float* x     = (const float*)d_in[0];
    const float* w1    = (const float*)d_in[1];
    const float* b1    = (const float*)d_in[2];
    const float* w2    = (const float*)d_in[3];
    const float* b2    = (const float*)d_in[4];
    const float* w3    = (const float*)d_in[5];
    const float* b3    = (const float*)d_in[6];
    const float* alpha = (const float*)d_in[7];
    const float* beta  = (const float*)d_in[8];
    const float* wf    = (const float*)d_in[9];
    const float* bf    = (const float*)d_in[10];
    float* out = (float*)d_out;

    cudaFuncSetAttribute(mma_gemm<false,true, 2,false>, cudaFuncAttributeMaxDynamicSharedMemorySize, GEMM_SMEM);
    cudaFuncSetAttribute(mma_gemm<true, true, 0,false>, cudaFuncAttributeMaxDynamicSharedMemorySize, GEMM_SMEM);
    cudaFuncSetAttribute(mma_gemm<false,false,2,false>, cudaFuncAttributeMaxDynamicSharedMemorySize, GEMM_SMEM);
    cudaFuncSetAttribute(mma_gemm<false,false,0,false>, cudaFuncAttributeMaxDynamicSharedMemorySize, GEMM_SMEM);
    cudaFuncSetAttribute(mma_gemm<true, true, 2,false>, cudaFuncAttributeMaxDynamicSharedMemorySize, GEMM_SMEM);
    cudaFuncSetAttribute(mma_gemm<false,true, 0,true >, cudaFuncAttributeMaxDynamicSharedMemorySize, GEMM_SMEM);

    fp16 *Vh, *Uh, *Mw16, *wfh, *Ah, *Bmh, *Dh, *xh, *Mh, *Sh, *spath, *chanh;
    float *Mb, *Sb;
    cudaGetSymbolAddress((void**)&Vh, g_Vh);
    cudaGetSymbolAddress((void**)&Uh, g_Uh);
    cudaGetSymbolAddress((void**)&Mw16, g_Mw);
    cudaGetSymbolAddress((void**)&wfh, g_wfh);
    cudaGetSymbolAddress((void**)&Ah,  g_Ah);
    cudaGetSymbolAddress((void**)&Bmh, g_Bmh);
    cudaGetSymbolAddress((void**)&Dh,  g_Dh);
    cudaGetSymbolAddress((void**)&xh,  g_xh);
    cudaGetSymbolAddress((void**)&Mb,  g_M);
    cudaGetSymbolAddress((void**)&Mh,  g_Mh);
    cudaGetSymbolAddress((void**)&Sb,  g_S);
    cudaGetSymbolAddress((void**)&Sh,  g_Sh);
    cudaGetSymbolAddress((void**)&spath, g_spath);
    cudaGetSymbolAddress((void**)&chanh, g_chanh);

    const long sX  = (long)CC * NN;
    const long sM  = (long)NN * NN;
    const long sS  = (long)CC * CC;
    const long sVt = (long)CC * TCOLS;
    const long sUt = (long)C3 * CC;
    const long sMwt = (long)C3 * TCOLS;
    const unsigned ZALL = 0xFFFFFFFFu;

    cudaStream_t s2;
    cudaStreamCreateWithFlags(&s2, cudaStreamNonBlocking);
    cudaEvent_t evFork, evJoin;
    cudaEventCreateWithFlags(&evFork, cudaEventDisableTiming);
    cudaEventCreateWithFlags(&evJoin, cudaEventDisableTiming);

    // 1) transforms (wino_input also produces xh)
    wino_input4<<<(unsigned)((long)BB * CC * NT4 / 256), 256>>>(x, Vh, xh);
    wino_weight4<<<dim3(CC * CC / 256, 3), 256>>>(w1, w2, w3, Uh);

    // fork: S-chain depends only on xh (+ wf for its cvt)
    cudaEventRecord(evFork, 0);
    cudaStreamWaitEvent(s2, evFork, 0);

    // --- side stream: cvt wf, S = x.x^T, softmax, chan ---
    cvt_kernel<<<CC * C3 / 256, 256, 0, s2>>>(wf, wfh);
    {
        dim3 g(CC / 128, CC / 128, BB);
        mma_gemm<false,false,0,false><<<g, 128, GEMM_SMEM, s2>>>(
            xh, NN, sX, ZALL, xh, xh, xh, NN, sX,
            Sb, nullptr, CC, sS, nullptr, nullptr, NN);
    }
    softmax_fp16<CC><<<BB * CC, 256, 0, s2>>>(Sb, Sh);
    {
        dim3 g(NN / 128, CC / 128, BB);
        mma_gemm<true,true,2,false><<<g, 128, GEMM_SMEM, s2>>>(
            Sh, CC, sS, ZALL, xh, xh, xh, NN, sX,
            nullptr, chanh, NN, sX, nullptr, beta, CC);
    }
    cudaEventRecord(evJoin, s2);

    // --- main stream: conv chain ---
    {
        dim3 g(TCOLS / 128, C3 / 128, TAPS);
        mma_gemm<false,true,2,false><<<g, 128, GEMM_SMEM>>>(
            Uh, CC, sUt, ZALL, Vh, Vh, Vh, TCOLS, sVt,
            nullptr, Mw16, TCOLS, sMwt, nullptr, nullptr, CC);
        wino_output4<<<(unsigned)((long)BB * C3 * NT4 / 256), 256>>>(
            Mw16, b1, b2, b3, Ah, Bmh, Dh);
    }
    {
        dim3 g(NN / 128, NN / 128, BB);
        mma_gemm<true,true,0,false><<<g, 128, GEMM_SMEM>>>(
            Ah, NN, sX, ZALL, Bmh, Bmh, Bmh, NN, sX,
            Mb, nullptr, NN, sM, nullptr, nullptr, CC);
    }
    softmax_fp16<NN><<<BB * NN, 256>>>(Mb, Mh);
    {
        dim3 g(NN / 128, CC / 128, BB);
        mma_gemm<false,false,2,false><<<g, 128, GEMM_SMEM>>>(
            Dh, NN, sX, ZALL, Mh, Mh, Mh, NN, sM,
            nullptr, spath, NN, sX, nullptr, alpha, NN);
    }

    // join: fuse needs chanh from the side stream
    cudaStreamWaitEvent(0, evJoin, 0);

    // fuse: out = bf + wf . [x; a*spat; b*chan]
    {
        dim3 g(NN / 128, CC / 128, BB);
        mma_gemm<false,true,0,true><<<g, 128, GEMM_SMEM>>>(
            wfh, C3, 0, ZALL, xh, spath, chanh, NN, sX,
            out, nullptr, NN, sX, bf, nullptr, C3);
    }
    // streams/events are host objects (no device allocation); intentionally not
    // destroyed while the surrounding graph capture may still reference them.
}